// round 1
// baseline (speedup 1.0000x reference)
#include <cuda_runtime.h>
#include <math.h>

// Problem constants
#define Tn   256
#define Bn   256
#define Hn   512
#define BH   (Bn*Hn)
#define NCTA 128

// Scratch: layer outputs, time-major [T][B][H]
__device__ float g_h0[(size_t)Tn*Bn*Hn];
__device__ float g_h1[(size_t)Tn*Bn*Hn];

// Grid barrier state
__device__ unsigned g_count;
__device__ unsigned g_gen;

__device__ __forceinline__ void ffma2(unsigned long long &d, unsigned long long a, unsigned long long b){
    asm("fma.rn.f32x2 %0, %1, %2, %0;" : "+l"(d) : "l"(a), "l"(b));
}
__device__ __forceinline__ float pairsum(unsigned long long v){
    float x, y;
    asm("mov.b64 {%0,%1}, %2;" : "=f"(x), "=f"(y) : "l"(v));
    return x + y;
}

// Sense-reversing grid barrier (all 128 CTAs are co-resident: grid < #SMs).
__device__ __forceinline__ void grid_barrier(){
    __syncthreads();
    if (threadIdx.x == 0){
        __threadfence();
        volatile unsigned* gen = &g_gen;
        unsigned g = *gen;
        unsigned t = atomicAdd(&g_count, 1u);
        if (t == NCTA - 1u){
            g_count = 0u;
            __threadfence();
            *gen = g + 1u;
        } else {
            while (*gen == g) { __nanosleep(32); }
            __threadfence();
        }
    }
    __syncthreads();
}

// Persistent LSTM layer.
// CTA tile: 64 b-rows x 16 hidden units (=> 64 gate-rows: j = g*512 + u, g in 0..3).
// Thread (ty 0..15, tx 0..15): 4 b's (b0+ty*4+bi), 1 u (u0+tx), all 4 gates.
// c lives in registers for the whole T loop; h is exchanged via h_out[t] slices.
__global__ void __launch_bounds__(256, 1) lstm_layer_kernel(
    const float* __restrict__ x_time,   // layer0: [B,T,5]
    const float* __restrict__ w_ih0,    // layer0: [2048,5]
    const float* __restrict__ w_ih,     // layer1: [2048,512]
    const float* __restrict__ w_hh,     // [2048,512]
    const float* __restrict__ bias,     // [2048]
    int layer)
{
    __shared__ __align__(16) float hs[64*68];
    __shared__ __align__(16) float ws[64*68];

    float* h_out = (layer == 0) ? g_h0 : g_h1;
    const float* src_in = g_h0;   // layer1 input sequence

    const int tid = threadIdx.x;
    const int tx = tid & 15;      // hidden unit within tile
    const int ty = tid >> 4;      // b group
    const int bx = blockIdx.x & 3;    // 4 b-tiles
    const int by = blockIdx.x >> 2;   // 32 u-tiles
    const int b0 = bx * 64;
    const int u0 = by * 16;
    const int u  = u0 + tx;

    float c[4] = {0.f, 0.f, 0.f, 0.f};

    for (int t = 0; t < Tn; ++t){
        unsigned long long acc[4][4];
        #pragma unroll
        for (int bi = 0; bi < 4; ++bi)
            #pragma unroll
            for (int gi = 0; gi < 4; ++gi) acc[bi][gi] = 0ull;

        #pragma unroll 1
        for (int pass = 0; pass < 2; ++pass){
            const float* src;
            const float* W;
            if (pass == 0){
                if (t == 0) continue;               // h_{-1} = 0
                src = h_out + (size_t)(t-1) * BH;
                W = w_hh;
            } else {
                if (layer == 0) continue;           // IN=5 handled scalar below
                src = src_in + (size_t)t * BH;
                W = w_ih;
            }
            #pragma unroll 1
            for (int kc = 0; kc < 8; ++kc){
                // stage h tile: 64 rows x 64 k
                #pragma unroll
                for (int it = 0; it < 4; ++it){
                    int idx = tid + it * 256;       // 0..1023 float4 slots
                    int row = idx >> 4;
                    int kk  = (idx & 15) << 2;
                    float4 v = *(const float4*)(src + (size_t)(b0 + row) * Hn + kc*64 + kk);
                    *(float4*)&hs[row*68 + kk] = v;
                }
                // stage W tile: row r -> j = (r>>4)*512 + u0 + (r&15)
                #pragma unroll
                for (int it = 0; it < 4; ++it){
                    int idx = tid + it * 256;
                    int row = idx >> 4;
                    int kk  = (idx & 15) << 2;
                    int j = (row >> 4) * Hn + u0 + (row & 15);
                    float4 v = *(const float4*)(W + (size_t)j * Hn + kc*64 + kk);
                    *(float4*)&ws[row*68 + kk] = v;
                }
                __syncthreads();
                #pragma unroll 4
                for (int k4 = 0; k4 < 16; ++k4){
                    ulonglong2 hv[4], wv[4];
                    #pragma unroll
                    for (int bi = 0; bi < 4; ++bi)
                        hv[bi] = *(const ulonglong2*)&hs[(ty*4 + bi)*68 + k4*4];
                    #pragma unroll
                    for (int gi = 0; gi < 4; ++gi)
                        wv[gi] = *(const ulonglong2*)&ws[(gi*16 + tx)*68 + k4*4];
                    #pragma unroll
                    for (int bi = 0; bi < 4; ++bi)
                        #pragma unroll
                        for (int gi = 0; gi < 4; ++gi){
                            ffma2(acc[bi][gi], hv[bi].x, wv[gi].x);
                            ffma2(acc[bi][gi], hv[bi].y, wv[gi].y);
                        }
                }
                __syncthreads();
            }
        }

        // finalize gates + state update
        #pragma unroll
        for (int bi = 0; bi < 4; ++bi){
            int b = b0 + ty*4 + bi;
            float a[4];
            #pragma unroll
            for (int gi = 0; gi < 4; ++gi)
                a[gi] = pairsum(acc[bi][gi]) + bias[gi*Hn + u];

            if (layer == 0){
                const float* xr = x_time + ((size_t)b * Tn + t) * 5;
                float x0 = xr[0], x1 = xr[1], x2 = xr[2], x3 = xr[3], x4 = xr[4];
                #pragma unroll
                for (int gi = 0; gi < 4; ++gi){
                    const float* wr = w_ih0 + (size_t)(gi*Hn + u) * 5;
                    a[gi] += x0*wr[0] + x1*wr[1] + x2*wr[2] + x3*wr[3] + x4*wr[4];
                }
            }
            float ig = 1.f / (1.f + expf(-a[0]));
            float fg = 1.f / (1.f + expf(-a[1]));
            float gg = tanhf(a[2]);
            float og = 1.f / (1.f + expf(-a[3]));
            c[bi] = fg * c[bi] + ig * gg;
            float hvv = og * tanhf(c[bi]);
            h_out[(size_t)t * BH + (size_t)b * Hn + u] = hvv;
        }
        grid_barrier();
    }
}

// Heads: time_preds = lstm_out.reshape(B, T*H) @ fc1_w.T + fc1_b (index = t*H+u),
// stat_preds = x_stat @ fc2_w.T + fc2_b, preds = concat @ fc3_w.T + fc3_b.
__global__ void __launch_bounds__(256) heads_kernel(
    const float* __restrict__ x_stat,
    const float* __restrict__ fc1_w, const float* __restrict__ fc1_b,
    const float* __restrict__ fc2_w, const float* __restrict__ fc2_b,
    const float* __restrict__ fc3_w, const float* __restrict__ fc3_b,
    float* __restrict__ out)
{
    const int b = blockIdx.x;
    const int tid = threadIdx.x;
    const float* h1 = g_h1;

    float p0 = 0.f, p1 = 0.f;
    for (int idx = tid; idx < Tn*Hn; idx += 256){
        int t = idx >> 9;
        int u = idx & 511;
        float hv = h1[(size_t)t * BH + (size_t)b * Hn + u];
        p0 += hv * fc1_w[idx];
        p1 += hv * fc1_w[Tn*Hn + idx];
    }
    __shared__ float s0[256], s1[256];
    s0[tid] = p0; s1[tid] = p1;
    __syncthreads();
    for (int s = 128; s > 0; s >>= 1){
        if (tid < s){ s0[tid] += s0[tid+s]; s1[tid] += s1[tid+s]; }
        __syncthreads();
    }
    if (tid == 0){
        float tp0 = s0[0] + fc1_b[0];
        float tp1 = s1[0] + fc1_b[1];
        float xs0 = x_stat[b*3+0], xs1 = x_stat[b*3+1], xs2 = x_stat[b*3+2];
        float sp0 = fc2_b[0] + xs0*fc2_w[0] + xs1*fc2_w[1] + xs2*fc2_w[2];
        float sp1 = fc2_b[1] + xs0*fc2_w[3] + xs1*fc2_w[4] + xs2*fc2_w[5];
        out[b*2+0] = fc3_b[0] + fc3_w[0]*sp0 + fc3_w[1]*sp1 + fc3_w[2]*tp0 + fc3_w[3]*tp1;
        out[b*2+1] = fc3_b[1] + fc3_w[4]*sp0 + fc3_w[5]*sp1 + fc3_w[6]*tp0 + fc3_w[7]*tp1;
    }
}

extern "C" void kernel_launch(void* const* d_in, const int* in_sizes, int n_in,
                              void* d_out, int out_size)
{
    const float* x_time = (const float*)d_in[0];
    const float* x_stat = (const float*)d_in[1];
    const float* w_ih0  = (const float*)d_in[2];
    const float* w_hh0  = (const float*)d_in[3];
    const float* b0     = (const float*)d_in[4];
    const float* w_ih1  = (const float*)d_in[5];
    const float* w_hh1  = (const float*)d_in[6];
    const float* b1     = (const float*)d_in[7];
    const float* fc1_w  = (const float*)d_in[8];
    const float* fc1_b  = (const float*)d_in[9];
    const float* fc2_w  = (const float*)d_in[10];
    const float* fc2_b  = (const float*)d_in[11];
    const float* fc3_w  = (const float*)d_in[12];
    const float* fc3_b  = (const float*)d_in[13];
    float* out = (float*)d_out;

    lstm_layer_kernel<<<NCTA, 256>>>(x_time, w_ih0, /*w_ih=*/nullptr, w_hh0, b0, /*layer=*/0);
    lstm_layer_kernel<<<NCTA, 256>>>(x_time, w_ih0, /*w_ih=*/w_ih1,  w_hh1, b1, /*layer=*/1);
    heads_kernel<<<Bn, 256>>>(x_stat, fc1_w, fc1_b, fc2_w, fc2_b, fc3_w, fc3_b, out);
}

// round 3
// speedup vs baseline: 2.4444x; 2.4444x over previous
#include <cuda_runtime.h>
#include <cuda_bf16.h>
#include <cstdint>
#include <math.h>

#define Tn   256
#define Bn   256
#define Hn   512
#define BH   (Bn*Hn)
#define G4   2048
#define NCTA 128

// ---------------- device globals (scratch) ----------------
__device__ __align__(128) __nv_bfloat16 g_whh0_hi[G4*Hn];
__device__ __align__(128) __nv_bfloat16 g_whh0_lo[G4*Hn];
__device__ __align__(128) __nv_bfloat16 g_whh1_hi[G4*Hn];
__device__ __align__(128) __nv_bfloat16 g_whh1_lo[G4*Hn];
__device__ __align__(128) __nv_bfloat16 g_wih1_hi[G4*Hn];
__device__ __align__(128) __nv_bfloat16 g_wih1_lo[G4*Hn];
__device__ __align__(128) __nv_bfloat16 g_h0_hi[(size_t)Tn*BH];
__device__ __align__(128) __nv_bfloat16 g_h0_lo[(size_t)Tn*BH];
__device__ __align__(128) __nv_bfloat16 g_h1_hi[(size_t)Tn*BH];
__device__ __align__(128) __nv_bfloat16 g_h1_lo[(size_t)Tn*BH];
__device__ __align__(128) float g_xp[(size_t)Tn*Bn*G4];   // [t][nt][b][64] packed
__device__ unsigned g_count;
__device__ unsigned g_gen;

// ---------------- SMEM layout (bytes) ----------------
#define W_HI    0
#define W_LO    66560
#define A_BUF(b,p) (133120 + (b)*34816 + (p)*17408)
#define GBUF    202752
#define BIASOFF 221184
#define WIH0OFF 221440
#define SMEMSZ  222720
// W row stride: 520 bf16 = 1040 B ; A row stride: 136 bf16 = 272 B ; gbuf stride 72 f32

// ---------------- PTX helpers ----------------
__device__ __forceinline__ uint32_t su32(const void* p){
    uint32_t a;
    asm("{ .reg .u64 t; cvta.to.shared.u64 t, %1; cvt.u32.u64 %0, t; }" : "=r"(a) : "l"(p));
    return a;
}
__device__ __forceinline__ void ldmx4(uint32_t* r, uint32_t a){
    asm volatile("ldmatrix.sync.aligned.m8n8.x4.shared.b16 {%0,%1,%2,%3}, [%4];"
        : "=r"(r[0]), "=r"(r[1]), "=r"(r[2]), "=r"(r[3]) : "r"(a));
}
__device__ __forceinline__ void mma_bf16(float* c, const uint32_t* a, uint32_t b0, uint32_t b1){
    asm("mma.sync.aligned.m16n8k16.row.col.f32.bf16.bf16.f32 "
        "{%0,%1,%2,%3}, {%4,%5,%6,%7}, {%8,%9}, {%0,%1,%2,%3};"
        : "+f"(c[0]), "+f"(c[1]), "+f"(c[2]), "+f"(c[3])
        : "r"(a[0]), "r"(a[1]), "r"(a[2]), "r"(a[3]), "r"(b0), "r"(b1));
}
__device__ __forceinline__ void cpa16(uint32_t dst, const void* src){
    asm volatile("cp.async.cg.shared.global [%0], [%1], 16;" :: "r"(dst), "l"(src));
}
#define CP_COMMIT asm volatile("cp.async.commit_group;" ::: "memory")
#define CP_WAIT0  asm volatile("cp.async.wait_group 0;" ::: "memory")
#define CP_WAIT1  asm volatile("cp.async.wait_group 1;" ::: "memory")

// ---------------- grid barrier (R1-proven) ----------------
__device__ __forceinline__ void grid_barrier(){
    __syncthreads();
    if (threadIdx.x == 0){
        __threadfence();
        volatile unsigned* gen = &g_gen;
        unsigned g = *gen;
        unsigned t = atomicAdd(&g_count, 1u);
        if (t == NCTA - 1u){
            g_count = 0u;
            __threadfence();
            *gen = g + 1u;
        } else {
            while (*gen == g) { __nanosleep(32); }
            __threadfence();
        }
    }
    __syncthreads();
}

// ---------------- prologue: fp32 -> bf16 hi/lo split ----------------
__global__ void split_all_kernel(const float* __restrict__ whh0,
                                 const float* __restrict__ whh1,
                                 const float* __restrict__ wih1)
{
    int i = blockIdx.x * blockDim.x + threadIdx.x;
    if (i >= G4*Hn) return;
    {
        float x = whh0[i]; __nv_bfloat16 h = __float2bfloat16(x);
        g_whh0_hi[i] = h; g_whh0_lo[i] = __float2bfloat16(x - __bfloat162float(h));
    }
    {
        float x = whh1[i]; __nv_bfloat16 h = __float2bfloat16(x);
        g_whh1_hi[i] = h; g_whh1_lo[i] = __float2bfloat16(x - __bfloat162float(h));
    }
    {
        float x = wih1[i]; __nv_bfloat16 h = __float2bfloat16(x);
        g_wih1_hi[i] = h; g_wih1_lo[i] = __float2bfloat16(x - __bfloat162float(h));
    }
}

// ---------------- shared building blocks ----------------
// Stage one A chunk [64 rows x 128 k] hi+lo via cp.async (128 threads)
__device__ __forceinline__ void stage_A(const __nv_bfloat16* __restrict__ bh,
                                        const __nv_bfloat16* __restrict__ bl,
                                        int kc, uint32_t sAhi, uint32_t sAlo, int tid)
{
    #pragma unroll
    for (int it = 0; it < 8; ++it){
        int idx = tid + it*128;
        int row = idx >> 4;
        int kk  = (idx & 15) << 3;
        size_t go = (size_t)row * Hn + kc*128 + kk;
        uint32_t so = (uint32_t)(row*272 + kk*2);
        cpa16(sAhi + so, bh + go);
        cpa16(sAlo + so, bl + go);
    }
}

// Stage persistent W tile [64 packed rows x 512 k] for one pass (plain LDG/STS)
__device__ __forceinline__ void stage_W(const __nv_bfloat16* __restrict__ src,
                                        char* smem, int woff, int u0, int tid)
{
    for (int it = 0; it < 32; ++it){
        int idx = tid + it*128;
        int row = idx >> 6;
        int kk  = (idx & 63) << 3;
        int j = (row >> 4) * Hn + u0 + (row & 15);
        uint4 v = *(const uint4*)(src + (size_t)j * Hn + kk);
        *(uint4*)(smem + woff + row*1040 + kk*2) = v;
    }
}

// Compute one K=128 chunk: 8 k16 steps, 24 HMMA each (3-pass split-bf16)
__device__ __forceinline__ void compute_chunk(
    uint32_t aHi, uint32_t aLo,
    uint32_t bHi0, uint32_t bHi1, uint32_t bLo0, uint32_t bLo1,
    float* acc)
{
    #pragma unroll
    for (int k16 = 0; k16 < 8; ++k16){
        uint32_t ah0[4], ah1[4], al0[4], al1[4], bh[8], bl[8];
        ldmx4(ah0, aHi + k16*32);
        ldmx4(ah1, aHi + 4352 + k16*32);
        ldmx4(al0, aLo + k16*32);
        ldmx4(al1, aLo + 4352 + k16*32);
        ldmx4(bh,     bHi0 + k16*32);
        ldmx4(bh + 4, bHi1 + k16*32);
        ldmx4(bl,     bLo0 + k16*32);
        ldmx4(bl + 4, bLo1 + k16*32);
        #pragma unroll
        for (int nb = 0; nb < 4; ++nb){
            mma_bf16(acc + (0*4+nb)*4, ah0, bh[nb*2], bh[nb*2+1]);
            mma_bf16(acc + (1*4+nb)*4, ah1, bh[nb*2], bh[nb*2+1]);
            mma_bf16(acc + (0*4+nb)*4, ah0, bl[nb*2], bl[nb*2+1]);
            mma_bf16(acc + (1*4+nb)*4, ah1, bl[nb*2], bl[nb*2+1]);
            mma_bf16(acc + (0*4+nb)*4, al0, bh[nb*2], bh[nb*2+1]);
            mma_bf16(acc + (1*4+nb)*4, al1, bh[nb*2], bh[nb*2+1]);
        }
    }
}

// Dump C fragments to padded gate buffer (stride 72 floats)
__device__ __forceinline__ void dump_accs(float* gb, const float* acc, int m0, int n0, int lane)
{
    #pragma unroll
    for (int mb = 0; mb < 2; ++mb){
        #pragma unroll
        for (int nb = 0; nb < 4; ++nb){
            const float* c = acc + (mb*4+nb)*4;
            int row = m0 + mb*16 + (lane >> 2);
            int col = n0 + nb*8 + 2*(lane & 3);
            *(float2*)(gb + row*72 + col)     = make_float2(c[0], c[1]);
            *(float2*)(gb + (row+8)*72 + col) = make_float2(c[2], c[3]);
        }
    }
}

// ---------------- persistent recurrent layer ----------------
// Grid 128 = 4 b-tiles x 32 n-tiles. Block 128 thr = 4 warps (2x2 of 32x32 tiles).
__global__ void __launch_bounds__(128, 1) lstm_rec_kernel(
    const float* __restrict__ x_time, const float* __restrict__ w_ih0,
    const float* __restrict__ bias, int layer)
{
    extern __shared__ __align__(128) char smem[];
    const int tid  = threadIdx.x;
    const int lane = tid & 31;
    const int wid  = tid >> 5;
    const int m0   = (wid & 1) * 32;
    const int n0   = (wid >> 1) * 32;
    const int bt   = blockIdx.x & 3;
    const int nt   = blockIdx.x >> 2;
    const int b0   = bt * 64;
    const int u0   = nt * 16;
    const uint32_t sb = su32(smem);

    const __nv_bfloat16* whh_hi = layer ? g_whh1_hi : g_whh0_hi;
    const __nv_bfloat16* whh_lo = layer ? g_whh1_lo : g_whh0_lo;
    __nv_bfloat16* out_hi = layer ? g_h1_hi : g_h0_hi;
    __nv_bfloat16* out_lo = layer ? g_h1_lo : g_h0_lo;

    stage_W(whh_hi, smem, W_HI, u0, tid);
    stage_W(whh_lo, smem, W_LO, u0, tid);
    float* s_bias = (float*)(smem + BIASOFF);
    float* s_wih0 = (float*)(smem + WIH0OFF);
    if (tid < 64){
        int j = (tid >> 4) * Hn + u0 + (tid & 15);
        s_bias[tid] = bias[j];
        if (layer == 0){
            #pragma unroll
            for (int q = 0; q < 5; ++q) s_wih0[tid*5 + q] = w_ih0[(size_t)j*5 + q];
        }
    }
    __syncthreads();

    // per-lane ldmatrix byte offsets
    const uint32_t aoff = (uint32_t)((m0 + (lane & 15)) * 272 + (lane >> 4) * 16);
    const int prow = n0 + (lane & 7) + ((lane >> 4) & 1) * 8;
    const uint32_t boff0 = (uint32_t)(prow * 1040 + (((lane >> 3) & 1) * 8) * 2);
    const uint32_t boff1 = boff0 + 16 * 1040;

    float* gb = (float*)(smem + GBUF);
    const int bl = tid & 63;
    const int uh = tid >> 6;
    float c[8];
    #pragma unroll
    for (int i = 0; i < 8; ++i) c[i] = 0.f;

    for (int t = 0; t < Tn; ++t){
        float acc[32];
        #pragma unroll
        for (int i = 0; i < 32; ++i) acc[i] = 0.f;

        if (t > 0){
            const __nv_bfloat16* bh = out_hi + (size_t)(t-1)*BH + (size_t)b0*Hn;
            const __nv_bfloat16* blo = out_lo + (size_t)(t-1)*BH + (size_t)b0*Hn;
            stage_A(bh, blo, 0, sb + A_BUF(0,0), sb + A_BUF(0,1), tid);
            CP_COMMIT;
            #pragma unroll 1
            for (int kc = 0; kc < 4; ++kc){
                if (kc < 3){
                    int nb_ = (kc+1) & 1;
                    stage_A(bh, blo, kc+1, sb + A_BUF(nb_,0), sb + A_BUF(nb_,1), tid);
                    CP_COMMIT;
                    CP_WAIT1;
                } else {
                    CP_WAIT0;
                }
                __syncthreads();
                int cb = kc & 1;
                compute_chunk(sb + A_BUF(cb,0) + aoff, sb + A_BUF(cb,1) + aoff,
                              sb + W_HI + boff0 + kc*256, sb + W_HI + boff1 + kc*256,
                              sb + W_LO + boff0 + kc*256, sb + W_LO + boff1 + kc*256,
                              acc);
                __syncthreads();
            }
        }

        dump_accs(gb, acc, m0, n0, lane);
        __syncthreads();

        // epilogue: this thread owns b = b0+bl, cells u = u0 + uh*8 + j (j 0..7)
        float a[4][8];
        #pragma unroll
        for (int g = 0; g < 4; ++g){
            float4 v0 = *(float4*)(gb + bl*72 + g*16 + uh*8);
            float4 v1 = *(float4*)(gb + bl*72 + g*16 + uh*8 + 4);
            a[g][0]=v0.x; a[g][1]=v0.y; a[g][2]=v0.z; a[g][3]=v0.w;
            a[g][4]=v1.x; a[g][5]=v1.y; a[g][6]=v1.z; a[g][7]=v1.w;
            #pragma unroll
            for (int j = 0; j < 8; ++j) a[g][j] += s_bias[g*16 + uh*8 + j];
        }
        if (layer == 0){
            const float* xr = x_time + ((size_t)(b0+bl) * Tn + t) * 5;
            float x0=xr[0], x1=xr[1], x2=xr[2], x3=xr[3], x4=xr[4];
            #pragma unroll
            for (int g = 0; g < 4; ++g)
                #pragma unroll
                for (int j = 0; j < 8; ++j){
                    const float* wr = s_wih0 + (g*16 + uh*8 + j)*5;
                    a[g][j] += x0*wr[0] + x1*wr[1] + x2*wr[2] + x3*wr[3] + x4*wr[4];
                }
        } else {
            const float* xp = g_xp + (((size_t)t*32 + nt)*256 + (b0+bl))*64 + uh*8;
            #pragma unroll
            for (int g = 0; g < 4; ++g){
                float4 v0 = *(const float4*)(xp + g*16);
                float4 v1 = *(const float4*)(xp + g*16 + 4);
                a[g][0]+=v0.x; a[g][1]+=v0.y; a[g][2]+=v0.z; a[g][3]+=v0.w;
                a[g][4]+=v1.x; a[g][5]+=v1.y; a[g][6]+=v1.z; a[g][7]+=v1.w;
            }
        }
        __align__(16) __nv_bfloat16 hh[8], hl[8];
        #pragma unroll
        for (int j = 0; j < 8; ++j){
            float ig = 1.f / (1.f + expf(-a[0][j]));
            float fg = 1.f / (1.f + expf(-a[1][j]));
            float gg = tanhf(a[2][j]);
            float og = 1.f / (1.f + expf(-a[3][j]));
            c[j] = fg * c[j] + ig * gg;
            float hv = og * tanhf(c[j]);
            __nv_bfloat16 hb = __float2bfloat16(hv);
            hh[j] = hb;
            hl[j] = __float2bfloat16(hv - __bfloat162float(hb));
        }
        size_t ob = (size_t)t*BH + (size_t)(b0+bl)*Hn + u0 + uh*8;
        *(uint4*)(out_hi + ob) = *(const uint4*)hh;
        *(uint4*)(out_lo + ob) = *(const uint4*)hl;

        grid_barrier();
    }
}

// ---------------- parallel precompute: xp = h0 @ W_ih1^T (3-pass) ----------------
// Grid 1024 = 32 n-tiles x 32 m-groups; each CTA does 32 M-tiles of 64 rows.
__global__ void __launch_bounds__(128, 1) xp_kernel()
{
    extern __shared__ __align__(128) char smem[];
    const int tid  = threadIdx.x;
    const int lane = tid & 31;
    const int wid  = tid >> 5;
    const int m0   = (wid & 1) * 32;
    const int n0   = (wid >> 1) * 32;
    const int nt   = blockIdx.x & 31;
    const int mg   = blockIdx.x >> 5;
    const int u0   = nt * 16;
    const uint32_t sb = su32(smem);

    stage_W(g_wih1_hi, smem, W_HI, u0, tid);
    stage_W(g_wih1_lo, smem, W_LO, u0, tid);
    __syncthreads();

    const uint32_t aoff = (uint32_t)((m0 + (lane & 15)) * 272 + (lane >> 4) * 16);
    const int prow = n0 + (lane & 7) + ((lane >> 4) & 1) * 8;
    const uint32_t boff0 = (uint32_t)(prow * 1040 + (((lane >> 3) & 1) * 8) * 2);
    const uint32_t boff1 = boff0 + 16 * 1040;
    float* gb = (float*)(smem + GBUF);

    for (int mi = 0; mi < 32; ++mi){
        int mt = mg * 32 + mi;
        int t  = mt >> 2;
        int b0 = (mt & 3) * 64;
        const __nv_bfloat16* bh  = g_h0_hi + (size_t)t*BH + (size_t)b0*Hn;
        const __nv_bfloat16* blo = g_h0_lo + (size_t)t*BH + (size_t)b0*Hn;

        float acc[32];
        #pragma unroll
        for (int i = 0; i < 32; ++i) acc[i] = 0.f;

        stage_A(bh, blo, 0, sb + A_BUF(0,0), sb + A_BUF(0,1), tid);
        CP_COMMIT;
        #pragma unroll 1
        for (int kc = 0; kc < 4; ++kc){
            if (kc < 3){
                int nb_ = (kc+1) & 1;
                stage_A(bh, blo, kc+1, sb + A_BUF(nb_,0), sb + A_BUF(nb_,1), tid);
                CP_COMMIT;
                CP_WAIT1;
            } else {
                CP_WAIT0;
            }
            __syncthreads();
            int cb = kc & 1;
            compute_chunk(sb + A_BUF(cb,0) + aoff, sb + A_BUF(cb,1) + aoff,
                          sb + W_HI + boff0 + kc*256, sb + W_HI + boff1 + kc*256,
                          sb + W_LO + boff0 + kc*256, sb + W_LO + boff1 + kc*256,
                          acc);
            __syncthreads();
        }

        dump_accs(gb, acc, m0, n0, lane);
        __syncthreads();

        float* xpb = g_xp + (((size_t)t*32 + nt)*256 + b0)*64;
        #pragma unroll
        for (int s = 0; s < 8; ++s){
            int idx = tid + s*128;      // 1024 float4 groups
            int row = idx >> 4;
            int grp = idx & 15;
            float4 v = *(float4*)(gb + row*72 + grp*4);
            *(float4*)(xpb + (size_t)row*64 + grp*4) = v;
        }
        __syncthreads();
    }
}

// ---------------- heads ----------------
__global__ void __launch_bounds__(256) heads_kernel(
    const float* __restrict__ x_stat,
    const float* __restrict__ fc1_w, const float* __restrict__ fc1_b,
    const float* __restrict__ fc2_w, const float* __restrict__ fc2_b,
    const float* __restrict__ fc3_w, const float* __restrict__ fc3_b,
    float* __restrict__ out)
{
    const int b = blockIdx.x;
    const int tid = threadIdx.x;

    float p0 = 0.f, p1 = 0.f;
    for (int idx = tid; idx < Tn*Hn; idx += 256){
        int t = idx >> 9;
        int u = idx & 511;
        size_t off = (size_t)t * BH + (size_t)b * Hn + u;
        float hv = __bfloat162float(g_h1_hi[off]) + __bfloat162float(g_h1_lo[off]);
        p0 += hv * fc1_w[idx];
        p1 += hv * fc1_w[Tn*Hn + idx];
    }
    __shared__ float s0[256], s1[256];
    s0[tid] = p0; s1[tid] = p1;
    __syncthreads();
    for (int s = 128; s > 0; s >>= 1){
        if (tid < s){ s0[tid] += s0[tid+s]; s1[tid] += s1[tid+s]; }
        __syncthreads();
    }
    if (tid == 0){
        float tp0 = s0[0] + fc1_b[0];
        float tp1 = s1[0] + fc1_b[1];
        float xs0 = x_stat[b*3+0], xs1 = x_stat[b*3+1], xs2 = x_stat[b*3+2];
        float sp0 = fc2_b[0] + xs0*fc2_w[0] + xs1*fc2_w[1] + xs2*fc2_w[2];
        float sp1 = fc2_b[1] + xs0*fc2_w[3] + xs1*fc2_w[4] + xs2*fc2_w[5];
        out[b*2+0] = fc3_b[0] + fc3_w[0]*sp0 + fc3_w[1]*sp1 + fc3_w[2]*tp0 + fc3_w[3]*tp1;
        out[b*2+1] = fc3_b[1] + fc3_w[4]*sp0 + fc3_w[5]*sp1 + fc3_w[6]*tp0 + fc3_w[7]*tp1;
    }
}

extern "C" void kernel_launch(void* const* d_in, const int* in_sizes, int n_in,
                              void* d_out, int out_size)
{
    const float* x_time = (const float*)d_in[0];
    const float* x_stat = (const float*)d_in[1];
    const float* w_ih0  = (const float*)d_in[2];
    const float* w_hh0  = (const float*)d_in[3];
    const float* b0     = (const float*)d_in[4];
    const float* w_ih1  = (const float*)d_in[5];
    const float* w_hh1  = (const float*)d_in[6];
    const float* b1     = (const float*)d_in[7];
    const float* fc1_w  = (const float*)d_in[8];
    const float* fc1_b  = (const float*)d_in[9];
    const float* fc2_w  = (const float*)d_in[10];
    const float* fc2_b  = (const float*)d_in[11];
    const float* fc3_w  = (const float*)d_in[12];
    const float* fc3_b  = (const float*)d_in[13];
    float* out = (float*)d_out;

    cudaFuncSetAttribute(lstm_rec_kernel, cudaFuncAttributeMaxDynamicSharedMemorySize, SMEMSZ);
    cudaFuncSetAttribute(xp_kernel,       cudaFuncAttributeMaxDynamicSharedMemorySize, SMEMSZ);

    split_all_kernel<<<(G4*Hn + 255)/256, 256>>>(w_hh0, w_hh1, w_ih1);
    lstm_rec_kernel<<<NCTA, 128, SMEMSZ>>>(x_time, w_ih0, b0, 0);
    xp_kernel<<<1024, 128, SMEMSZ>>>();
    lstm_rec_kernel<<<NCTA, 128, SMEMSZ>>>(x_time, w_ih0, b1, 1);
    heads_kernel<<<Bn, 256>>>(x_stat, fc1_w, fc1_b, fc2_w, fc2_b, fc3_w, fc3_b, out);
}

// round 4
// speedup vs baseline: 2.4713x; 1.0110x over previous
#include <cuda_runtime.h>
#include <cuda_bf16.h>
#include <cstdint>
#include <math.h>

#define Tn   256
#define Bn   256
#define Hn   512
#define BH   (Bn*Hn)
#define G4   2048
#define NCTA 128

// ---------------- device globals (scratch) ----------------
__device__ __align__(128) __nv_bfloat16 g_whh0_hi[G4*Hn];
__device__ __align__(128) __nv_bfloat16 g_whh0_lo[G4*Hn];
__device__ __align__(128) __nv_bfloat16 g_whh1_hi[G4*Hn];
__device__ __align__(128) __nv_bfloat16 g_whh1_lo[G4*Hn];
__device__ __align__(128) __nv_bfloat16 g_wih1_hi[G4*Hn];
__device__ __align__(128) __nv_bfloat16 g_wih1_lo[G4*Hn];
__device__ __align__(128) __nv_bfloat16 g_h0_hi[(size_t)Tn*BH];
__device__ __align__(128) __nv_bfloat16 g_h0_lo[(size_t)Tn*BH];
__device__ __align__(128) __nv_bfloat16 g_h1_hi[(size_t)Tn*BH];
__device__ __align__(128) __nv_bfloat16 g_h1_lo[(size_t)Tn*BH];
__device__ __align__(128) float g_xp[(size_t)Tn*Bn*G4];   // fragment-layout [t][bt][nt][tid][32]
__device__ unsigned g_count;
__device__ unsigned g_gen;

// ---------------- SMEM layout (bytes) ----------------
// W rows: 64 packed rows (pr = g*16+uu), stride 1040 B (512 bf16 + 8 pad)
// A rows: 64 b-rows, stride 272 B (128 bf16 + 8 pad)
#define W_HI    0
#define W_LO    66560
#define A_BUF(b,p) (133120 + (b)*34816 + (p)*17408)
#define BIASOFF 202752
#define WIH0OFF 203008
#define SMEMSZ  204800

// ---------------- PTX helpers ----------------
__device__ __forceinline__ uint32_t su32(const void* p){
    uint32_t a;
    asm("{ .reg .u64 t; cvta.to.shared.u64 t, %1; cvt.u32.u64 %0, t; }" : "=r"(a) : "l"(p));
    return a;
}
__device__ __forceinline__ void ldmx4(uint32_t* r, uint32_t a){
    asm volatile("ldmatrix.sync.aligned.m8n8.x4.shared.b16 {%0,%1,%2,%3}, [%4];"
        : "=r"(r[0]), "=r"(r[1]), "=r"(r[2]), "=r"(r[3]) : "r"(a));
}
__device__ __forceinline__ void mma_bf16(float* c, const uint32_t* a, uint32_t b0, uint32_t b1){
    asm("mma.sync.aligned.m16n8k16.row.col.f32.bf16.bf16.f32 "
        "{%0,%1,%2,%3}, {%4,%5,%6,%7}, {%8,%9}, {%0,%1,%2,%3};"
        : "+f"(c[0]), "+f"(c[1]), "+f"(c[2]), "+f"(c[3])
        : "r"(a[0]), "r"(a[1]), "r"(a[2]), "r"(a[3]), "r"(b0), "r"(b1));
}
__device__ __forceinline__ void cpa16(uint32_t dst, const void* src){
    asm volatile("cp.async.cg.shared.global [%0], [%1], 16;" :: "r"(dst), "l"(src));
}
#define CP_COMMIT asm volatile("cp.async.commit_group;" ::: "memory")
#define CP_WAIT0  asm volatile("cp.async.wait_group 0;" ::: "memory")
#define CP_WAIT1  asm volatile("cp.async.wait_group 1;" ::: "memory")

__device__ __forceinline__ uint32_t packbf2(float a, float b){
    __nv_bfloat162 v = __floats2bfloat162_rn(a, b);
    return *(uint32_t*)&v;
}

// ---------------- grid barrier (tight spin, no nanosleep) ----------------
__device__ __forceinline__ void grid_barrier(){
    __syncthreads();
    if (threadIdx.x == 0){
        __threadfence();
        volatile unsigned* gen = &g_gen;
        unsigned g = *gen;
        unsigned t = atomicAdd(&g_count, 1u);
        if (t == NCTA - 1u){
            g_count = 0u;
            __threadfence();
            *gen = g + 1u;
        } else {
            while (*gen == g) {}
            __threadfence();
        }
    }
    __syncthreads();
}

// ---------------- prologue: fp32 -> bf16 hi/lo split ----------------
__global__ void split_all_kernel(const float* __restrict__ whh0,
                                 const float* __restrict__ whh1,
                                 const float* __restrict__ wih1)
{
    int i = blockIdx.x * blockDim.x + threadIdx.x;
    if (i >= G4*Hn) return;
    {
        float x = whh0[i]; __nv_bfloat16 h = __float2bfloat16(x);
        g_whh0_hi[i] = h; g_whh0_lo[i] = __float2bfloat16(x - __bfloat162float(h));
    }
    {
        float x = whh1[i]; __nv_bfloat16 h = __float2bfloat16(x);
        g_whh1_hi[i] = h; g_whh1_lo[i] = __float2bfloat16(x - __bfloat162float(h));
    }
    {
        float x = wih1[i]; __nv_bfloat16 h = __float2bfloat16(x);
        g_wih1_hi[i] = h; g_wih1_lo[i] = __float2bfloat16(x - __bfloat162float(h));
    }
}

// ---------------- staging ----------------
__device__ __forceinline__ void stage_A(const __nv_bfloat16* __restrict__ bh,
                                        const __nv_bfloat16* __restrict__ bl,
                                        int kc, uint32_t sAhi, uint32_t sAlo, int tid)
{
    #pragma unroll
    for (int it = 0; it < 8; ++it){
        int idx = tid + it*128;
        int row = idx >> 4;
        int kk  = (idx & 15) << 3;
        size_t go = (size_t)row * Hn + kc*128 + kk;
        uint32_t so = (uint32_t)(row*272 + kk*2);
        cpa16(sAhi + so, bh + go);
        cpa16(sAlo + so, bl + go);
    }
}

__device__ __forceinline__ void stage_W(const __nv_bfloat16* __restrict__ src,
                                        char* smem, int woff, int u0, int tid)
{
    for (int it = 0; it < 32; ++it){
        int idx = tid + it*128;
        int row = idx >> 6;
        int kk  = (idx & 63) << 3;
        int j = (row >> 4) * Hn + u0 + (row & 15);
        uint4 v = *(const uint4*)(src + (size_t)j * Hn + kk);
        *(uint4*)(smem + woff + row*1040 + kk*2) = v;
    }
}

// ---------------- fragment pipeline ----------------
struct Frags { uint32_t ah[4], al[4], bh[16], bl[16]; };

__device__ __forceinline__ void load_frags(Frags& f, uint32_t aHi, uint32_t aLo,
                                           uint32_t wHi, uint32_t wLo, int k16)
{
    ldmx4(f.ah, aHi + k16*32);
    ldmx4(f.al, aLo + k16*32);
    #pragma unroll
    for (int cb = 0; cb < 4; ++cb){
        ldmx4(f.bh + cb*4, wHi + cb*16*1040 + k16*32);
        ldmx4(f.bl + cb*4, wLo + cb*16*1040 + k16*32);
    }
}
__device__ __forceinline__ void do_hmma(float* acc, const Frags& f){
    #pragma unroll
    for (int nb = 0; nb < 8; ++nb){
        mma_bf16(acc + nb*4, f.ah, f.bh[nb*2], f.bh[nb*2+1]);
        mma_bf16(acc + nb*4, f.ah, f.bl[nb*2], f.bl[nb*2+1]);
        mma_bf16(acc + nb*4, f.al, f.bh[nb*2], f.bh[nb*2+1]);
    }
}

// one K=128 chunk with fragment double-buffering
__device__ __forceinline__ void compute_chunk(uint32_t aHi, uint32_t aLo,
                                              uint32_t wHi, uint32_t wLo, float* acc)
{
    Frags f[2];
    load_frags(f[0], aHi, aLo, wHi, wLo, 0);
    #pragma unroll
    for (int k16 = 0; k16 < 8; ++k16){
        if (k16 < 7) load_frags(f[(k16+1)&1], aHi, aLo, wHi, wLo, k16+1);
        do_hmma(acc, f[k16&1]);
    }
}

// full K=512, 4 chunks, double-buffered cp.async
__device__ __forceinline__ void gemm_step(const __nv_bfloat16* __restrict__ bh,
                                          const __nv_bfloat16* __restrict__ bl,
                                          uint32_t sb, uint32_t aoff, uint32_t wboff,
                                          int whoff, int wloff, float* acc, int tid)
{
    stage_A(bh, bl, 0, sb + A_BUF(0,0), sb + A_BUF(0,1), tid);
    CP_COMMIT;
    #pragma unroll 1
    for (int kc = 0; kc < 4; ++kc){
        if (kc < 3){
            int nb_ = (kc+1) & 1;
            stage_A(bh, bl, kc+1, sb + A_BUF(nb_,0), sb + A_BUF(nb_,1), tid);
            CP_COMMIT;
            CP_WAIT1;
        } else {
            CP_WAIT0;
        }
        __syncthreads();
        int cb = kc & 1;
        compute_chunk(sb + A_BUF(cb,0) + aoff, sb + A_BUF(cb,1) + aoff,
                      sb + whoff + wboff + kc*256, sb + wloff + wboff + kc*256, acc);
        __syncthreads();
    }
}

// ---------------- persistent recurrent layer ----------------
// Grid 128 = 4 b-tiles(64) x 32 n-tiles(16u). 128 thr = 4 warps, warp tile 16x64.
__global__ void __launch_bounds__(128, 1) lstm_rec_kernel(
    const float* __restrict__ x_time, const float* __restrict__ w_ih0,
    const float* __restrict__ bias, int layer)
{
    extern __shared__ __align__(128) char smem[];
    const int tid  = threadIdx.x;
    const int lane = tid & 31;
    const int wid  = tid >> 5;
    const int bt   = blockIdx.x & 3;
    const int nt   = blockIdx.x >> 2;
    const int b0   = bt * 64;
    const int u0   = nt * 16;
    const uint32_t sb = su32(smem);

    const __nv_bfloat16* whh_hi = layer ? g_whh1_hi : g_whh0_hi;
    const __nv_bfloat16* whh_lo = layer ? g_whh1_lo : g_whh0_lo;
    __nv_bfloat16* out_hi = layer ? g_h1_hi : g_h0_hi;
    __nv_bfloat16* out_lo = layer ? g_h1_lo : g_h0_lo;

    stage_W(whh_hi, smem, W_HI, u0, tid);
    stage_W(whh_lo, smem, W_LO, u0, tid);
    float* s_wih0 = (float*)(smem + WIH0OFF);
    if (layer == 0 && tid < 64){
        int j = (tid >> 4) * Hn + u0 + (tid & 15);
        #pragma unroll
        for (int q = 0; q < 5; ++q) s_wih0[tid*5 + q] = w_ih0[(size_t)j*5 + q];
    }
    __syncthreads();

    // per-lane ldmatrix offsets
    const uint32_t aoff  = (uint32_t)((wid*16 + (lane & 15)) * 272 + (lane >> 4) * 16);
    const uint32_t wboff = (uint32_t)(((lane & 7) + ((lane >> 4) & 1) * 8) * 1040
                                      + ((lane >> 3) & 1) * 16);

    // cell ownership: rows {ra, rb}, u-locals {q2, q2+1, q2+8, q2+9}
    const int q2 = 2 * (lane & 3);
    const int ra = wid*16 + (lane >> 2);
    const int rb = ra + 8;

    // preload bias (layer 0 only; layer 1 bias folded into xp)
    float breg[4][4];
    if (layer == 0){
        #pragma unroll
        for (int g = 0; g < 4; ++g){
            breg[g][0] = bias[g*Hn + u0 + q2];
            breg[g][1] = bias[g*Hn + u0 + q2 + 1];
            breg[g][2] = bias[g*Hn + u0 + q2 + 8];
            breg[g][3] = bias[g*Hn + u0 + q2 + 9];
        }
    }

    float c[8];
    #pragma unroll
    for (int i = 0; i < 8; ++i) c[i] = 0.f;

    for (int t = 0; t < Tn; ++t){
        float acc[32];
        #pragma unroll
        for (int i = 0; i < 32; ++i) acc[i] = 0.f;

        if (t > 0){
            gemm_step(out_hi + (size_t)(t-1)*BH + (size_t)b0*Hn,
                      out_lo + (size_t)(t-1)*BH + (size_t)b0*Hn,
                      sb, aoff, wboff, W_HI, W_LO, acc, tid);
        }

        // add xp (layer1) or bias + x-projection (layer0)
        if (layer == 1){
            const float* xp = g_xp + ((((size_t)t*4 + bt)*32 + nt)*128 + tid)*32;
            #pragma unroll
            for (int i = 0; i < 8; ++i){
                float4 v = *(const float4*)(xp + i*4);
                acc[i*4+0] += v.x; acc[i*4+1] += v.y; acc[i*4+2] += v.z; acc[i*4+3] += v.w;
            }
        } else {
            const float* xra = x_time + ((size_t)(b0+ra) * Tn + t) * 5;
            const float* xrb = x_time + ((size_t)(b0+rb) * Tn + t) * 5;
            float xa[5], xb[5];
            #pragma unroll
            for (int q = 0; q < 5; ++q){ xa[q] = xra[q]; xb[q] = xrb[q]; }
            #pragma unroll
            for (int g = 0; g < 4; ++g){
                #pragma unroll
                for (int us = 0; us < 4; ++us){
                    int uu = (us < 2) ? (q2 + us) : (q2 + 6 + us);
                    const float* wr = s_wih0 + (g*16 + uu)*5;
                    float da = breg[g][us], db = breg[g][us];
                    #pragma unroll
                    for (int q = 0; q < 5; ++q){ da += xa[q]*wr[q]; db += xb[q]*wr[q]; }
                    int nb = 2*g + (us >> 1);
                    acc[nb*4 + (us & 1)]     += da;
                    acc[nb*4 + 2 + (us & 1)] += db;
                }
            }
        }

        // in-register epilogue: 8 cells per thread (2 rows x 4 u)
        #pragma unroll
        for (int rs = 0; rs < 2; ++rs){
            int row = rs ? rb : ra;
            float hv[4];
            #pragma unroll
            for (int us = 0; us < 4; ++us){
                int nbo = (us >> 1);         // 0: u in [0,8), 1: u in [8,16)
                int j   = rs*2 + (us & 1);
                float ai = acc[(0 + nbo)*4 + j];
                float af = acc[(2 + nbo)*4 + j];
                float ag = acc[(4 + nbo)*4 + j];
                float ao = acc[(6 + nbo)*4 + j];
                float ig = 1.f / (1.f + expf(-ai));
                float fg = 1.f / (1.f + expf(-af));
                float gg = tanhf(ag);
                float og = 1.f / (1.f + expf(-ao));
                int ci = rs*4 + us;
                c[ci] = fg * c[ci] + ig * gg;
                hv[us] = og * tanhf(c[ci]);
            }
            size_t ob = (size_t)t*BH + (size_t)(b0+row)*Hn + u0;
            uint32_t p0 = packbf2(hv[0], hv[1]);
            uint32_t p1 = packbf2(hv[2], hv[3]);
            *(uint32_t*)(out_hi + ob + q2)     = p0;
            *(uint32_t*)(out_hi + ob + q2 + 8) = p1;
            __nv_bfloat162 h0b = *(__nv_bfloat162*)&p0;
            __nv_bfloat162 h1b = *(__nv_bfloat162*)&p1;
            *(uint32_t*)(out_lo + ob + q2) =
                packbf2(hv[0] - __bfloat162float(h0b.x), hv[1] - __bfloat162float(h0b.y));
            *(uint32_t*)(out_lo + ob + q2 + 8) =
                packbf2(hv[2] - __bfloat162float(h1b.x), hv[3] - __bfloat162float(h1b.y));
        }

        grid_barrier();
    }
}

// ---------------- parallel precompute: xp = h0 @ W_ih1^T + b1 (fragment layout) ----------------
// Grid 512 = 32 nt x 16 groups; each CTA does 64 (t,bt) tiles with W resident.
__global__ void __launch_bounds__(128, 1) xp_kernel(const float* __restrict__ bias)
{
    extern __shared__ __align__(128) char smem[];
    const int tid  = threadIdx.x;
    const int lane = tid & 31;
    const int wid  = tid >> 5;
    const int nt   = blockIdx.x & 31;
    const int grp  = blockIdx.x >> 5;
    const int u0   = nt * 16;
    const uint32_t sb = su32(smem);

    stage_W(g_wih1_hi, smem, W_HI, u0, tid);
    stage_W(g_wih1_lo, smem, W_LO, u0, tid);
    __syncthreads();

    const uint32_t aoff  = (uint32_t)((wid*16 + (lane & 15)) * 272 + (lane >> 4) * 16);
    const uint32_t wboff = (uint32_t)(((lane & 7) + ((lane >> 4) & 1) * 8) * 1040
                                      + ((lane >> 3) & 1) * 16);
    const int q2 = 2 * (lane & 3);

    // bias per acc slot: col(nb, j&1) = nb*8 + q2 + (j&1)
    float bx[8][2];
    #pragma unroll
    for (int nb = 0; nb < 8; ++nb){
        int colb = (nb >> 1)*Hn + u0 + (nb & 1)*8 + q2;
        bx[nb][0] = bias[colb];
        bx[nb][1] = bias[colb + 1];
    }

    for (int mi = 0; mi < 64; ++mi){
        int mt = grp * 64 + mi;
        int t  = mt >> 2;
        int bt = mt & 3;
        int b0 = bt * 64;

        float acc[32];
        #pragma unroll
        for (int i = 0; i < 32; ++i) acc[i] = 0.f;

        gemm_step(g_h0_hi + (size_t)t*BH + (size_t)b0*Hn,
                  g_h0_lo + (size_t)t*BH + (size_t)b0*Hn,
                  sb, aoff, wboff, W_HI, W_LO, acc, tid);

        float* xp = g_xp + ((((size_t)t*4 + bt)*32 + nt)*128 + tid)*32;
        #pragma unroll
        for (int nb = 0; nb < 8; ++nb){
            float4 v;
            v.x = acc[nb*4+0] + bx[nb][0];
            v.y = acc[nb*4+1] + bx[nb][1];
            v.z = acc[nb*4+2] + bx[nb][0];
            v.w = acc[nb*4+3] + bx[nb][1];
            *(float4*)(xp + nb*4) = v;
        }
    }
}

// ---------------- heads ----------------
__global__ void __launch_bounds__(256) heads_kernel(
    const float* __restrict__ x_stat,
    const float* __restrict__ fc1_w, const float* __restrict__ fc1_b,
    const float* __restrict__ fc2_w, const float* __restrict__ fc2_b,
    const float* __restrict__ fc3_w, const float* __restrict__ fc3_b,
    float* __restrict__ out)
{
    const int b = blockIdx.x;
    const int tid = threadIdx.x;

    float p0 = 0.f, p1 = 0.f;
    for (int idx = tid; idx < Tn*Hn; idx += 256){
        int t = idx >> 9;
        int u = idx & 511;
        size_t off = (size_t)t * BH + (size_t)b * Hn + u;
        float hv = __bfloat162float(g_h1_hi[off]) + __bfloat162float(g_h1_lo[off]);
        p0 += hv * fc1_w[idx];
        p1 += hv * fc1_w[Tn*Hn + idx];
    }
    __shared__ float s0[256], s1[256];
    s0[tid] = p0; s1[tid] = p1;
    __syncthreads();
    for (int s = 128; s > 0; s >>= 1){
        if (tid < s){ s0[tid] += s0[tid+s]; s1[tid] += s1[tid+s]; }
        __syncthreads();
    }
    if (tid == 0){
        float tp0 = s0[0] + fc1_b[0];
        float tp1 = s1[0] + fc1_b[1];
        float xs0 = x_stat[b*3+0], xs1 = x_stat[b*3+1], xs2 = x_stat[b*3+2];
        float sp0 = fc2_b[0] + xs0*fc2_w[0] + xs1*fc2_w[1] + xs2*fc2_w[2];
        float sp1 = fc2_b[1] + xs0*fc2_w[3] + xs1*fc2_w[4] + xs2*fc2_w[5];
        out[b*2+0] = fc3_b[0] + fc3_w[0]*sp0 + fc3_w[1]*sp1 + fc3_w[2]*tp0 + fc3_w[3]*tp1;
        out[b*2+1] = fc3_b[1] + fc3_w[4]*sp0 + fc3_w[5]*sp1 + fc3_w[6]*tp0 + fc3_w[7]*tp1;
    }
}

extern "C" void kernel_launch(void* const* d_in, const int* in_sizes, int n_in,
                              void* d_out, int out_size)
{
    const float* x_time = (const float*)d_in[0];
    const float* x_stat = (const float*)d_in[1];
    const float* w_ih0  = (const float*)d_in[2];
    const float* w_hh0  = (const float*)d_in[3];
    const float* b0     = (const float*)d_in[4];
    const float* w_ih1  = (const float*)d_in[5];
    const float* w_hh1  = (const float*)d_in[6];
    const float* b1     = (const float*)d_in[7];
    const float* fc1_w  = (const float*)d_in[8];
    const float* fc1_b  = (const float*)d_in[9];
    const float* fc2_w  = (const float*)d_in[10];
    const float* fc2_b  = (const float*)d_in[11];
    const float* fc3_w  = (const float*)d_in[12];
    const float* fc3_b  = (const float*)d_in[13];
    float* out = (float*)d_out;

    cudaFuncSetAttribute(lstm_rec_kernel, cudaFuncAttributeMaxDynamicSharedMemorySize, SMEMSZ);
    cudaFuncSetAttribute(xp_kernel,       cudaFuncAttributeMaxDynamicSharedMemorySize, SMEMSZ);

    split_all_kernel<<<(G4*Hn + 255)/256, 256>>>(w_hh0, w_hh1, w_ih1);
    lstm_rec_kernel<<<NCTA, 128, SMEMSZ>>>(x_time, w_ih0, b0, 0);
    xp_kernel<<<512, 128, SMEMSZ>>>(b1);
    lstm_rec_kernel<<<NCTA, 128, SMEMSZ>>>(x_time, w_ih0, b1, 1);
    heads_kernel<<<Bn, 256>>>(x_stat, fc1_w, fc1_b, fc2_w, fc2_b, fc3_w, fc3_b, out);
}

// round 5
// speedup vs baseline: 2.8165x; 1.1397x over previous
#include <cuda_runtime.h>
#include <cuda_bf16.h>
#include <cstdint>
#include <math.h>

#define Tn   256
#define Bn   256
#define Hn   512
#define BH   (Bn*Hn)
#define G4   2048
#define NCTA 128

// ---------------- device globals (scratch) ----------------
__device__ __align__(128) __nv_bfloat16 g_whh0_hi[G4*Hn];
__device__ __align__(128) __nv_bfloat16 g_whh0_lo[G4*Hn];
__device__ __align__(128) __nv_bfloat16 g_whh1_hi[G4*Hn];
__device__ __align__(128) __nv_bfloat16 g_whh1_lo[G4*Hn];
__device__ __align__(128) __nv_bfloat16 g_wih1_hi[G4*Hn];
__device__ __align__(128) __nv_bfloat16 g_wih1_lo[G4*Hn];
__device__ __align__(128) __nv_bfloat16 g_h0_hi[(size_t)Tn*BH];
__device__ __align__(128) __nv_bfloat16 g_h0_lo[(size_t)Tn*BH];
__device__ __align__(128) __nv_bfloat16 g_h1_hi[(size_t)Tn*BH];
__device__ __align__(128) __nv_bfloat16 g_h1_lo[(size_t)Tn*BH];
__device__ __align__(128) float g_xp[(size_t)Tn*Bn*G4];   // [t][bt][nt][tid(256)][16]
__device__ __align__(128) unsigned g_flag[4*32*32];       // (bt*32+nt)*32, 128B padded

// ---------------- SMEM layout (bytes) ----------------
// W rows: 64 packed rows pr = nh*32 + g*8 + u, stride 1040 B (512 bf16 + 8 pad)
// A rows: 64 b-rows, stride 272 B (128 bf16 + 8 pad)
#define W_HI    0
#define W_LO    66560
#define A_BUF(db,p) (133120 + (db)*34816 + (p)*17408)
#define WIH0OFF 202752
#define SMEMSZ  204800

// ---------------- PTX helpers ----------------
__device__ __forceinline__ uint32_t su32(const void* p){
    uint32_t a;
    asm("{ .reg .u64 t; cvta.to.shared.u64 t, %1; cvt.u32.u64 %0, t; }" : "=r"(a) : "l"(p));
    return a;
}
__device__ __forceinline__ void ldmx4(uint32_t* r, uint32_t a){
    asm volatile("ldmatrix.sync.aligned.m8n8.x4.shared.b16 {%0,%1,%2,%3}, [%4];"
        : "=r"(r[0]), "=r"(r[1]), "=r"(r[2]), "=r"(r[3]) : "r"(a));
}
__device__ __forceinline__ void mma_bf16(float* c, const uint32_t* a, uint32_t b0, uint32_t b1){
    asm("mma.sync.aligned.m16n8k16.row.col.f32.bf16.bf16.f32 "
        "{%0,%1,%2,%3}, {%4,%5,%6,%7}, {%8,%9}, {%0,%1,%2,%3};"
        : "+f"(c[0]), "+f"(c[1]), "+f"(c[2]), "+f"(c[3])
        : "r"(a[0]), "r"(a[1]), "r"(a[2]), "r"(a[3]), "r"(b0), "r"(b1));
}
__device__ __forceinline__ void cpa16(uint32_t dst, const void* src){
    asm volatile("cp.async.cg.shared.global [%0], [%1], 16;" :: "r"(dst), "l"(src));
}
#define CP_COMMIT asm volatile("cp.async.commit_group;" ::: "memory")
#define CP_WAIT0  asm volatile("cp.async.wait_group 0;" ::: "memory")
#define CP_WAIT1  asm volatile("cp.async.wait_group 1;" ::: "memory")

__device__ __forceinline__ uint32_t packbf2(float a, float b){
    __nv_bfloat162 v = __floats2bfloat162_rn(a, b);
    return *(uint32_t*)&v;
}

// ---------------- per-b-group barrier: 32 CTAs, all-to-all flags ----------------
__device__ __forceinline__ void group_barrier(int bt, int nt, unsigned tgt, int tid){
    __syncthreads();
    if (tid == 0){
        __threadfence();
        *((volatile unsigned*)&g_flag[(bt*32 + nt)*32]) = tgt;
    }
    if (tid < 32){
        while (*((volatile unsigned*)&g_flag[(bt*32 + tid)*32]) < tgt) {}
        __threadfence();
    }
    __syncthreads();
}

// ---------------- prologue: fp32 -> bf16 hi/lo split + flag reset ----------------
__global__ void split_all_kernel(const float* __restrict__ whh0,
                                 const float* __restrict__ whh1,
                                 const float* __restrict__ wih1)
{
    int i = blockIdx.x * blockDim.x + threadIdx.x;
    if (blockIdx.x == 0 && threadIdx.x < 128) g_flag[threadIdx.x * 32] = 0u;
    if (i >= G4*Hn) return;
    {
        float x = whh0[i]; __nv_bfloat16 h = __float2bfloat16(x);
        g_whh0_hi[i] = h; g_whh0_lo[i] = __float2bfloat16(x - __bfloat162float(h));
    }
    {
        float x = whh1[i]; __nv_bfloat16 h = __float2bfloat16(x);
        g_whh1_hi[i] = h; g_whh1_lo[i] = __float2bfloat16(x - __bfloat162float(h));
    }
    {
        float x = wih1[i]; __nv_bfloat16 h = __float2bfloat16(x);
        g_wih1_hi[i] = h; g_wih1_lo[i] = __float2bfloat16(x - __bfloat162float(h));
    }
}

// ---------------- staging (256 threads) ----------------
__device__ __forceinline__ void stage_A(const __nv_bfloat16* __restrict__ bh,
                                        const __nv_bfloat16* __restrict__ bl,
                                        int kc, uint32_t sAhi, uint32_t sAlo, int tid)
{
    #pragma unroll
    for (int it = 0; it < 4; ++it){
        int idx = tid + it*256;
        int row = idx >> 4;
        int kk  = (idx & 15) << 3;
        size_t go = (size_t)row * Hn + kc*128 + kk;
        uint32_t so = (uint32_t)(row*272 + kk*2);
        cpa16(sAhi + so, bh + go);
        cpa16(sAlo + so, bl + go);
    }
}

// packed row pr -> weight row j: g=(pr>>3)&3, u = (pr&7) + (pr>>5)*8
__device__ __forceinline__ void stage_W(const __nv_bfloat16* __restrict__ src,
                                        char* smem, int woff, int u0, int tid)
{
    for (int it = 0; it < 16; ++it){
        int idx = tid + it*256;
        int row = idx >> 6;
        int kk  = (idx & 63) << 3;
        int j = ((row >> 3) & 3) * Hn + u0 + (row & 7) + (row >> 5) * 8;
        uint4 v = *(const uint4*)(src + (size_t)j * Hn + kk);
        *(uint4*)(smem + woff + row*1040 + kk*2) = v;
    }
}

// ---------------- fragment pipeline (warp tile 16x32) ----------------
struct Frags { uint32_t ah[4], al[4], bh[8], bl[8]; };

__device__ __forceinline__ void load_frags(Frags& f, uint32_t aHi, uint32_t aLo,
                                           uint32_t wHi, uint32_t wLo, int k16)
{
    ldmx4(f.ah, aHi + k16*32);
    ldmx4(f.al, aLo + k16*32);
    ldmx4(f.bh,     wHi + k16*32);
    ldmx4(f.bh + 4, wHi + 16*1040 + k16*32);
    ldmx4(f.bl,     wLo + k16*32);
    ldmx4(f.bl + 4, wLo + 16*1040 + k16*32);
}
__device__ __forceinline__ void do_hmma(float* acc, const Frags& f){
    #pragma unroll
    for (int nb = 0; nb < 4; ++nb)
        mma_bf16(acc + nb*4, f.ah, f.bh[nb*2], f.bh[nb*2+1]);
    #pragma unroll
    for (int nb = 0; nb < 4; ++nb)
        mma_bf16(acc + nb*4, f.ah, f.bl[nb*2], f.bl[nb*2+1]);
    #pragma unroll
    for (int nb = 0; nb < 4; ++nb)
        mma_bf16(acc + nb*4, f.al, f.bh[nb*2], f.bh[nb*2+1]);
}

__device__ __forceinline__ void compute_chunk(uint32_t aHi, uint32_t aLo,
                                              uint32_t wHi, uint32_t wLo, float* acc)
{
    Frags f[2];
    load_frags(f[0], aHi, aLo, wHi, wLo, 0);
    #pragma unroll
    for (int k16 = 0; k16 < 8; ++k16){
        if (k16 < 7) load_frags(f[(k16+1)&1], aHi, aLo, wHi, wLo, k16+1);
        do_hmma(acc, f[k16&1]);
    }
}

__device__ __forceinline__ void gemm_step(const __nv_bfloat16* __restrict__ bh,
                                          const __nv_bfloat16* __restrict__ bl,
                                          uint32_t sb, uint32_t aoff, uint32_t wboff,
                                          float* acc, int tid)
{
    stage_A(bh, bl, 0, sb + A_BUF(0,0), sb + A_BUF(0,1), tid);
    CP_COMMIT;
    #pragma unroll 1
    for (int kc = 0; kc < 4; ++kc){
        if (kc < 3){
            int nb_ = (kc+1) & 1;
            stage_A(bh, bl, kc+1, sb + A_BUF(nb_,0), sb + A_BUF(nb_,1), tid);
            CP_COMMIT;
            CP_WAIT1;
        } else {
            CP_WAIT0;
        }
        __syncthreads();
        int cb = kc & 1;
        compute_chunk(sb + A_BUF(cb,0) + aoff, sb + A_BUF(cb,1) + aoff,
                      sb + W_HI + wboff + kc*256, sb + W_LO + wboff + kc*256, acc);
        __syncthreads();
    }
}

// ---------------- persistent recurrent layer ----------------
// Grid 128 = 4 bt x 32 nt. 256 thr = 8 warps: mg = wid&3 (m16), nh = wid>>2 (n32).
template<int LAYER>
__global__ void __launch_bounds__(256, 1) lstm_rec_kernel(
    const float* __restrict__ x_time, const float* __restrict__ w_ih0,
    const float* __restrict__ bias)
{
    extern __shared__ __align__(128) char smem[];
    const int tid  = threadIdx.x;
    const int lane = tid & 31;
    const int wid  = tid >> 5;
    const int mg   = wid & 3;
    const int nh   = wid >> 2;
    const int bt   = blockIdx.x & 3;
    const int nt   = blockIdx.x >> 2;
    const int b0   = bt * 64;
    const int u0   = nt * 16;
    const uint32_t sb = su32(smem);

    const __nv_bfloat16* whh_hi = LAYER ? g_whh1_hi : g_whh0_hi;
    const __nv_bfloat16* whh_lo = LAYER ? g_whh1_lo : g_whh0_lo;
    __nv_bfloat16* out_hi = LAYER ? g_h1_hi : g_h0_hi;
    __nv_bfloat16* out_lo = LAYER ? g_h1_lo : g_h0_lo;

    stage_W(whh_hi, smem, W_HI, u0, tid);
    stage_W(whh_lo, smem, W_LO, u0, tid);
    float* s_wih0 = (float*)(smem + WIH0OFF);
    if (LAYER == 0 && tid < 64){
        int j = ((tid >> 3) & 3) * Hn + u0 + (tid & 7) + (tid >> 5) * 8;
        #pragma unroll
        for (int q = 0; q < 5; ++q) s_wih0[tid*5 + q] = w_ih0[(size_t)j*5 + q];
    }
    __syncthreads();

    // per-lane ldmatrix offsets
    const uint32_t aoff  = (uint32_t)((mg*16 + (lane & 15)) * 272 + (lane >> 4) * 16);
    const uint32_t wboff = (uint32_t)((nh*32 + (lane & 7) + ((lane >> 4) & 1) * 8) * 1040
                                      + ((lane >> 3) & 1) * 16);

    // cell ownership: rows {ra, rb}, units ubase + {0,1}, all 4 gates (nb = gate)
    const int q2    = 2 * (lane & 3);
    const int ra    = mg*16 + (lane >> 2);
    const int rb    = ra + 8;
    const int ubase = u0 + nh*8 + q2;

    float breg[4][2];
    if (LAYER == 0){
        #pragma unroll
        for (int g = 0; g < 4; ++g){
            breg[g][0] = bias[g*Hn + ubase];
            breg[g][1] = bias[g*Hn + ubase + 1];
        }
    }

    const unsigned fbase = LAYER ? (Tn - 1) : 0;

    float c[4] = {0.f, 0.f, 0.f, 0.f};
    float xpre[16];
    float xa[5], xb[5];

    // prefetch step-0 inputs
    if (LAYER == 1){
        const float* xp = g_xp + ((((size_t)0*4 + bt)*32 + nt)*256 + tid)*16;
        #pragma unroll
        for (int i = 0; i < 4; ++i){
            float4 v = *(const float4*)(xp + i*4);
            xpre[i*4+0]=v.x; xpre[i*4+1]=v.y; xpre[i*4+2]=v.z; xpre[i*4+3]=v.w;
        }
    } else {
        const float* pa = x_time + ((size_t)(b0+ra) * Tn + 0) * 5;
        const float* pb = x_time + ((size_t)(b0+rb) * Tn + 0) * 5;
        #pragma unroll
        for (int q = 0; q < 5; ++q){ xa[q] = pa[q]; xb[q] = pb[q]; }
    }

    for (int t = 0; t < Tn; ++t){
        float acc[16];
        #pragma unroll
        for (int i = 0; i < 16; ++i) acc[i] = 0.f;

        if (t > 0){
            gemm_step(out_hi + (size_t)(t-1)*BH + (size_t)b0*Hn,
                      out_lo + (size_t)(t-1)*BH + (size_t)b0*Hn,
                      sb, aoff, wboff, acc, tid);
        }

        if (LAYER == 1){
            #pragma unroll
            for (int i = 0; i < 16; ++i) acc[i] += xpre[i];
        } else {
            #pragma unroll
            for (int g = 0; g < 4; ++g){
                #pragma unroll
                for (int j = 0; j < 2; ++j){
                    int pr = nh*32 + g*8 + q2 + j;
                    const float* wr = s_wih0 + pr*5;
                    float da = breg[g][j], db = breg[g][j];
                    #pragma unroll
                    for (int q = 0; q < 5; ++q){ da += xa[q]*wr[q]; db += xb[q]*wr[q]; }
                    acc[g*4 + j]     += da;
                    acc[g*4 + 2 + j] += db;
                }
            }
        }

        // epilogue: 4 cells (2 rows x 2 units), all gates in-register
        #pragma unroll
        for (int rs = 0; rs < 2; ++rs){
            int row = rs ? rb : ra;
            float hv[2];
            #pragma unroll
            for (int j = 0; j < 2; ++j){
                float ai = acc[0*4 + rs*2 + j];
                float af = acc[1*4 + rs*2 + j];
                float ag = acc[2*4 + rs*2 + j];
                float ao = acc[3*4 + rs*2 + j];
                float ig = 1.f / (1.f + expf(-ai));
                float fg = 1.f / (1.f + expf(-af));
                float gg = tanhf(ag);
                float og = 1.f / (1.f + expf(-ao));
                int ci = rs*2 + j;
                c[ci] = fg * c[ci] + ig * gg;
                hv[j] = og * tanhf(c[ci]);
            }
            size_t ob = (size_t)t*BH + (size_t)(b0+row)*Hn + ubase;
            uint32_t ph = packbf2(hv[0], hv[1]);
            *(uint32_t*)(out_hi + ob) = ph;
            __nv_bfloat162 hb = *(__nv_bfloat162*)&ph;
            *(uint32_t*)(out_lo + ob) =
                packbf2(hv[0] - __bfloat162float(hb.x), hv[1] - __bfloat162float(hb.y));
        }

        if (t < Tn - 1){
            // prefetch next step's inputs (hidden behind the barrier)
            if (LAYER == 1){
                const float* xp = g_xp + ((((size_t)(t+1)*4 + bt)*32 + nt)*256 + tid)*16;
                #pragma unroll
                for (int i = 0; i < 4; ++i){
                    float4 v = *(const float4*)(xp + i*4);
                    xpre[i*4+0]=v.x; xpre[i*4+1]=v.y; xpre[i*4+2]=v.z; xpre[i*4+3]=v.w;
                }
            } else {
                const float* pa = x_time + ((size_t)(b0+ra) * Tn + (t+1)) * 5;
                const float* pb = x_time + ((size_t)(b0+rb) * Tn + (t+1)) * 5;
                #pragma unroll
                for (int q = 0; q < 5; ++q){ xa[q] = pa[q]; xb[q] = pb[q]; }
            }
            group_barrier(bt, nt, fbase + (unsigned)t + 1u, tid);
        }
    }
}

// ---------------- parallel precompute: xp = h0 @ W_ih1^T + b1 (fragment layout) ----------------
__global__ void __launch_bounds__(256, 1) xp_kernel(const float* __restrict__ bias)
{
    extern __shared__ __align__(128) char smem[];
    const int tid  = threadIdx.x;
    const int lane = tid & 31;
    const int wid  = tid >> 5;
    const int mg   = wid & 3;
    const int nh   = wid >> 2;
    const int nt   = blockIdx.x & 31;
    const int grp  = blockIdx.x >> 5;
    const int u0   = nt * 16;
    const uint32_t sb = su32(smem);

    stage_W(g_wih1_hi, smem, W_HI, u0, tid);
    stage_W(g_wih1_lo, smem, W_LO, u0, tid);
    __syncthreads();

    const uint32_t aoff  = (uint32_t)((mg*16 + (lane & 15)) * 272 + (lane >> 4) * 16);
    const uint32_t wboff = (uint32_t)((nh*32 + (lane & 7) + ((lane >> 4) & 1) * 8) * 1040
                                      + ((lane >> 3) & 1) * 16);
    const int q2    = 2 * (lane & 3);
    const int ubase = u0 + nh*8 + q2;

    float bx[4][2];
    #pragma unroll
    for (int nb = 0; nb < 4; ++nb){
        bx[nb][0] = bias[nb*Hn + ubase];
        bx[nb][1] = bias[nb*Hn + ubase + 1];
    }

    for (int mi = 0; mi < 64; ++mi){
        int mt = grp * 64 + mi;
        int t  = mt >> 2;
        int bt = mt & 3;
        int b0 = bt * 64;

        float acc[16];
        #pragma unroll
        for (int i = 0; i < 16; ++i) acc[i] = 0.f;

        gemm_step(g_h0_hi + (size_t)t*BH + (size_t)b0*Hn,
                  g_h0_lo + (size_t)t*BH + (size_t)b0*Hn,
                  sb, aoff, wboff, acc, tid);

        float* xp = g_xp + ((((size_t)t*4 + bt)*32 + nt)*256 + tid)*16;
        #pragma unroll
        for (int nb = 0; nb < 4; ++nb){
            float4 v;
            v.x = acc[nb*4+0] + bx[nb][0];
            v.y = acc[nb*4+1] + bx[nb][1];
            v.z = acc[nb*4+2] + bx[nb][0];
            v.w = acc[nb*4+3] + bx[nb][1];
            *(float4*)(xp + nb*4) = v;
        }
    }
}

// ---------------- heads ----------------
__global__ void __launch_bounds__(256) heads_kernel(
    const float* __restrict__ x_stat,
    const float* __restrict__ fc1_w, const float* __restrict__ fc1_b,
    const float* __restrict__ fc2_w, const float* __restrict__ fc2_b,
    const float* __restrict__ fc3_w, const float* __restrict__ fc3_b,
    float* __restrict__ out)
{
    const int b = blockIdx.x;
    const int tid = threadIdx.x;

    float p0 = 0.f, p1 = 0.f;
    for (int idx = tid; idx < Tn*Hn; idx += 256){
        int t = idx >> 9;
        int u = idx & 511;
        size_t off = (size_t)t * BH + (size_t)b * Hn + u;
        float hv = __bfloat162float(g_h1_hi[off]) + __bfloat162float(g_h1_lo[off]);
        p0 += hv * fc1_w[idx];
        p1 += hv * fc1_w[Tn*Hn + idx];
    }
    __shared__ float s0[256], s1[256];
    s0[tid] = p0; s1[tid] = p1;
    __syncthreads();
    for (int s = 128; s > 0; s >>= 1){
        if (tid < s){ s0[tid] += s0[tid+s]; s1[tid] += s1[tid+s]; }
        __syncthreads();
    }
    if (tid == 0){
        float tp0 = s0[0] + fc1_b[0];
        float tp1 = s1[0] + fc1_b[1];
        float xs0 = x_stat[b*3+0], xs1 = x_stat[b*3+1], xs2 = x_stat[b*3+2];
        float sp0 = fc2_b[0] + xs0*fc2_w[0] + xs1*fc2_w[1] + xs2*fc2_w[2];
        float sp1 = fc2_b[1] + xs0*fc2_w[3] + xs1*fc2_w[4] + xs2*fc2_w[5];
        out[b*2+0] = fc3_b[0] + fc3_w[0]*sp0 + fc3_w[1]*sp1 + fc3_w[2]*tp0 + fc3_w[3]*tp1;
        out[b*2+1] = fc3_b[1] + fc3_w[4]*sp0 + fc3_w[5]*sp1 + fc3_w[6]*tp0 + fc3_w[7]*tp1;
    }
}

extern "C" void kernel_launch(void* const* d_in, const int* in_sizes, int n_in,
                              void* d_out, int out_size)
{
    const float* x_time = (const float*)d_in[0];
    const float* x_stat = (const float*)d_in[1];
    const float* w_ih0  = (const float*)d_in[2];
    const float* w_hh0  = (const float*)d_in[3];
    const float* b0     = (const float*)d_in[4];
    const float* w_ih1  = (const float*)d_in[5];
    const float* w_hh1  = (const float*)d_in[6];
    const float* b1     = (const float*)d_in[7];
    const float* fc1_w  = (const float*)d_in[8];
    const float* fc1_b  = (const float*)d_in[9];
    const float* fc2_w  = (const float*)d_in[10];
    const float* fc2_b  = (const float*)d_in[11];
    const float* fc3_w  = (const float*)d_in[12];
    const float* fc3_b  = (const float*)d_in[13];
    float* out = (float*)d_out;

    cudaFuncSetAttribute(lstm_rec_kernel<0>, cudaFuncAttributeMaxDynamicSharedMemorySize, SMEMSZ);
    cudaFuncSetAttribute(lstm_rec_kernel<1>, cudaFuncAttributeMaxDynamicSharedMemorySize, SMEMSZ);
    cudaFuncSetAttribute(xp_kernel,          cudaFuncAttributeMaxDynamicSharedMemorySize, SMEMSZ);

    split_all_kernel<<<(G4*Hn + 255)/256, 256>>>(w_hh0, w_hh1, w_ih1);
    lstm_rec_kernel<0><<<NCTA, 256, SMEMSZ>>>(x_time, w_ih0, b0);
    xp_kernel<<<512, 256, SMEMSZ>>>(b1);
    lstm_rec_kernel<1><<<NCTA, 256, SMEMSZ>>>(x_time, w_ih0, b1);
    heads_kernel<<<Bn, 256>>>(x_stat, fc1_w, fc1_b, fc2_w, fc2_b, fc3_w, fc3_b, out);
}

// round 6
// speedup vs baseline: 3.4208x; 1.2146x over previous
#include <cuda_runtime.h>
#include <cuda_fp16.h>
#include <cstdint>
#include <math.h>

#define Tn   256
#define Bn   256
#define Hn   512
#define BH   (Bn*Hn)
#define G4   2048
#define NCTA 128

// ---------------- device globals (scratch) ----------------
__device__ __align__(128) __half g_whh0_hi[G4*Hn];
__device__ __align__(128) __half g_whh0_lo[G4*Hn];
__device__ __align__(128) __half g_whh1_hi[G4*Hn];
__device__ __align__(128) __half g_whh1_lo[G4*Hn];
__device__ __align__(128) __half g_wih1_hi[G4*Hn];
__device__ __align__(128) __half g_wih1_lo[G4*Hn];
__device__ __align__(128) __half g_h0[(size_t)Tn*BH];
__device__ __align__(128) __half g_h1[(size_t)Tn*BH];
__device__ __align__(128) float g_xp[(size_t)Tn*Bn*G4];   // [t][bt][nt][tid(256)][16]
__device__ __align__(128) unsigned g_flag[4*32*32];       // (bt*32+nt)*32, 128B padded

// ---------------- SMEM layout (bytes) ----------------
// W rows: 64 packed rows pr = nh*32 + g*8 + u, stride 1040 B (512 fp16 + 8 pad)
// A rows: 64 b-rows x 256 k per chunk, stride 528 B (256 fp16 + 8 pad)
#define W_HI    0
#define W_LO    66560
#define A_OFF(db) (133120 + (db)*33792)
#define WIH0OFF 200704
#define SMEMSZ  202752

// ---------------- PTX helpers ----------------
__device__ __forceinline__ uint32_t su32(const void* p){
    uint32_t a;
    asm("{ .reg .u64 t; cvta.to.shared.u64 t, %1; cvt.u32.u64 %0, t; }" : "=r"(a) : "l"(p));
    return a;
}
__device__ __forceinline__ void ldmx4(uint32_t* r, uint32_t a){
    asm volatile("ldmatrix.sync.aligned.m8n8.x4.shared.b16 {%0,%1,%2,%3}, [%4];"
        : "=r"(r[0]), "=r"(r[1]), "=r"(r[2]), "=r"(r[3]) : "r"(a));
}
__device__ __forceinline__ void mma_f16(float* c, const uint32_t* a, uint32_t b0, uint32_t b1){
    asm("mma.sync.aligned.m16n8k16.row.col.f32.f16.f16.f32 "
        "{%0,%1,%2,%3}, {%4,%5,%6,%7}, {%8,%9}, {%0,%1,%2,%3};"
        : "+f"(c[0]), "+f"(c[1]), "+f"(c[2]), "+f"(c[3])
        : "r"(a[0]), "r"(a[1]), "r"(a[2]), "r"(a[3]), "r"(b0), "r"(b1));
}
__device__ __forceinline__ void cpa16(uint32_t dst, const void* src){
    asm volatile("cp.async.cg.shared.global [%0], [%1], 16;" :: "r"(dst), "l"(src));
}
#define CP_COMMIT asm volatile("cp.async.commit_group;" ::: "memory")
#define CP_WAIT0  asm volatile("cp.async.wait_group 0;" ::: "memory")
#define CP_WAIT1  asm volatile("cp.async.wait_group 1;" ::: "memory")

__device__ __forceinline__ uint32_t packh2(float a, float b){
    __half2 v = __floats2half2_rn(a, b);
    return *(uint32_t*)&v;
}

// ---------------- half-group flag wait (16 producer CTAs) ----------------
__device__ __forceinline__ void wait_half(int bt, int base, unsigned tgt, int tid){
    if (tid < 16){
        while (*((volatile unsigned*)&g_flag[(bt*32 + base + tid)*32]) < tgt) {}
        __threadfence();
    }
    __syncthreads();
}

// ---------------- prologue: fp32 -> fp16 hi/lo weight split + flag reset ----------------
__global__ void split_all_kernel(const float* __restrict__ whh0,
                                 const float* __restrict__ whh1,
                                 const float* __restrict__ wih1)
{
    int i = blockIdx.x * blockDim.x + threadIdx.x;
    if (blockIdx.x == 0 && threadIdx.x < 128) g_flag[threadIdx.x * 32] = 0u;
    if (i >= G4*Hn) return;
    {
        float x = whh0[i]; __half h = __float2half_rn(x);
        g_whh0_hi[i] = h; g_whh0_lo[i] = __float2half_rn(x - __half2float(h));
    }
    {
        float x = whh1[i]; __half h = __float2half_rn(x);
        g_whh1_hi[i] = h; g_whh1_lo[i] = __float2half_rn(x - __half2float(h));
    }
    {
        float x = wih1[i]; __half h = __float2half_rn(x);
        g_wih1_hi[i] = h; g_wih1_lo[i] = __float2half_rn(x - __half2float(h));
    }
}

// ---------------- staging (256 threads) ----------------
// one K=256 chunk of A (h, single fp16): 64 rows x 512 B
__device__ __forceinline__ void stage_A(const __half* __restrict__ src,
                                        int kc, uint32_t sA, int tid)
{
    #pragma unroll
    for (int it = 0; it < 8; ++it){
        int idx = tid + it*256;        // 0..2047
        int row = idx >> 5;            // 0..63
        int kk  = (idx & 31) << 3;     // fp16 elems
        cpa16(sA + (uint32_t)(row*528 + kk*2),
              src + (size_t)row * Hn + kc*256 + kk);
    }
}

// persistent W tile: packed row pr -> j: g=(pr>>3)&3, u=(pr&7)+(pr>>5)*8
__device__ __forceinline__ void stage_W(const __half* __restrict__ src,
                                        char* smem, int woff, int u0, int tid)
{
    for (int it = 0; it < 16; ++it){
        int idx = tid + it*256;
        int row = idx >> 6;
        int kk  = (idx & 63) << 3;
        int j = ((row >> 3) & 3) * Hn + u0 + (row & 7) + (row >> 5) * 8;
        uint4 v = *(const uint4*)(src + (size_t)j * Hn + kk);
        *(uint4*)(smem + woff + row*1040 + kk*2) = v;
    }
}

// ---------------- fragment pipeline (warp tile 16x32, 2-pass W-split) ----------------
struct Frags { uint32_t a[4], wh[8], wl[8]; };

__device__ __forceinline__ void load_frags(Frags& f, uint32_t aB,
                                           uint32_t wHi, uint32_t wLo, int k16)
{
    ldmx4(f.a, aB + k16*32);
    ldmx4(f.wh,     wHi + k16*32);
    ldmx4(f.wh + 4, wHi + 16*1040 + k16*32);
    ldmx4(f.wl,     wLo + k16*32);
    ldmx4(f.wl + 4, wLo + 16*1040 + k16*32);
}
__device__ __forceinline__ void do_hmma(float* acc, const Frags& f){
    #pragma unroll
    for (int nb = 0; nb < 4; ++nb)
        mma_f16(acc + nb*4, f.a, f.wh[nb*2], f.wh[nb*2+1]);
    #pragma unroll
    for (int nb = 0; nb < 4; ++nb)
        mma_f16(acc + nb*4, f.a, f.wl[nb*2], f.wl[nb*2+1]);
}

// one K=256 chunk: 16 k16 iterations, fragment double-buffered
__device__ __forceinline__ void compute_chunk(uint32_t aB, uint32_t wHi, uint32_t wLo,
                                              float* acc)
{
    Frags f[2];
    load_frags(f[0], aB, wHi, wLo, 0);
    #pragma unroll
    for (int k16 = 0; k16 < 16; ++k16){
        if (k16 < 15) load_frags(f[(k16+1)&1], aB, wHi, wLo, k16+1);
        do_hmma(acc, f[k16&1]);
    }
}

// plain full-K GEMM (xp kernel; inputs already available)
__device__ __forceinline__ void gemm_step(const __half* __restrict__ src,
                                          uint32_t sb, uint32_t aoff, uint32_t wboff,
                                          float* acc, int tid)
{
    stage_A(src, 0, sb + A_OFF(0), tid);
    CP_COMMIT;
    stage_A(src, 1, sb + A_OFF(1), tid);
    CP_COMMIT; CP_WAIT1; __syncthreads();
    compute_chunk(sb + A_OFF(0) + aoff, sb + W_HI + wboff, sb + W_LO + wboff, acc);
    CP_WAIT0; __syncthreads();
    compute_chunk(sb + A_OFF(1) + aoff, sb + W_HI + wboff + 512, sb + W_LO + wboff + 512, acc);
    __syncthreads();
}

// ---------------- persistent recurrent layer ----------------
// Grid 128 = 4 bt x 32 nt. 256 thr = 8 warps: mg = wid&3 (m16), nh = wid>>2 (n32).
template<int LAYER>
__global__ void __launch_bounds__(256, 1) lstm_rec_kernel(
    const float* __restrict__ x_time, const float* __restrict__ w_ih0,
    const float* __restrict__ bias)
{
    extern __shared__ __align__(128) char smem[];
    const int tid  = threadIdx.x;
    const int lane = tid & 31;
    const int wid  = tid >> 5;
    const int mg   = wid & 3;
    const int nh   = wid >> 2;
    const int bt   = blockIdx.x & 3;
    const int nt   = blockIdx.x >> 2;
    const int b0   = bt * 64;
    const int u0   = nt * 16;
    const uint32_t sb = su32(smem);

    const __half* whh_hi = LAYER ? g_whh1_hi : g_whh0_hi;
    const __half* whh_lo = LAYER ? g_whh1_lo : g_whh0_lo;
    __half* out = LAYER ? g_h1 : g_h0;

    stage_W(whh_hi, smem, W_HI, u0, tid);
    stage_W(whh_lo, smem, W_LO, u0, tid);
    float* s_wih0 = (float*)(smem + WIH0OFF);
    if (LAYER == 0 && tid < 64){
        int j = ((tid >> 3) & 3) * Hn + u0 + (tid & 7) + (tid >> 5) * 8;
        #pragma unroll
        for (int q = 0; q < 5; ++q) s_wih0[tid*5 + q] = w_ih0[(size_t)j*5 + q];
    }
    __syncthreads();

    // per-lane ldmatrix offsets
    const uint32_t aoff  = (uint32_t)((mg*16 + (lane & 15)) * 528 + (lane >> 4) * 16);
    const uint32_t wboff = (uint32_t)((nh*32 + (lane & 7) + ((lane >> 4) & 1) * 8) * 1040
                                      + ((lane >> 3) & 1) * 16);

    // cell ownership: rows {ra, rb}, units ubase + {0,1}, all 4 gates
    const int q2    = 2 * (lane & 3);
    const int ra    = mg*16 + (lane >> 2);
    const int rb    = ra + 8;
    const int ubase = u0 + nh*8 + q2;

    float breg[4][2];
    if (LAYER == 0){
        #pragma unroll
        for (int g = 0; g < 4; ++g){
            breg[g][0] = bias[g*Hn + ubase];
            breg[g][1] = bias[g*Hn + ubase + 1];
        }
    }

    const unsigned fbase = LAYER ? (Tn - 1) : 0;

    float c[4] = {0.f, 0.f, 0.f, 0.f};
    float xpre[16];
    float xa[5], xb[5];

    if (LAYER == 1){
        const float* xp = g_xp + ((((size_t)0*4 + bt)*32 + nt)*256 + tid)*16;
        #pragma unroll
        for (int i = 0; i < 4; ++i){
            float4 v = *(const float4*)(xp + i*4);
            xpre[i*4+0]=v.x; xpre[i*4+1]=v.y; xpre[i*4+2]=v.z; xpre[i*4+3]=v.w;
        }
    } else {
        const float* pa = x_time + ((size_t)(b0+ra) * Tn + 0) * 5;
        const float* pb = x_time + ((size_t)(b0+rb) * Tn + 0) * 5;
        #pragma unroll
        for (int q = 0; q < 5; ++q){ xa[q] = pa[q]; xb[q] = pb[q]; }
    }

    for (int t = 0; t < Tn; ++t){
        float acc[16];
        #pragma unroll
        for (int i = 0; i < 16; ++i) acc[i] = 0.f;

        if (t > 0){
            const __half* src = out + (size_t)(t-1)*BH + (size_t)b0*Hn;
            unsigned tgt = fbase + (unsigned)t;
            // chunk 0 needs producers nt 0..15 (u-cols 0..255)
            wait_half(bt, 0, tgt, tid);
            stage_A(src, 0, sb + A_OFF(0), tid);
            CP_COMMIT;
            // chunk 1 needs producers nt 16..31
            wait_half(bt, 16, tgt, tid);
            stage_A(src, 1, sb + A_OFF(1), tid);
            CP_COMMIT; CP_WAIT1; __syncthreads();
            compute_chunk(sb + A_OFF(0) + aoff, sb + W_HI + wboff, sb + W_LO + wboff, acc);
            CP_WAIT0; __syncthreads();
            compute_chunk(sb + A_OFF(1) + aoff, sb + W_HI + wboff + 512,
                          sb + W_LO + wboff + 512, acc);
        }

        if (LAYER == 1){
            #pragma unroll
            for (int i = 0; i < 16; ++i) acc[i] += xpre[i];
        } else {
            #pragma unroll
            for (int g = 0; g < 4; ++g){
                #pragma unroll
                for (int j = 0; j < 2; ++j){
                    int pr = nh*32 + g*8 + q2 + j;
                    const float* wr = s_wih0 + pr*5;
                    float da = breg[g][j], db = breg[g][j];
                    #pragma unroll
                    for (int q = 0; q < 5; ++q){ da += xa[q]*wr[q]; db += xb[q]*wr[q]; }
                    acc[g*4 + j]     += da;
                    acc[g*4 + 2 + j] += db;
                }
            }
        }

        // epilogue: 4 cells (2 rows x 2 units), all gates in-register
        #pragma unroll
        for (int rs = 0; rs < 2; ++rs){
            int row = rs ? rb : ra;
            float hv[2];
            #pragma unroll
            for (int j = 0; j < 2; ++j){
                float ai = acc[0*4 + rs*2 + j];
                float af = acc[1*4 + rs*2 + j];
                float ag = acc[2*4 + rs*2 + j];
                float ao = acc[3*4 + rs*2 + j];
                float ig = 1.f / (1.f + expf(-ai));
                float fg = 1.f / (1.f + expf(-af));
                float gg = tanhf(ag);
                float og = 1.f / (1.f + expf(-ao));
                int ci = rs*2 + j;
                c[ci] = fg * c[ci] + ig * gg;
                hv[j] = og * tanhf(c[ci]);
            }
            size_t ob = (size_t)t*BH + (size_t)(b0+row)*Hn + ubase;
            *(uint32_t*)(out + ob) = packh2(hv[0], hv[1]);
        }

        if (t < Tn - 1){
            // prefetch next-step inputs (hidden behind flag publication)
            if (LAYER == 1){
                const float* xp = g_xp + ((((size_t)(t+1)*4 + bt)*32 + nt)*256 + tid)*16;
                #pragma unroll
                for (int i = 0; i < 4; ++i){
                    float4 v = *(const float4*)(xp + i*4);
                    xpre[i*4+0]=v.x; xpre[i*4+1]=v.y; xpre[i*4+2]=v.z; xpre[i*4+3]=v.w;
                }
            } else {
                const float* pa = x_time + ((size_t)(b0+ra) * Tn + (t+1)) * 5;
                const float* pb = x_time + ((size_t)(b0+rb) * Tn + (t+1)) * 5;
                #pragma unroll
                for (int q = 0; q < 5; ++q){ xa[q] = pa[q]; xb[q] = pb[q]; }
            }
            __syncthreads();
            if (tid == 0){
                __threadfence();
                *((volatile unsigned*)&g_flag[(bt*32 + nt)*32]) = fbase + (unsigned)t + 1u;
            }
        }
    }
}

// ---------------- parallel precompute: xp = h0 @ W_ih1^T + b1 (fragment layout) ----------------
__global__ void __launch_bounds__(256, 1) xp_kernel(const float* __restrict__ bias)
{
    extern __shared__ __align__(128) char smem[];
    const int tid  = threadIdx.x;
    const int lane = tid & 31;
    const int wid  = tid >> 5;
    const int mg   = wid & 3;
    const int nh   = wid >> 2;
    const int nt   = blockIdx.x & 31;
    const int grp  = blockIdx.x >> 5;
    const int u0   = nt * 16;
    const uint32_t sb = su32(smem);

    stage_W(g_wih1_hi, smem, W_HI, u0, tid);
    stage_W(g_wih1_lo, smem, W_LO, u0, tid);
    __syncthreads();

    const uint32_t aoff  = (uint32_t)((mg*16 + (lane & 15)) * 528 + (lane >> 4) * 16);
    const uint32_t wboff = (uint32_t)((nh*32 + (lane & 7) + ((lane >> 4) & 1) * 8) * 1040
                                      + ((lane >> 3) & 1) * 16);
    const int q2    = 2 * (lane & 3);
    const int ubase = u0 + nh*8 + q2;

    float bx[4][2];
    #pragma unroll
    for (int nb = 0; nb < 4; ++nb){
        bx[nb][0] = bias[nb*Hn + ubase];
        bx[nb][1] = bias[nb*Hn + ubase + 1];
    }

    for (int mi = 0; mi < 64; ++mi){
        int mt = grp * 64 + mi;
        int t  = mt >> 2;
        int bt = mt & 3;
        int b0 = bt * 64;

        float acc[16];
        #pragma unroll
        for (int i = 0; i < 16; ++i) acc[i] = 0.f;

        gemm_step(g_h0 + (size_t)t*BH + (size_t)b0*Hn, sb, aoff, wboff, acc, tid);

        float* xp = g_xp + ((((size_t)t*4 + bt)*32 + nt)*256 + tid)*16;
        #pragma unroll
        for (int nb = 0; nb < 4; ++nb){
            float4 v;
            v.x = acc[nb*4+0] + bx[nb][0];
            v.y = acc[nb*4+1] + bx[nb][1];
            v.z = acc[nb*4+2] + bx[nb][0];
            v.w = acc[nb*4+3] + bx[nb][1];
            *(float4*)(xp + nb*4) = v;
        }
    }
}

// ---------------- heads ----------------
__global__ void __launch_bounds__(256) heads_kernel(
    const float* __restrict__ x_stat,
    const float* __restrict__ fc1_w, const float* __restrict__ fc1_b,
    const float* __restrict__ fc2_w, const float* __restrict__ fc2_b,
    const float* __restrict__ fc3_w, const float* __restrict__ fc3_b,
    float* __restrict__ out)
{
    const int b = blockIdx.x;
    const int tid = threadIdx.x;

    float p0 = 0.f, p1 = 0.f;
    for (int idx = tid; idx < Tn*Hn; idx += 256){
        int t = idx >> 9;
        int u = idx & 511;
        float hv = __half2float(g_h1[(size_t)t * BH + (size_t)b * Hn + u]);
        p0 += hv * fc1_w[idx];
        p1 += hv * fc1_w[Tn*Hn + idx];
    }
    __shared__ float s0[256], s1[256];
    s0[tid] = p0; s1[tid] = p1;
    __syncthreads();
    for (int s = 128; s > 0; s >>= 1){
        if (tid < s){ s0[tid] += s0[tid+s]; s1[tid] += s1[tid+s]; }
        __syncthreads();
    }
    if (tid == 0){
        float tp0 = s0[0] + fc1_b[0];
        float tp1 = s1[0] + fc1_b[1];
        float xs0 = x_stat[b*3+0], xs1 = x_stat[b*3+1], xs2 = x_stat[b*3+2];
        float sp0 = fc2_b[0] + xs0*fc2_w[0] + xs1*fc2_w[1] + xs2*fc2_w[2];
        float sp1 = fc2_b[1] + xs0*fc2_w[3] + xs1*fc2_w[4] + xs2*fc2_w[5];
        out[b*2+0] = fc3_b[0] + fc3_w[0]*sp0 + fc3_w[1]*sp1 + fc3_w[2]*tp0 + fc3_w[3]*tp1;
        out[b*2+1] = fc3_b[1] + fc3_w[4]*sp0 + fc3_w[5]*sp1 + fc3_w[6]*tp0 + fc3_w[7]*tp1;
    }
}

extern "C" void kernel_launch(void* const* d_in, const int* in_sizes, int n_in,
                              void* d_out, int out_size)
{
    const float* x_time = (const float*)d_in[0];
    const float* x_stat = (const float*)d_in[1];
    const float* w_ih0  = (const float*)d_in[2];
    const float* w_hh0  = (const float*)d_in[3];
    const float* b0     = (const float*)d_in[4];
    const float* w_ih1  = (const float*)d_in[5];
    const float* w_hh1  = (const float*)d_in[6];
    const float* b1     = (const float*)d_in[7];
    const float* fc1_w  = (const float*)d_in[8];
    const float* fc1_b  = (const float*)d_in[9];
    const float* fc2_w  = (const float*)d_in[10];
    const float* fc2_b  = (const float*)d_in[11];
    const float* fc3_w  = (const float*)d_in[12];
    const float* fc3_b  = (const float*)d_in[13];
    float* out = (float*)d_out;

    cudaFuncSetAttribute(lstm_rec_kernel<0>, cudaFuncAttributeMaxDynamicSharedMemorySize, SMEMSZ);
    cudaFuncSetAttribute(lstm_rec_kernel<1>, cudaFuncAttributeMaxDynamicSharedMemorySize, SMEMSZ);
    cudaFuncSetAttribute(xp_kernel,          cudaFuncAttributeMaxDynamicSharedMemorySize, SMEMSZ);

    split_all_kernel<<<(G4*Hn + 255)/256, 256>>>(w_hh0, w_hh1, w_ih1);
    lstm_rec_kernel<0><<<NCTA, 256, SMEMSZ>>>(x_time, w_ih0, b0);
    xp_kernel<<<512, 256, SMEMSZ>>>(b1);
    lstm_rec_kernel<1><<<NCTA, 256, SMEMSZ>>>(x_time, w_ih0, b1);
    heads_kernel<<<Bn, 256>>>(x_stat, fc1_w, fc1_b, fc2_w, fc2_b, fc3_w, fc3_b, out);
}

// round 7
// speedup vs baseline: 3.7074x; 1.0838x over previous
#include <cuda_runtime.h>
#include <cuda_fp16.h>
#include <cstdint>
#include <math.h>

#define Tn   256
#define Bn   256
#define Hn   512
#define BH   (Bn*Hn)
#define G4   2048
#define NCTA 128

// ---------------- device globals (scratch) ----------------
__device__ __align__(128) __half g_whh0_hi[G4*Hn];
__device__ __align__(128) __half g_whh0_lo[G4*Hn];
__device__ __align__(128) __half g_whh1_hi[G4*Hn];
__device__ __align__(128) __half g_whh1_lo[G4*Hn];
__device__ __align__(128) __half g_wih1_hi[G4*Hn];
__device__ __align__(128) __half g_wih1_lo[G4*Hn];
__device__ __align__(128) __half g_h0[(size_t)Tn*BH];
__device__ __align__(128) __half g_h1[(size_t)Tn*BH];
__device__ __align__(128) float g_xp[(size_t)Tn*Bn*G4];   // [t][bt][nt][ktid(128)][32]
__device__ __align__(128) unsigned g_flag[4*32*32];       // (bt*32+nt)*32, 128B padded

// ---------------- SMEM layout (bytes) ----------------
// W rows: 64 packed rows pr = nh*32 + g*8 + u, stride 1040 B (512 fp16 + 8 pad)
// A rows: 64 b-rows x 256 k per chunk, stride 528 B (256 fp16 + 8 pad)
// gbuf (kg reduction, 64x68 f32 = 17408 B) aliases A chunk 0 (dead at reduction time)
#define W_HI    0
#define W_LO    66560
#define A_OFF(db) (133120 + (db)*33792)
#define GBUF    133120
#define WIH0OFF 200704
#define SMEMSZ  202752

// ---------------- PTX helpers ----------------
__device__ __forceinline__ uint32_t su32(const void* p){
    uint32_t a;
    asm("{ .reg .u64 t; cvta.to.shared.u64 t, %1; cvt.u32.u64 %0, t; }" : "=r"(a) : "l"(p));
    return a;
}
__device__ __forceinline__ void ldmx4(uint32_t* r, uint32_t a){
    asm volatile("ldmatrix.sync.aligned.m8n8.x4.shared.b16 {%0,%1,%2,%3}, [%4];"
        : "=r"(r[0]), "=r"(r[1]), "=r"(r[2]), "=r"(r[3]) : "r"(a));
}
__device__ __forceinline__ void mma_f16(float* c, const uint32_t* a, uint32_t b0, uint32_t b1){
    asm("mma.sync.aligned.m16n8k16.row.col.f32.f16.f16.f32 "
        "{%0,%1,%2,%3}, {%4,%5,%6,%7}, {%8,%9}, {%0,%1,%2,%3};"
        : "+f"(c[0]), "+f"(c[1]), "+f"(c[2]), "+f"(c[3])
        : "r"(a[0]), "r"(a[1]), "r"(a[2]), "r"(a[3]), "r"(b0), "r"(b1));
}
__device__ __forceinline__ void cpa16(uint32_t dst, const void* src){
    asm volatile("cp.async.cg.shared.global [%0], [%1], 16;" :: "r"(dst), "l"(src));
}
#define CP_COMMIT asm volatile("cp.async.commit_group;" ::: "memory")
#define CP_WAIT0  asm volatile("cp.async.wait_group 0;" ::: "memory")
#define CP_WAIT1  asm volatile("cp.async.wait_group 1;" ::: "memory")

__device__ __forceinline__ uint32_t packh2(float a, float b){
    __half2 v = __floats2half2_rn(a, b);
    return *(uint32_t*)&v;
}
__device__ __forceinline__ float fsig(float x){
    return __fdividef(1.f, 1.f + __expf(-x));
}
__device__ __forceinline__ float ftanh(float x){
    return 1.f - __fdividef(2.f, __expf(2.f*x) + 1.f);
}

// ---------------- half-group flag wait (16 producer CTAs) ----------------
__device__ __forceinline__ void wait_half(int bt, int base, unsigned tgt, int tid){
    if (tid < 16){
        while (*((volatile unsigned*)&g_flag[(bt*32 + base + tid)*32]) < tgt) {}
        __threadfence();
    }
    __syncthreads();
}

// ---------------- prologue: fp32 -> fp16 hi/lo weight split + flag reset ----------------
__global__ void split_all_kernel(const float* __restrict__ whh0,
                                 const float* __restrict__ whh1,
                                 const float* __restrict__ wih1)
{
    int i = blockIdx.x * blockDim.x + threadIdx.x;
    if (blockIdx.x == 0 && threadIdx.x < 128) g_flag[threadIdx.x * 32] = 0u;
    if (i >= G4*Hn) return;
    {
        float x = whh0[i]; __half h = __float2half_rn(x);
        g_whh0_hi[i] = h; g_whh0_lo[i] = __float2half_rn(x - __half2float(h));
    }
    {
        float x = whh1[i]; __half h = __float2half_rn(x);
        g_whh1_hi[i] = h; g_whh1_lo[i] = __float2half_rn(x - __half2float(h));
    }
    {
        float x = wih1[i]; __half h = __float2half_rn(x);
        g_wih1_hi[i] = h; g_wih1_lo[i] = __float2half_rn(x - __half2float(h));
    }
}

// ---------------- staging (256 threads) ----------------
__device__ __forceinline__ void stage_A(const __half* __restrict__ src,
                                        int kc, uint32_t sA, int tid)
{
    #pragma unroll
    for (int it = 0; it < 8; ++it){
        int idx = tid + it*256;        // 0..2047
        int row = idx >> 5;            // 0..63
        int kk  = (idx & 31) << 3;     // fp16 elems
        cpa16(sA + (uint32_t)(row*528 + kk*2),
              src + (size_t)row * Hn + kc*256 + kk);
    }
}

// packed row pr -> weight row j: g=(pr>>3)&3, u=(pr&7)+(pr>>5)*8
__device__ __forceinline__ void stage_W(const __half* __restrict__ src,
                                        char* smem, int woff, int u0, int tid)
{
    for (int it = 0; it < 16; ++it){
        int idx = tid + it*256;
        int row = idx >> 6;
        int kk  = (idx & 63) << 3;
        int j = ((row >> 3) & 3) * Hn + u0 + (row & 7) + (row >> 5) * 8;
        uint4 v = *(const uint4*)(src + (size_t)j * Hn + kk);
        *(uint4*)(smem + woff + row*1040 + kk*2) = v;
    }
}

// ---------------- fragment pipeline (warp tile 32x32, kg-split K, 2-pass W) ----------------
struct Frags { uint32_t a[8], wh[8], wl[8]; };

__device__ __forceinline__ void load_frags(Frags& f, uint32_t aB,
                                           uint32_t wHi, uint32_t wLo, int k16)
{
    ldmx4(f.a,     aB + k16*32);
    ldmx4(f.a + 4, aB + 16*528 + k16*32);
    ldmx4(f.wh,     wHi + k16*32);
    ldmx4(f.wh + 4, wHi + 16*1040 + k16*32);
    ldmx4(f.wl,     wLo + k16*32);
    ldmx4(f.wl + 4, wLo + 16*1040 + k16*32);
}
__device__ __forceinline__ void do_hmma(float* acc, const Frags& f){
    #pragma unroll
    for (int mh = 0; mh < 2; ++mh)
        #pragma unroll
        for (int g = 0; g < 4; ++g)
            mma_f16(acc + (mh*4+g)*4, f.a + mh*4, f.wh[g*2], f.wh[g*2+1]);
    #pragma unroll
    for (int mh = 0; mh < 2; ++mh)
        #pragma unroll
        for (int g = 0; g < 4; ++g)
            mma_f16(acc + (mh*4+g)*4, f.a + mh*4, f.wl[g*2], f.wl[g*2+1]);
}

// one K=256 chunk; this warp handles its kg-half (8 k16 iterations)
__device__ __forceinline__ void compute_chunk(uint32_t aB, uint32_t wHi, uint32_t wLo,
                                              float* acc)
{
    Frags f[2];
    load_frags(f[0], aB, wHi, wLo, 0);
    #pragma unroll
    for (int k16 = 0; k16 < 8; ++k16){
        if (k16 < 7) load_frags(f[(k16+1)&1], aB, wHi, wLo, k16+1);
        do_hmma(acc, f[k16&1]);
    }
}

// full K=512 GEMM body (both chunks); per-lane/kg offsets pre-baked into aoff/wboff args
__device__ __forceinline__ void gemm_body(uint32_t sb, uint32_t aoff, uint32_t wboff,
                                          float* acc)
{
    compute_chunk(sb + A_OFF(0) + aoff, sb + W_HI + wboff, sb + W_LO + wboff, acc);
    CP_WAIT0; __syncthreads();
    compute_chunk(sb + A_OFF(1) + aoff, sb + W_HI + wboff + 512,
                  sb + W_LO + wboff + 512, acc);
}

// kg1 -> gbuf partial store
__device__ __forceinline__ void kg1_store(float* gb, const float* acc, int mg, int nh, int lane)
{
    int row0 = mg*32 + (lane >> 2);
    int p0   = nh*32 + 2*(lane & 3);
    #pragma unroll
    for (int mh = 0; mh < 2; ++mh)
        #pragma unroll
        for (int g = 0; g < 4; ++g){
            const float* c = acc + (mh*4+g)*4;
            int r = row0 + mh*16;
            int p = p0 + g*8;
            *(float2*)(gb + r*68 + p)     = make_float2(c[0], c[1]);
            *(float2*)(gb + (r+8)*68 + p) = make_float2(c[2], c[3]);
        }
}
// kg0 merge
__device__ __forceinline__ void kg0_merge(float* gb, float* acc, int mg, int nh, int lane)
{
    int row0 = mg*32 + (lane >> 2);
    int p0   = nh*32 + 2*(lane & 3);
    #pragma unroll
    for (int mh = 0; mh < 2; ++mh)
        #pragma unroll
        for (int g = 0; g < 4; ++g){
            float* c = acc + (mh*4+g)*4;
            int r = row0 + mh*16;
            int p = p0 + g*8;
            float2 v0 = *(float2*)(gb + r*68 + p);
            float2 v1 = *(float2*)(gb + (r+8)*68 + p);
            c[0] += v0.x; c[1] += v0.y; c[2] += v1.x; c[3] += v1.y;
        }
}

// ---------------- persistent recurrent layer ----------------
// Grid 128 = 4 bt x 32 nt. 256 thr = 8 warps: kg=wid>>2, mg=wid&1, nh=(wid>>1)&1.
template<int LAYER>
__global__ void __launch_bounds__(256, 1) lstm_rec_kernel(
    const float* __restrict__ x_time, const float* __restrict__ w_ih0,
    const float* __restrict__ bias)
{
    extern __shared__ __align__(128) char smem[];
    const int tid  = threadIdx.x;
    const int lane = tid & 31;
    const int wid  = tid >> 5;
    const int kg   = wid >> 2;
    const int mg   = wid & 1;
    const int nh   = (wid >> 1) & 1;
    const int bt   = blockIdx.x & 3;
    const int nt   = blockIdx.x >> 2;
    const int b0   = bt * 64;
    const int u0   = nt * 16;
    const uint32_t sb = su32(smem);

    const __half* whh_hi = LAYER ? g_whh1_hi : g_whh0_hi;
    const __half* whh_lo = LAYER ? g_whh1_lo : g_whh0_lo;
    __half* out = LAYER ? g_h1 : g_h0;

    stage_W(whh_hi, smem, W_HI, u0, tid);
    stage_W(whh_lo, smem, W_LO, u0, tid);
    float* s_wih0 = (float*)(smem + WIH0OFF);
    if (LAYER == 0 && tid < 64){
        int j = ((tid >> 3) & 3) * Hn + u0 + (tid & 7) + (tid >> 5) * 8;
        #pragma unroll
        for (int q = 0; q < 5; ++q) s_wih0[tid*5 + q] = w_ih0[(size_t)j*5 + q];
    }
    __syncthreads();

    // per-lane ldmatrix offsets (include kg half offset: 8 k16 = 256 B)
    const uint32_t aoff  = (uint32_t)((mg*32 + (lane & 15)) * 528 + (lane >> 4) * 16
                                      + kg*256);
    const uint32_t wboff = (uint32_t)((nh*32 + (lane & 7) + ((lane >> 4) & 1) * 8) * 1040
                                      + ((lane >> 3) & 1) * 16 + kg*256);

    // kg0 cell ownership: rows b0 + mg*32 + mh*16 + (lane>>2) + rs*8;
    // units ubase + {0,1}; all 4 gates.
    const int q2    = 2 * (lane & 3);
    const int rb0   = mg*32 + (lane >> 2);
    const int ubase = u0 + nh*8 + q2;

    float breg[4][2];
    if (LAYER == 0){
        #pragma unroll
        for (int g = 0; g < 4; ++g){
            breg[g][0] = bias[g*Hn + ubase];
            breg[g][1] = bias[g*Hn + ubase + 1];
        }
    }

    const unsigned fbase = LAYER ? (Tn - 1) : 0;
    float* gb = (float*)(smem + GBUF);

    float c[8];
    #pragma unroll
    for (int i = 0; i < 8; ++i) c[i] = 0.f;

    float xpre[32];
    float xr[4][5];

    // prefetch step-0 inputs (kg0 only)
    if (kg == 0){
        if (LAYER == 1){
            const float* xp = g_xp + ((((size_t)0*4 + bt)*32 + nt)*128 + wid*32 + lane)*32;
            #pragma unroll
            for (int i = 0; i < 8; ++i){
                float4 v = *(const float4*)(xp + i*4);
                xpre[i*4+0]=v.x; xpre[i*4+1]=v.y; xpre[i*4+2]=v.z; xpre[i*4+3]=v.w;
            }
        } else {
            #pragma unroll
            for (int mh = 0; mh < 2; ++mh)
                #pragma unroll
                for (int rs = 0; rs < 2; ++rs){
                    const float* p = x_time + ((size_t)(b0 + rb0 + mh*16 + rs*8) * Tn) * 5;
                    #pragma unroll
                    for (int q = 0; q < 5; ++q) xr[mh*2+rs][q] = p[q];
                }
        }
    }

    for (int t = 0; t < Tn; ++t){
        float acc[32];
        #pragma unroll
        for (int i = 0; i < 32; ++i) acc[i] = 0.f;

        if (t > 0){
            const __half* src = out + (size_t)(t-1)*BH + (size_t)b0*Hn;
            unsigned tgt = fbase + (unsigned)t;
            wait_half(bt, 0, tgt, tid);             // producers of u-cols 0..255
            stage_A(src, 0, sb + A_OFF(0), tid);
            CP_COMMIT;
            wait_half(bt, 16, tgt, tid);            // producers of u-cols 256..511
            stage_A(src, 1, sb + A_OFF(1), tid);
            CP_COMMIT; CP_WAIT1; __syncthreads();
            gemm_body(sb, aoff, wboff, acc);
        }

        // kg reduction (gbuf aliases A chunk 0 — dead here)
        if (kg == 1) kg1_store(gb, acc, mg, nh, lane);
        __syncthreads();

        if (kg == 0){
            if (t > 0) kg0_merge(gb, acc, mg, nh, lane);

            if (LAYER == 1){
                #pragma unroll
                for (int i = 0; i < 32; ++i) acc[i] += xpre[i];
            } else {
                #pragma unroll
                for (int mh = 0; mh < 2; ++mh)
                    #pragma unroll
                    for (int rs = 0; rs < 2; ++rs)
                        #pragma unroll
                        for (int g = 0; g < 4; ++g)
                            #pragma unroll
                            for (int j = 0; j < 2; ++j){
                                const float* wr = s_wih0 + (nh*32 + g*8 + q2 + j)*5;
                                float d = breg[g][j];
                                #pragma unroll
                                for (int q = 0; q < 5; ++q) d += xr[mh*2+rs][q]*wr[q];
                                acc[(mh*4+g)*4 + rs*2 + j] += d;
                            }
            }

            // epilogue: 8 cells (4 rows x 2 units), all gates in-register
            #pragma unroll
            for (int mh = 0; mh < 2; ++mh)
                #pragma unroll
                for (int rs = 0; rs < 2; ++rs){
                    int row = rb0 + mh*16 + rs*8;
                    float hv[2];
                    #pragma unroll
                    for (int j = 0; j < 2; ++j){
                        float ai = acc[(mh*4+0)*4 + rs*2 + j];
                        float af = acc[(mh*4+1)*4 + rs*2 + j];
                        float ag = acc[(mh*4+2)*4 + rs*2 + j];
                        float ao = acc[(mh*4+3)*4 + rs*2 + j];
                        int ci = mh*4 + rs*2 + j;
                        c[ci] = fsig(af) * c[ci] + fsig(ai) * ftanh(ag);
                        hv[j] = fsig(ao) * ftanh(c[ci]);
                    }
                    size_t ob = (size_t)t*BH + (size_t)(b0+row)*Hn + ubase;
                    *(uint32_t*)(out + ob) = packh2(hv[0], hv[1]);
                }

            // prefetch next-step inputs
            if (t < Tn - 1){
                if (LAYER == 1){
                    const float* xp = g_xp + ((((size_t)(t+1)*4 + bt)*32 + nt)*128
                                              + wid*32 + lane)*32;
                    #pragma unroll
                    for (int i = 0; i < 8; ++i){
                        float4 v = *(const float4*)(xp + i*4);
                        xpre[i*4+0]=v.x; xpre[i*4+1]=v.y; xpre[i*4+2]=v.z; xpre[i*4+3]=v.w;
                    }
                } else {
                    #pragma unroll
                    for (int mh = 0; mh < 2; ++mh)
                        #pragma unroll
                        for (int rs = 0; rs < 2; ++rs){
                            const float* p = x_time
                                + ((size_t)(b0 + rb0 + mh*16 + rs*8) * Tn + (t+1)) * 5;
                            #pragma unroll
                            for (int q = 0; q < 5; ++q) xr[mh*2+rs][q] = p[q];
                        }
                }
            }
        }

        if (t < Tn - 1){
            __syncthreads();
            if (tid == 0){
                __threadfence();
                *((volatile unsigned*)&g_flag[(bt*32 + nt)*32]) = fbase + (unsigned)t + 1u;
            }
        }
    }
}

// ---------------- parallel precompute: xp = h0 @ W_ih1^T + b1 (fragment layout) ----------------
__global__ void __launch_bounds__(256, 1) xp_kernel(const float* __restrict__ bias)
{
    extern __shared__ __align__(128) char smem[];
    const int tid  = threadIdx.x;
    const int lane = tid & 31;
    const int wid  = tid >> 5;
    const int kg   = wid >> 2;
    const int mg   = wid & 1;
    const int nh   = (wid >> 1) & 1;
    const int nt   = blockIdx.x & 31;
    const int grp  = blockIdx.x >> 5;
    const int u0   = nt * 16;
    const uint32_t sb = su32(smem);

    stage_W(g_wih1_hi, smem, W_HI, u0, tid);
    stage_W(g_wih1_lo, smem, W_LO, u0, tid);
    __syncthreads();

    const uint32_t aoff  = (uint32_t)((mg*32 + (lane & 15)) * 528 + (lane >> 4) * 16
                                      + kg*256);
    const uint32_t wboff = (uint32_t)((nh*32 + (lane & 7) + ((lane >> 4) & 1) * 8) * 1040
                                      + ((lane >> 3) & 1) * 16 + kg*256);
    const int q2    = 2 * (lane & 3);
    const int ubase = u0 + nh*8 + q2;
    float* gb = (float*)(smem + GBUF);

    float bx[4][2];
    #pragma unroll
    for (int g = 0; g < 4; ++g){
        bx[g][0] = bias[g*Hn + ubase];
        bx[g][1] = bias[g*Hn + ubase + 1];
    }

    for (int mi = 0; mi < 64; ++mi){
        int mt = grp * 64 + mi;
        int t  = mt >> 2;
        int bt = mt & 3;
        int b0 = bt * 64;
        const __half* src = g_h0 + (size_t)t*BH + (size_t)b0*Hn;

        float acc[32];
        #pragma unroll
        for (int i = 0; i < 32; ++i) acc[i] = 0.f;

        stage_A(src, 0, sb + A_OFF(0), tid);
        CP_COMMIT;
        stage_A(src, 1, sb + A_OFF(1), tid);
        CP_COMMIT; CP_WAIT1; __syncthreads();
        gemm_body(sb, aoff, wboff, acc);

        if (kg == 1) kg1_store(gb, acc, mg, nh, lane);
        __syncthreads();
        if (kg == 0){
            kg0_merge(gb, acc, mg, nh, lane);
            float* xp = g_xp + ((((size_t)t*4 + bt)*32 + nt)*128 + wid*32 + lane)*32;
            #pragma unroll
            for (int mh = 0; mh < 2; ++mh)
                #pragma unroll
                for (int g = 0; g < 4; ++g){
                    float4 v;
                    v.x = acc[(mh*4+g)*4+0] + bx[g][0];
                    v.y = acc[(mh*4+g)*4+1] + bx[g][1];
                    v.z = acc[(mh*4+g)*4+2] + bx[g][0];
                    v.w = acc[(mh*4+g)*4+3] + bx[g][1];
                    *(float4*)(xp + (mh*4+g)*4) = v;
                }
        }
        __syncthreads();   // gbuf consumed before next stage_A overwrites it
    }
}

// ---------------- heads ----------------
__global__ void __launch_bounds__(256) heads_kernel(
    const float* __restrict__ x_stat,
    const float* __restrict__ fc1_w, const float* __restrict__ fc1_b,
    const float* __restrict__ fc2_w, const float* __restrict__ fc2_b,
    const float* __restrict__ fc3_w, const float* __restrict__ fc3_b,
    float* __restrict__ out)
{
    const int b = blockIdx.x;
    const int tid = threadIdx.x;

    float p0 = 0.f, p1 = 0.f;
    for (int idx = tid; idx < Tn*Hn; idx += 256){
        int t = idx >> 9;
        int u = idx & 511;
        float hv = __half2float(g_h1[(size_t)t * BH + (size_t)b * Hn + u]);
        p0 += hv * fc1_w[idx];
        p1 += hv * fc1_w[Tn*Hn + idx];
    }
    __shared__ float s0[256], s1[256];
    s0[tid] = p0; s1[tid] = p1;
    __syncthreads();
    for (int s = 128; s > 0; s >>= 1){
        if (tid < s){ s0[tid] += s0[tid+s]; s1[tid] += s1[tid+s]; }
        __syncthreads();
    }
    if (tid == 0){
        float tp0 = s0[0] + fc1_b[0];
        float tp1 = s1[0] + fc1_b[1];
        float xs0 = x_stat[b*3+0], xs1 = x_stat[b*3+1], xs2 = x_stat[b*3+2];
        float sp0 = fc2_b[0] + xs0*fc2_w[0] + xs1*fc2_w[1] + xs2*fc2_w[2];
        float sp1 = fc2_b[1] + xs0*fc2_w[3] + xs1*fc2_w[4] + xs2*fc2_w[5];
        out[b*2+0] = fc3_b[0] + fc3_w[0]*sp0 + fc3_w[1]*sp1 + fc3_w[2]*tp0 + fc3_w[3]*tp1;
        out[b*2+1] = fc3_b[1] + fc3_w[4]*sp0 + fc3_w[5]*sp1 + fc3_w[6]*tp0 + fc3_w[7]*tp1;
    }
}

extern "C" void kernel_launch(void* const* d_in, const int* in_sizes, int n_in,
                              void* d_out, int out_size)
{
    const float* x_time = (const float*)d_in[0];
    const float* x_stat = (const float*)d_in[1];
    const float* w_ih0  = (const float*)d_in[2];
    const float* w_hh0  = (const float*)d_in[3];
    const float* b0     = (const float*)d_in[4];
    const float* w_ih1  = (const float*)d_in[5];
    const float* w_hh1  = (const float*)d_in[6];
    const float* b1     = (const float*)d_in[7];
    const float* fc1_w  = (const float*)d_in[8];
    const float* fc1_b  = (const float*)d_in[9];
    const float* fc2_w  = (const float*)d_in[10];
    const float* fc2_b  = (const float*)d_in[11];
    const float* fc3_w  = (const float*)d_in[12];
    const float* fc3_b  = (const float*)d_in[13];
    float* out = (float*)d_out;

    cudaFuncSetAttribute(lstm_rec_kernel<0>, cudaFuncAttributeMaxDynamicSharedMemorySize, SMEMSZ);
    cudaFuncSetAttribute(lstm_rec_kernel<1>, cudaFuncAttributeMaxDynamicSharedMemorySize, SMEMSZ);
    cudaFuncSetAttribute(xp_kernel,          cudaFuncAttributeMaxDynamicSharedMemorySize, SMEMSZ);

    split_all_kernel<<<(G4*Hn + 255)/256, 256>>>(w_hh0, w_hh1, w_ih1);
    lstm_rec_kernel<0><<<NCTA, 256, SMEMSZ>>>(x_time, w_ih0, b0);
    xp_kernel<<<512, 256, SMEMSZ>>>(b1);
    lstm_rec_kernel<1><<<NCTA, 256, SMEMSZ>>>(x_time, w_ih0, b1);
    heads_kernel<<<Bn, 256>>>(x_stat, fc1_w, fc1_b, fc2_w, fc2_b, fc3_w, fc3_b, out);
}

// round 8
// speedup vs baseline: 4.4760x; 1.2073x over previous
#include <cuda_runtime.h>
#include <cuda_fp16.h>
#include <cstdint>
#include <math.h>

#define Tn   256
#define Bn   256
#define Hn   512
#define BH   (Bn*Hn)
#define G4   2048
#define NCTA 128

// ---------------- device globals (scratch) ----------------
__device__ __align__(128) __half g_whh0[G4*Hn];
__device__ __align__(128) __half g_whh1[G4*Hn];
__device__ __align__(128) __half g_wih1[G4*Hn];
__device__ __align__(128) __half g_h0[(size_t)Tn*BH];
__device__ __align__(128) __half g_h1[(size_t)Tn*BH];
__device__ __align__(128) float g_xp[(size_t)Tn*Bn*G4];   // [t][bt][nt][ktid(128)][32]
__device__ __align__(128) unsigned g_flag[4*32*32];       // (bt*32+nt)*32, 128B padded

// ---------------- SMEM layout (bytes) ----------------
// W rows: 64 packed rows pr = nh*32 + g*8 + u, stride 1040 B (512 fp16 + 8 pad)
// A rows: 64 b-rows x 256 k per chunk, stride 528 B (256 fp16 + 8 pad)
// gbuf (kg reduction, 64x68 f32 = 17408 B) aliases A chunk 0 (dead at reduction time)
#define W_OFF   0
#define A_OFF(db) (66560 + (db)*33792)
#define GBUF    66560
#define WIH0OFF 134144
#define SMEMSZ  136192

// ---------------- PTX helpers ----------------
__device__ __forceinline__ uint32_t su32(const void* p){
    uint32_t a;
    asm("{ .reg .u64 t; cvta.to.shared.u64 t, %1; cvt.u32.u64 %0, t; }" : "=r"(a) : "l"(p));
    return a;
}
__device__ __forceinline__ void ldmx4(uint32_t* r, uint32_t a){
    asm volatile("ldmatrix.sync.aligned.m8n8.x4.shared.b16 {%0,%1,%2,%3}, [%4];"
        : "=r"(r[0]), "=r"(r[1]), "=r"(r[2]), "=r"(r[3]) : "r"(a));
}
__device__ __forceinline__ void mma_f16(float* c, const uint32_t* a, uint32_t b0, uint32_t b1){
    asm("mma.sync.aligned.m16n8k16.row.col.f32.f16.f16.f32 "
        "{%0,%1,%2,%3}, {%4,%5,%6,%7}, {%8,%9}, {%0,%1,%2,%3};"
        : "+f"(c[0]), "+f"(c[1]), "+f"(c[2]), "+f"(c[3])
        : "r"(a[0]), "r"(a[1]), "r"(a[2]), "r"(a[3]), "r"(b0), "r"(b1));
}
__device__ __forceinline__ void cpa16(uint32_t dst, const void* src){
    asm volatile("cp.async.cg.shared.global [%0], [%1], 16;" :: "r"(dst), "l"(src));
}
#define CP_COMMIT asm volatile("cp.async.commit_group;" ::: "memory")
#define CP_WAIT0  asm volatile("cp.async.wait_group 0;" ::: "memory")
#define CP_WAIT1  asm volatile("cp.async.wait_group 1;" ::: "memory")

__device__ __forceinline__ uint32_t packh2(float a, float b){
    __half2 v = __floats2half2_rn(a, b);
    return *(uint32_t*)&v;
}
__device__ __forceinline__ float fsig(float x){
    return __fdividef(1.f, 1.f + __expf(-x));
}
__device__ __forceinline__ float ftanh(float x){
    return 1.f - __fdividef(2.f, __expf(2.f*x) + 1.f);
}

// ---------------- half-group flag wait (16 producer CTAs) ----------------
__device__ __forceinline__ void wait_half(int bt, int base, unsigned tgt, int tid){
    if (tid < 16){
        while (*((volatile unsigned*)&g_flag[(bt*32 + base + tid)*32]) < tgt) {}
        __threadfence();
    }
    __syncthreads();
}

// ---------------- prologue: fp32 -> fp16 weight convert + flag reset ----------------
__global__ void conv_all_kernel(const float* __restrict__ whh0,
                                const float* __restrict__ whh1,
                                const float* __restrict__ wih1)
{
    int i = blockIdx.x * blockDim.x + threadIdx.x;
    if (blockIdx.x == 0 && threadIdx.x < 128) g_flag[threadIdx.x * 32] = 0u;
    if (i >= G4*Hn) return;
    g_whh0[i] = __float2half_rn(whh0[i]);
    g_whh1[i] = __float2half_rn(whh1[i]);
    g_wih1[i] = __float2half_rn(wih1[i]);
}

// ---------------- staging (256 threads) ----------------
__device__ __forceinline__ void stage_A(const __half* __restrict__ src,
                                        int kc, uint32_t sA, int tid)
{
    #pragma unroll
    for (int it = 0; it < 8; ++it){
        int idx = tid + it*256;        // 0..2047
        int row = idx >> 5;            // 0..63
        int kk  = (idx & 31) << 3;     // fp16 elems
        cpa16(sA + (uint32_t)(row*528 + kk*2),
              src + (size_t)row * Hn + kc*256 + kk);
    }
}

// packed row pr -> weight row j: g=(pr>>3)&3, u=(pr&7)+(pr>>5)*8
__device__ __forceinline__ void stage_W(const __half* __restrict__ src,
                                        char* smem, int u0, int tid)
{
    for (int it = 0; it < 16; ++it){
        int idx = tid + it*256;
        int row = idx >> 6;
        int kk  = (idx & 63) << 3;
        int j = ((row >> 3) & 3) * Hn + u0 + (row & 7) + (row >> 5) * 8;
        uint4 v = *(const uint4*)(src + (size_t)j * Hn + kk);
        *(uint4*)(smem + W_OFF + row*1040 + kk*2) = v;
    }
}

// ---------------- fragment pipeline (warp tile 32x32, kg-split K, 1-pass fp16) ----------------
struct Frags { uint32_t a[8], w[8]; };

__device__ __forceinline__ void load_frags(Frags& f, uint32_t aB, uint32_t wB, int k16)
{
    ldmx4(f.a,     aB + k16*32);
    ldmx4(f.a + 4, aB + 16*528 + k16*32);
    ldmx4(f.w,     wB + k16*32);
    ldmx4(f.w + 4, wB + 16*1040 + k16*32);
}
__device__ __forceinline__ void do_hmma(float* acc, const Frags& f){
    #pragma unroll
    for (int mh = 0; mh < 2; ++mh)
        #pragma unroll
        for (int g = 0; g < 4; ++g)
            mma_f16(acc + (mh*4+g)*4, f.a + mh*4, f.w[g*2], f.w[g*2+1]);
}

// one K=256 chunk; this warp handles its kg-half (8 k16 iterations)
__device__ __forceinline__ void compute_chunk(uint32_t aB, uint32_t wB, float* acc)
{
    Frags f[2];
    load_frags(f[0], aB, wB, 0);
    #pragma unroll
    for (int k16 = 0; k16 < 8; ++k16){
        if (k16 < 7) load_frags(f[(k16+1)&1], aB, wB, k16+1);
        do_hmma(acc, f[k16&1]);
    }
}

// full K=512 GEMM body (both chunks); per-lane/kg offsets pre-baked
__device__ __forceinline__ void gemm_body(uint32_t sb, uint32_t aoff, uint32_t wboff,
                                          float* acc)
{
    compute_chunk(sb + A_OFF(0) + aoff, sb + W_OFF + wboff, acc);
    CP_WAIT0; __syncthreads();
    compute_chunk(sb + A_OFF(1) + aoff, sb + W_OFF + wboff + 512, acc);
}

// kg1 -> gbuf partial store
__device__ __forceinline__ void kg1_store(float* gb, const float* acc, int mg, int nh, int lane)
{
    int row0 = mg*32 + (lane >> 2);
    int p0   = nh*32 + 2*(lane & 3);
    #pragma unroll
    for (int mh = 0; mh < 2; ++mh)
        #pragma unroll
        for (int g = 0; g < 4; ++g){
            const float* c = acc + (mh*4+g)*4;
            int r = row0 + mh*16;
            int p = p0 + g*8;
            *(float2*)(gb + r*68 + p)     = make_float2(c[0], c[1]);
            *(float2*)(gb + (r+8)*68 + p) = make_float2(c[2], c[3]);
        }
}
// kg0 merge
__device__ __forceinline__ void kg0_merge(float* gb, float* acc, int mg, int nh, int lane)
{
    int row0 = mg*32 + (lane >> 2);
    int p0   = nh*32 + 2*(lane & 3);
    #pragma unroll
    for (int mh = 0; mh < 2; ++mh)
        #pragma unroll
        for (int g = 0; g < 4; ++g){
            float* c = acc + (mh*4+g)*4;
            int r = row0 + mh*16;
            int p = p0 + g*8;
            float2 v0 = *(float2*)(gb + r*68 + p);
            float2 v1 = *(float2*)(gb + (r+8)*68 + p);
            c[0] += v0.x; c[1] += v0.y; c[2] += v1.x; c[3] += v1.y;
        }
}

// ---------------- persistent recurrent layer ----------------
// Grid 128 = 4 bt x 32 nt. 256 thr = 8 warps: kg=wid>>2, mg=wid&1, nh=(wid>>1)&1.
template<int LAYER>
__global__ void __launch_bounds__(256, 1) lstm_rec_kernel(
    const float* __restrict__ x_time, const float* __restrict__ w_ih0,
    const float* __restrict__ bias)
{
    extern __shared__ __align__(128) char smem[];
    const int tid  = threadIdx.x;
    const int lane = tid & 31;
    const int wid  = tid >> 5;
    const int kg   = wid >> 2;
    const int mg   = wid & 1;
    const int nh   = (wid >> 1) & 1;
    const int bt   = blockIdx.x & 3;
    const int nt   = blockIdx.x >> 2;
    const int b0   = bt * 64;
    const int u0   = nt * 16;
    const uint32_t sb = su32(smem);

    const __half* whh = LAYER ? g_whh1 : g_whh0;
    __half* out = LAYER ? g_h1 : g_h0;

    stage_W(whh, smem, u0, tid);
    float* s_wih0 = (float*)(smem + WIH0OFF);
    if (LAYER == 0 && tid < 64){
        int j = ((tid >> 3) & 3) * Hn + u0 + (tid & 7) + (tid >> 5) * 8;
        #pragma unroll
        for (int q = 0; q < 5; ++q) s_wih0[tid*5 + q] = w_ih0[(size_t)j*5 + q];
    }
    __syncthreads();

    // per-lane ldmatrix offsets (include kg half offset: 8 k16 = 256 B)
    const uint32_t aoff  = (uint32_t)((mg*32 + (lane & 15)) * 528 + (lane >> 4) * 16
                                      + kg*256);
    const uint32_t wboff = (uint32_t)((nh*32 + (lane & 7) + ((lane >> 4) & 1) * 8) * 1040
                                      + ((lane >> 3) & 1) * 16 + kg*256);

    // kg0 cell ownership: rows b0 + mg*32 + mh*16 + (lane>>2) + rs*8;
    // units ubase + {0,1}; all 4 gates.
    const int q2    = 2 * (lane & 3);
    const int rb0   = mg*32 + (lane >> 2);
    const int ubase = u0 + nh*8 + q2;

    float breg[4][2];
    if (LAYER == 0){
        #pragma unroll
        for (int g = 0; g < 4; ++g){
            breg[g][0] = bias[g*Hn + ubase];
            breg[g][1] = bias[g*Hn + ubase + 1];
        }
    }

    const unsigned fbase = LAYER ? (Tn - 1) : 0;
    float* gb = (float*)(smem + GBUF);

    float c[8];
    #pragma unroll
    for (int i = 0; i < 8; ++i) c[i] = 0.f;

    float xpre[32];
    float xr[4][5];

    // prefetch step-0 inputs (kg0 only)
    if (kg == 0){
        if (LAYER == 1){
            const float* xp = g_xp + ((((size_t)0*4 + bt)*32 + nt)*128 + wid*32 + lane)*32;
            #pragma unroll
            for (int i = 0; i < 8; ++i){
                float4 v = *(const float4*)(xp + i*4);
                xpre[i*4+0]=v.x; xpre[i*4+1]=v.y; xpre[i*4+2]=v.z; xpre[i*4+3]=v.w;
            }
        } else {
            #pragma unroll
            for (int mh = 0; mh < 2; ++mh)
                #pragma unroll
                for (int rs = 0; rs < 2; ++rs){
                    const float* p = x_time + ((size_t)(b0 + rb0 + mh*16 + rs*8) * Tn) * 5;
                    #pragma unroll
                    for (int q = 0; q < 5; ++q) xr[mh*2+rs][q] = p[q];
                }
        }
    }

    for (int t = 0; t < Tn; ++t){
        float acc[32];
        #pragma unroll
        for (int i = 0; i < 32; ++i) acc[i] = 0.f;

        if (t > 0){
            const __half* src = out + (size_t)(t-1)*BH + (size_t)b0*Hn;
            unsigned tgt = fbase + (unsigned)t;
            wait_half(bt, 0, tgt, tid);             // producers of u-cols 0..255
            stage_A(src, 0, sb + A_OFF(0), tid);
            CP_COMMIT;
            wait_half(bt, 16, tgt, tid);            // producers of u-cols 256..511
            stage_A(src, 1, sb + A_OFF(1), tid);
            CP_COMMIT; CP_WAIT1; __syncthreads();
            gemm_body(sb, aoff, wboff, acc);
        }

        // kg reduction (gbuf aliases A chunk 0 — dead here)
        if (kg == 1) kg1_store(gb, acc, mg, nh, lane);
        __syncthreads();

        if (kg == 0){
            if (t > 0) kg0_merge(gb, acc, mg, nh, lane);

            if (LAYER == 1){
                #pragma unroll
                for (int i = 0; i < 32; ++i) acc[i] += xpre[i];
            } else {
                #pragma unroll
                for (int mh = 0; mh < 2; ++mh)
                    #pragma unroll
                    for (int rs = 0; rs < 2; ++rs)
                        #pragma unroll
                        for (int g = 0; g < 4; ++g)
                            #pragma unroll
                            for (int j = 0; j < 2; ++j){
                                const float* wr = s_wih0 + (nh*32 + g*8 + q2 + j)*5;
                                float d = breg[g][j];
                                #pragma unroll
                                for (int q = 0; q < 5; ++q) d += xr[mh*2+rs][q]*wr[q];
                                acc[(mh*4+g)*4 + rs*2 + j] += d;
                            }
            }

            // epilogue: 8 cells (4 rows x 2 units), all gates in-register
            #pragma unroll
            for (int mh = 0; mh < 2; ++mh)
                #pragma unroll
                for (int rs = 0; rs < 2; ++rs){
                    int row = rb0 + mh*16 + rs*8;
                    float hv[2];
                    #pragma unroll
                    for (int j = 0; j < 2; ++j){
                        float ai = acc[(mh*4+0)*4 + rs*2 + j];
                        float af = acc[(mh*4+1)*4 + rs*2 + j];
                        float ag = acc[(mh*4+2)*4 + rs*2 + j];
                        float ao = acc[(mh*4+3)*4 + rs*2 + j];
                        int ci = mh*4 + rs*2 + j;
                        c[ci] = fsig(af) * c[ci] + fsig(ai) * ftanh(ag);
                        hv[j] = fsig(ao) * ftanh(c[ci]);
                    }
                    size_t ob = (size_t)t*BH + (size_t)(b0+row)*Hn + ubase;
                    *(uint32_t*)(out + ob) = packh2(hv[0], hv[1]);
                }

            // prefetch next-step inputs
            if (t < Tn - 1){
                if (LAYER == 1){
                    const float* xp = g_xp + ((((size_t)(t+1)*4 + bt)*32 + nt)*128
                                              + wid*32 + lane)*32;
                    #pragma unroll
                    for (int i = 0; i < 8; ++i){
                        float4 v = *(const float4*)(xp + i*4);
                        xpre[i*4+0]=v.x; xpre[i*4+1]=v.y; xpre[i*4+2]=v.z; xpre[i*4+3]=v.w;
                    }
                } else {
                    #pragma unroll
                    for (int mh = 0; mh < 2; ++mh)
                        #pragma unroll
                        for (int rs = 0; rs < 2; ++rs){
                            const float* p = x_time
                                + ((size_t)(b0 + rb0 + mh*16 + rs*8) * Tn + (t+1)) * 5;
                            #pragma unroll
                            for (int q = 0; q < 5; ++q) xr[mh*2+rs][q] = p[q];
                        }
                }
            }
        }

        if (t < Tn - 1){
            __syncthreads();
            if (tid == 0){
                __threadfence();
                *((volatile unsigned*)&g_flag[(bt*32 + nt)*32]) = fbase + (unsigned)t + 1u;
            }
        }
    }
}

// ---------------- parallel precompute: xp = h0 @ W_ih1^T + b1 (fragment layout) ----------------
__global__ void __launch_bounds__(256, 1) xp_kernel(const float* __restrict__ bias)
{
    extern __shared__ __align__(128) char smem[];
    const int tid  = threadIdx.x;
    const int lane = tid & 31;
    const int wid  = tid >> 5;
    const int kg   = wid >> 2;
    const int mg   = wid & 1;
    const int nh   = (wid >> 1) & 1;
    const int nt   = blockIdx.x & 31;
    const int grp  = blockIdx.x >> 5;
    const int u0   = nt * 16;
    const uint32_t sb = su32(smem);

    stage_W(g_wih1, smem, u0, tid);
    __syncthreads();

    const uint32_t aoff  = (uint32_t)((mg*32 + (lane & 15)) * 528 + (lane >> 4) * 16
                                      + kg*256);
    const uint32_t wboff = (uint32_t)((nh*32 + (lane & 7) + ((lane >> 4) & 1) * 8) * 1040
                                      + ((lane >> 3) & 1) * 16 + kg*256);
    const int q2    = 2 * (lane & 3);
    const int ubase = u0 + nh*8 + q2;
    float* gb = (float*)(smem + GBUF);

    float bx[4][2];
    #pragma unroll
    for (int g = 0; g < 4; ++g){
        bx[g][0] = bias[g*Hn + ubase];
        bx[g][1] = bias[g*Hn + ubase + 1];
    }

    for (int mi = 0; mi < 64; ++mi){
        int mt = grp * 64 + mi;
        int t  = mt >> 2;
        int bt = mt & 3;
        int b0 = bt * 64;
        const __half* src = g_h0 + (size_t)t*BH + (size_t)b0*Hn;

        float acc[32];
        #pragma unroll
        for (int i = 0; i < 32; ++i) acc[i] = 0.f;

        stage_A(src, 0, sb + A_OFF(0), tid);
        CP_COMMIT;
        stage_A(src, 1, sb + A_OFF(1), tid);
        CP_COMMIT; CP_WAIT1; __syncthreads();
        gemm_body(sb, aoff, wboff, acc);

        if (kg == 1) kg1_store(gb, acc, mg, nh, lane);
        __syncthreads();
        if (kg == 0){
            kg0_merge(gb, acc, mg, nh, lane);
            float* xp = g_xp + ((((size_t)t*4 + bt)*32 + nt)*128 + wid*32 + lane)*32;
            #pragma unroll
            for (int mh = 0; mh < 2; ++mh)
                #pragma unroll
                for (int g = 0; g < 4; ++g){
                    float4 v;
                    v.x = acc[(mh*4+g)*4+0] + bx[g][0];
                    v.y = acc[(mh*4+g)*4+1] + bx[g][1];
                    v.z = acc[(mh*4+g)*4+2] + bx[g][0];
                    v.w = acc[(mh*4+g)*4+3] + bx[g][1];
                    *(float4*)(xp + (mh*4+g)*4) = v;
                }
        }
        __syncthreads();   // gbuf consumed before next stage_A overwrites it
    }
}

// ---------------- heads ----------------
__global__ void __launch_bounds__(256) heads_kernel(
    const float* __restrict__ x_stat,
    const float* __restrict__ fc1_w, const float* __restrict__ fc1_b,
    const float* __restrict__ fc2_w, const float* __restrict__ fc2_b,
    const float* __restrict__ fc3_w, const float* __restrict__ fc3_b,
    float* __restrict__ out)
{
    const int b = blockIdx.x;
    const int tid = threadIdx.x;

    float p0 = 0.f, p1 = 0.f;
    for (int idx = tid; idx < Tn*Hn; idx += 256){
        int t = idx >> 9;
        int u = idx & 511;
        float hv = __half2float(g_h1[(size_t)t * BH + (size_t)b * Hn + u]);
        p0 += hv * fc1_w[idx];
        p1 += hv * fc1_w[Tn*Hn + idx];
    }
    __shared__ float s0[256], s1[256];
    s0[tid] = p0; s1[tid] = p1;
    __syncthreads();
    for (int s = 128; s > 0; s >>= 1){
        if (tid < s){ s0[tid] += s0[tid+s]; s1[tid] += s1[tid+s]; }
        __syncthreads();
    }
    if (tid == 0){
        float tp0 = s0[0] + fc1_b[0];
        float tp1 = s1[0] + fc1_b[1];
        float xs0 = x_stat[b*3+0], xs1 = x_stat[b*3+1], xs2 = x_stat[b*3+2];
        float sp0 = fc2_b[0] + xs0*fc2_w[0] + xs1*fc2_w[1] + xs2*fc2_w[2];
        float sp1 = fc2_b[1] + xs0*fc2_w[3] + xs1*fc2_w[4] + xs2*fc2_w[5];
        out[b*2+0] = fc3_b[0] + fc3_w[0]*sp0 + fc3_w[1]*sp1 + fc3_w[2]*tp0 + fc3_w[3]*tp1;
        out[b*2+1] = fc3_b[1] + fc3_w[4]*sp0 + fc3_w[5]*sp1 + fc3_w[6]*tp0 + fc3_w[7]*tp1;
    }
}

extern "C" void kernel_launch(void* const* d_in, const int* in_sizes, int n_in,
                              void* d_out, int out_size)
{
    const float* x_time = (const float*)d_in[0];
    const float* x_stat = (const float*)d_in[1];
    const float* w_ih0  = (const float*)d_in[2];
    const float* w_hh0  = (const float*)d_in[3];
    const float* b0     = (const float*)d_in[4];
    const float* w_ih1  = (const float*)d_in[5];
    const float* w_hh1  = (const float*)d_in[6];
    const float* b1     = (const float*)d_in[7];
    const float* fc1_w  = (const float*)d_in[8];
    const float* fc1_b  = (const float*)d_in[9];
    const float* fc2_w  = (const float*)d_in[10];
    const float* fc2_b  = (const float*)d_in[11];
    const float* fc3_w  = (const float*)d_in[12];
    const float* fc3_b  = (const float*)d_in[13];
    float* out = (float*)d_out;

    cudaFuncSetAttribute(lstm_rec_kernel<0>, cudaFuncAttributeMaxDynamicSharedMemorySize, SMEMSZ);
    cudaFuncSetAttribute(lstm_rec_kernel<1>, cudaFuncAttributeMaxDynamicSharedMemorySize, SMEMSZ);
    cudaFuncSetAttribute(xp_kernel,          cudaFuncAttributeMaxDynamicSharedMemorySize, SMEMSZ);

    conv_all_kernel<<<(G4*Hn + 255)/256, 256>>>(w_hh0, w_hh1, w_ih1);
    lstm_rec_kernel<0><<<NCTA, 256, SMEMSZ>>>(x_time, w_ih0, b0);
    xp_kernel<<<512, 256, SMEMSZ>>>(b1);
    lstm_rec_kernel<1><<<NCTA, 256, SMEMSZ>>>(x_time, w_ih0, b1);
    heads_kernel<<<Bn, 256>>>(x_stat, fc1_w, fc1_b, fc2_w, fc2_b, fc3_w, fc3_b, out);
}

// round 9
// speedup vs baseline: 4.8192x; 1.0767x over previous
#include <cuda_runtime.h>
#include <cuda_fp16.h>
#include <cstdint>
#include <math.h>

#define Tn 256
#define Bn 256
#define Hn 512
#define BH (Bn*Hn)
#define G4 2048

// ---------------- device globals (scratch) ----------------
__device__ __align__(128) __half g_whh0[G4*Hn];
__device__ __align__(128) __half g_whh1[G4*Hn];
__device__ __align__(128) __half g_wih1[G4*Hn];
__device__ __align__(128) __half g_h0[(size_t)Tn*BH];
__device__ __align__(128) __half g_h1[(size_t)Tn*BH];
__device__ __align__(128) float g_xp[134217728];      // [t][bt][nt][tid(256)][32] fp32
__device__ __align__(128) unsigned g_flagA[2048];     // L0: h0_t + xp_{t-1} published
__device__ __align__(128) unsigned g_flagB[2048];     // L1: h1_t published

// ---------------- SMEM layout (bytes) ----------------
// W tiles: 64 packed rows pr = nh*32 + g*8 + u, stride 1040 (512 fp16 + 8 pad)
// A tiles: 128 b-rows x 128 k per chunk, stride 272 (128 fp16 + 8 pad)
#define W0OFF 0
#define W1OFF 66560
#define A_OFF(db) (133120 + (db)*34816)
#define WIH0OFF 202752
#define SMEMSZ 204800

// ---------------- PTX helpers ----------------
__device__ __forceinline__ uint32_t su32(const void* p){
    uint32_t a;
    asm("{ .reg .u64 t; cvta.to.shared.u64 t, %1; cvt.u32.u64 %0, t; }" : "=r"(a) : "l"(p));
    return a;
}
__device__ __forceinline__ void ldmx4(uint32_t* r, uint32_t a){
    asm volatile("ldmatrix.sync.aligned.m8n8.x4.shared.b16 {%0,%1,%2,%3}, [%4];"
        : "=r"(r[0]), "=r"(r[1]), "=r"(r[2]), "=r"(r[3]) : "r"(a));
}
__device__ __forceinline__ void mma_f16(float* c, const uint32_t* a, uint32_t b0, uint32_t b1){
    asm("mma.sync.aligned.m16n8k16.row.col.f32.f16.f16.f32 "
        "{%0,%1,%2,%3}, {%4,%5,%6,%7}, {%8,%9}, {%0,%1,%2,%3};"
        : "+f"(c[0]), "+f"(c[1]), "+f"(c[2]), "+f"(c[3])
        : "r"(a[0]), "r"(a[1]), "r"(a[2]), "r"(a[3]), "r"(b0), "r"(b1));
}
__device__ __forceinline__ void cpa16(uint32_t dst, const void* src){
    asm volatile("cp.async.cg.shared.global [%0], [%1], 16;" :: "r"(dst), "l"(src));
}
#define CP_COMMIT asm volatile("cp.async.commit_group;" ::: "memory")
#define CP_WAIT0  asm volatile("cp.async.wait_group 0;" ::: "memory")
#define CP_WAIT1  asm volatile("cp.async.wait_group 1;" ::: "memory")

__device__ __forceinline__ uint32_t packh2(float a, float b){
    __half2 v = __floats2half2_rn(a, b);
    return *(uint32_t*)&v;
}
__device__ __forceinline__ float fsig(float x){
    return __fdividef(1.f, 1.f + __expf(-x));
}
__device__ __forceinline__ float ftanh(float x){
    return 1.f - __fdividef(2.f, __expf(2.f*x) + 1.f);
}

// ---------------- per-chunk producer wait (8 flags) ----------------
__device__ __forceinline__ void wait8(unsigned* flg, int base, unsigned tgt, int tid){
    if (tid < 8){
        volatile unsigned* p = flg + (size_t)(base + tid)*32;
        while (*p < tgt) {}
        __threadfence();
    }
    __syncthreads();
}

// ---------------- prologue: fp32 -> fp16 weight convert + flag reset ----------------
__global__ void conv_all_kernel(const float* __restrict__ whh0,
                                const float* __restrict__ whh1,
                                const float* __restrict__ wih1)
{
    int i = blockIdx.x * blockDim.x + threadIdx.x;
    if (blockIdx.x == 0){
        for (int k = threadIdx.x; k < 2048; k += 256){ g_flagA[k] = 0u; g_flagB[k] = 0u; }
    }
    if (i >= G4*Hn) return;
    g_whh0[i] = __float2half_rn(whh0[i]);
    g_whh1[i] = __float2half_rn(whh1[i]);
    g_wih1[i] = __float2half_rn(wih1[i]);
}

// ---------------- staging (256 threads) ----------------
// one K=128 chunk of A: 128 rows x 256 B
__device__ __forceinline__ void stage_A128(const __half* __restrict__ src,
                                           int kc, uint32_t sA, int tid)
{
    #pragma unroll
    for (int it = 0; it < 8; ++it){
        int idx = tid + it*256;        // 0..2047
        int row = idx >> 4;            // 0..127
        int kk  = (idx & 15) << 3;     // fp16 elems 0..120
        cpa16(sA + (uint32_t)(row*272 + kk*2),
              src + (size_t)row * Hn + kc*128 + kk);
    }
}

// persistent W tile: packed row pr -> j: g=(pr>>3)&3, u=(pr&7)+(pr>>5)*8
__device__ __forceinline__ void stage_W(const __half* __restrict__ src,
                                        char* smem, int woff, int u0, int tid)
{
    for (int it = 0; it < 16; ++it){
        int idx = tid + it*256;
        int row = idx >> 6;
        int kk  = (idx & 63) << 3;
        int j = ((row >> 3) & 3) * Hn + u0 + (row & 7) + (row >> 5) * 8;
        uint4 v = *(const uint4*)(src + (size_t)j * Hn + kk);
        *(uint4*)(smem + woff + row*1040 + kk*2) = v;
    }
}

// ---------------- fragment pipelines (warp tile 32x32, mg4 x nh2, full K) ----------------
struct Fr2 { uint32_t a[8], wr[8], wx[8]; };
struct Fr1 { uint32_t a[8], wr[8]; };

__device__ __forceinline__ void load2(Fr2& f, uint32_t aB, uint32_t wrB, uint32_t wxB, int k16){
    ldmx4(f.a,     aB + k16*32);
    ldmx4(f.a + 4, aB + 4352 + k16*32);          // +16 rows * 272
    ldmx4(f.wr,     wrB + k16*32);
    ldmx4(f.wr + 4, wrB + 16640 + k16*32);       // +16 packed rows * 1040
    ldmx4(f.wx,     wxB + k16*32);
    ldmx4(f.wx + 4, wxB + 16640 + k16*32);
}
__device__ __forceinline__ void load1(Fr1& f, uint32_t aB, uint32_t wrB, int k16){
    ldmx4(f.a,     aB + k16*32);
    ldmx4(f.a + 4, aB + 4352 + k16*32);
    ldmx4(f.wr,     wrB + k16*32);
    ldmx4(f.wr + 4, wrB + 16640 + k16*32);
}

// one K=128 chunk, rec + xp sharing A fragments
__device__ __forceinline__ void chunk2(uint32_t aB, uint32_t wrB, uint32_t wxB,
                                       float* accR, float* accX)
{
    Fr2 f[2];
    load2(f[0], aB, wrB, wxB, 0);
    #pragma unroll
    for (int k16 = 0; k16 < 8; ++k16){
        if (k16 < 7) load2(f[(k16+1)&1], aB, wrB, wxB, k16+1);
        const Fr2& fc = f[k16&1];
        #pragma unroll
        for (int mh = 0; mh < 2; ++mh)
            #pragma unroll
            for (int g = 0; g < 4; ++g)
                mma_f16(accR + (mh*4+g)*4, fc.a + mh*4, fc.wr[g*2], fc.wr[g*2+1]);
        #pragma unroll
        for (int mh = 0; mh < 2; ++mh)
            #pragma unroll
            for (int g = 0; g < 4; ++g)
                mma_f16(accX + (mh*4+g)*4, fc.a + mh*4, fc.wx[g*2], fc.wx[g*2+1]);
    }
}
__device__ __forceinline__ void chunk1(uint32_t aB, uint32_t wrB, float* accR)
{
    Fr1 f[2];
    load1(f[0], aB, wrB, 0);
    #pragma unroll
    for (int k16 = 0; k16 < 8; ++k16){
        if (k16 < 7) load1(f[(k16+1)&1], aB, wrB, k16+1);
        const Fr1& fc = f[k16&1];
        #pragma unroll
        for (int mh = 0; mh < 2; ++mh)
            #pragma unroll
            for (int g = 0; g < 4; ++g)
                mma_f16(accR + (mh*4+g)*4, fc.a + mh*4, fc.wr[g*2], fc.wr[g*2+1]);
    }
}

// full K=512 GEMM: 4 chunks, per-chunk producer waits + cp.async double buffering
template<int XP>
__device__ __forceinline__ void gemm512(const __half* __restrict__ src, uint32_t sb,
                                        uint32_t aoff, uint32_t wboff,
                                        float* accR, float* accX, int tid,
                                        unsigned* flg, int fbase, unsigned tgt)
{
    wait8(flg, fbase + 0, tgt, tid);
    stage_A128(src, 0, sb + A_OFF(0), tid); CP_COMMIT;
    #pragma unroll 1
    for (int c = 0; c < 4; ++c){
        if (c < 3){
            wait8(flg, fbase + (c+1)*8, tgt, tid);
            stage_A128(src, c+1, sb + A_OFF((c+1)&1), tid); CP_COMMIT; CP_WAIT1;
        } else { CP_WAIT0; }
        __syncthreads();
        if (XP) chunk2(sb + A_OFF(c&1) + aoff, sb + W0OFF + wboff + c*256,
                       sb + W1OFF + wboff + c*256, accR, accX);
        else    chunk1(sb + A_OFF(c&1) + aoff, sb + W0OFF + wboff + c*256, accR);
        __syncthreads();
    }
}

// ---------------- fused two-layer pipelined kernel ----------------
// 128 CTAs: role 0 (blk 0..63) = layer0 rec + xp precompute for layer1;
//           role 1 (blk 64..127) = layer1 rec (consumes xp at lag 2).
// Per role: 2 bt (128 b) x 32 nt (16 u). 8 warps: mg = wid>>1 (m32), nh = wid&1 (n32).
__global__ void __launch_bounds__(256, 1) lstm_fused(
    const float* __restrict__ x_time, const float* __restrict__ w_ih0,
    const float* __restrict__ bias0, const float* __restrict__ bias1)
{
    extern __shared__ __align__(128) char smem[];
    const int tid  = threadIdx.x;
    const int lane = tid & 31;
    const int wid  = tid >> 5;
    const int mg   = wid >> 1;
    const int nh   = wid & 1;
    const int role = blockIdx.x >> 6;
    const int lidx = blockIdx.x & 63;
    const int bt   = lidx >> 5;
    const int nt   = lidx & 31;
    const int b0   = bt * 128;
    const int u0   = nt * 16;
    const uint32_t sb = su32(smem);

    // per-lane ldmatrix offsets
    const uint32_t aoff  = (uint32_t)((mg*32 + (lane & 15)) * 272 + (lane >> 4) * 16);
    const uint32_t wboff = (uint32_t)((nh*32 + (lane & 7) + ((lane >> 4) & 1) * 8) * 1040
                                      + ((lane >> 3) & 1) * 16);
    // cell ownership: rows b0 + rb0 + mh*16 + rs*8; units ubase + {0,1}; all 4 gates
    const int q2    = 2 * (lane & 3);
    const int rb0   = mg*32 + (lane >> 2);
    const int ubase = u0 + nh*8 + q2;

    if (role == 0){
        // ================= layer 0 + xp producer =================
        stage_W(g_whh0, smem, W0OFF, u0, tid);
        stage_W(g_wih1, smem, W1OFF, u0, tid);
        float* s_wih0 = (float*)(smem + WIH0OFF);
        if (tid < 64){
            int j = ((tid >> 3) & 3) * Hn + u0 + (tid & 7) + (tid >> 5) * 8;
            #pragma unroll
            for (int q = 0; q < 5; ++q) s_wih0[tid*5 + q] = w_ih0[(size_t)j*5 + q];
        }
        float breg[4][2], bx[4][2];
        #pragma unroll
        for (int g = 0; g < 4; ++g){
            breg[g][0] = bias0[g*Hn + ubase];
            breg[g][1] = bias0[g*Hn + ubase + 1];
            bx[g][0]   = bias1[g*Hn + ubase];
            bx[g][1]   = bias1[g*Hn + ubase + 1];
        }
        __syncthreads();

        float c[8];
        #pragma unroll
        for (int i = 0; i < 8; ++i) c[i] = 0.f;

        for (int t = 0; t <= Tn; ++t){
            // prefetch this step's x inputs (independent of flags)
            float xr[4][5];
            if (t < Tn){
                #pragma unroll
                for (int mh = 0; mh < 2; ++mh)
                    #pragma unroll
                    for (int rs = 0; rs < 2; ++rs){
                        const float* p = x_time
                            + ((size_t)(b0 + rb0 + mh*16 + rs*8) * Tn + t) * 5;
                        #pragma unroll
                        for (int q = 0; q < 5; ++q) xr[mh*2+rs][q] = p[q];
                    }
            }

            float accR[32], accX[32];
            #pragma unroll
            for (int i = 0; i < 32; ++i){ accR[i] = 0.f; accX[i] = 0.f; }

            if (t > 0)
                gemm512<1>(g_h0 + (size_t)(t-1)*BH + (size_t)b0*Hn, sb, aoff, wboff,
                           accR, accX, tid, g_flagA, bt*32, (unsigned)t);

            if (t < Tn){
                // x-projection + bias into accR
                #pragma unroll
                for (int mh = 0; mh < 2; ++mh)
                    #pragma unroll
                    for (int rs = 0; rs < 2; ++rs)
                        #pragma unroll
                        for (int g = 0; g < 4; ++g)
                            #pragma unroll
                            for (int j = 0; j < 2; ++j){
                                const float* wr = s_wih0 + (nh*32 + g*8 + q2 + j)*5;
                                float d = breg[g][j];
                                #pragma unroll
                                for (int q = 0; q < 5; ++q) d += xr[mh*2+rs][q]*wr[q];
                                accR[(mh*4+g)*4 + rs*2 + j] += d;
                            }
                // epilogue: 8 cells, write h0_t (fp16)
                #pragma unroll
                for (int mh = 0; mh < 2; ++mh)
                    #pragma unroll
                    for (int rs = 0; rs < 2; ++rs){
                        int row = rb0 + mh*16 + rs*8;
                        float hv[2];
                        #pragma unroll
                        for (int j = 0; j < 2; ++j){
                            float ai = accR[(mh*4+0)*4 + rs*2 + j];
                            float af = accR[(mh*4+1)*4 + rs*2 + j];
                            float ag = accR[(mh*4+2)*4 + rs*2 + j];
                            float ao = accR[(mh*4+3)*4 + rs*2 + j];
                            int ci = mh*4 + rs*2 + j;
                            c[ci] = fsig(af) * c[ci] + fsig(ai) * ftanh(ag);
                            hv[j] = fsig(ao) * ftanh(c[ci]);
                        }
                        size_t ob = (size_t)t*BH + (size_t)(b0+row)*Hn + ubase;
                        *(uint32_t*)(g_h0 + ob) = packh2(hv[0], hv[1]);
                    }
            }

            if (t > 0){
                // store xp_{t-1} (+bias1) in consumer fragment layout
                float* xp = g_xp + ((((size_t)(t-1)*2 + bt)*32 + nt)*256 + tid)*32;
                #pragma unroll
                for (int mh = 0; mh < 2; ++mh)
                    #pragma unroll
                    for (int g = 0; g < 4; ++g){
                        int i = mh*4 + g;
                        float4 v;
                        v.x = accX[i*4+0] + bx[g][0];
                        v.y = accX[i*4+1] + bx[g][1];
                        v.z = accX[i*4+2] + bx[g][0];
                        v.w = accX[i*4+3] + bx[g][1];
                        *(float4*)(xp + i*4) = v;
                    }
            }

            __syncthreads();
            if (tid == 0){
                __threadfence();
                *((volatile unsigned*)&g_flagA[(size_t)(bt*32 + nt)*32]) = (unsigned)(t + 1);
            }
        }
    } else {
        // ================= layer 1 consumer =================
        stage_W(g_whh1, smem, W0OFF, u0, tid);
        __syncthreads();

        float c[8];
        #pragma unroll
        for (int i = 0; i < 8; ++i) c[i] = 0.f;

        for (int t = 0; t < Tn; ++t){
            // xp_t readiness: partner L0 CTA must have finished its step t+1
            if (tid == 0){
                volatile unsigned* p = &g_flagA[(size_t)(bt*32 + nt)*32];
                while (*p < (unsigned)(t + 2)) {}
                __threadfence();
            }
            __syncthreads();

            // prefetch xp_t (hidden behind the GEMM)
            const float* xps = g_xp + ((((size_t)t*2 + bt)*32 + nt)*256 + tid)*32;
            float xpre[32];
            #pragma unroll
            for (int i = 0; i < 8; ++i){
                float4 v = *(const float4*)(xps + i*4);
                xpre[i*4+0]=v.x; xpre[i*4+1]=v.y; xpre[i*4+2]=v.z; xpre[i*4+3]=v.w;
            }

            float accR[32];
            #pragma unroll
            for (int i = 0; i < 32; ++i) accR[i] = 0.f;

            if (t > 0)
                gemm512<0>(g_h1 + (size_t)(t-1)*BH + (size_t)b0*Hn, sb, aoff, wboff,
                           accR, (float*)0, tid, g_flagB, bt*32, (unsigned)t);

            #pragma unroll
            for (int i = 0; i < 32; ++i) accR[i] += xpre[i];

            // epilogue: 8 cells, write h1_t (fp16)
            #pragma unroll
            for (int mh = 0; mh < 2; ++mh)
                #pragma unroll
                for (int rs = 0; rs < 2; ++rs){
                    int row = rb0 + mh*16 + rs*8;
                    float hv[2];
                    #pragma unroll
                    for (int j = 0; j < 2; ++j){
                        float ai = accR[(mh*4+0)*4 + rs*2 + j];
                        float af = accR[(mh*4+1)*4 + rs*2 + j];
                        float ag = accR[(mh*4+2)*4 + rs*2 + j];
                        float ao = accR[(mh*4+3)*4 + rs*2 + j];
                        int ci = mh*4 + rs*2 + j;
                        c[ci] = fsig(af) * c[ci] + fsig(ai) * ftanh(ag);
                        hv[j] = fsig(ao) * ftanh(c[ci]);
                    }
                    size_t ob = (size_t)t*BH + (size_t)(b0+row)*Hn + ubase;
                    *(uint32_t*)(g_h1 + ob) = packh2(hv[0], hv[1]);
                }

            __syncthreads();
            if (tid == 0){
                __threadfence();
                *((volatile unsigned*)&g_flagB[(size_t)(bt*32 + nt)*32]) = (unsigned)(t + 1);
            }
        }
    }
}

// ---------------- heads ----------------
__global__ void __launch_bounds__(256) heads_kernel(
    const float* __restrict__ x_stat,
    const float* __restrict__ fc1_w, const float* __restrict__ fc1_b,
    const float* __restrict__ fc2_w, const float* __restrict__ fc2_b,
    const float* __restrict__ fc3_w, const float* __restrict__ fc3_b,
    float* __restrict__ out)
{
    const int b = blockIdx.x;
    const int tid = threadIdx.x;

    float p0 = 0.f, p1 = 0.f;
    for (int idx = tid; idx < Tn*Hn; idx += 256){
        int t = idx >> 9;
        int u = idx & 511;
        float hv = __half2float(g_h1[(size_t)t * BH + (size_t)b * Hn + u]);
        p0 += hv * fc1_w[idx];
        p1 += hv * fc1_w[Tn*Hn + idx];
    }
    __shared__ float s0[256], s1[256];
    s0[tid] = p0; s1[tid] = p1;
    __syncthreads();
    for (int s = 128; s > 0; s >>= 1){
        if (tid < s){ s0[tid] += s0[tid+s]; s1[tid] += s1[tid+s]; }
        __syncthreads();
    }
    if (tid == 0){
        float tp0 = s0[0] + fc1_b[0];
        float tp1 = s1[0] + fc1_b[1];
        float xs0 = x_stat[b*3+0], xs1 = x_stat[b*3+1], xs2 = x_stat[b*3+2];
        float sp0 = fc2_b[0] + xs0*fc2_w[0] + xs1*fc2_w[1] + xs2*fc2_w[2];
        float sp1 = fc2_b[1] + xs0*fc2_w[3] + xs1*fc2_w[4] + xs2*fc2_w[5];
        out[b*2+0] = fc3_b[0] + fc3_w[0]*sp0 + fc3_w[1]*sp1 + fc3_w[2]*tp0 + fc3_w[3]*tp1;
        out[b*2+1] = fc3_b[1] + fc3_w[4]*sp0 + fc3_w[5]*sp1 + fc3_w[6]*tp0 + fc3_w[7]*tp1;
    }
}

extern "C" void kernel_launch(void* const* d_in, const int* in_sizes, int n_in,
                              void* d_out, int out_size)
{
    const float* x_time = (const float*)d_in[0];
    const float* x_stat = (const float*)d_in[1];
    const float* w_ih0  = (const float*)d_in[2];
    const float* w_hh0  = (const float*)d_in[3];
    const float* b0     = (const float*)d_in[4];
    const float* w_ih1  = (const float*)d_in[5];
    const float* w_hh1  = (const float*)d_in[6];
    const float* b1     = (const float*)d_in[7];
    const float* fc1_w  = (const float*)d_in[8];
    const float* fc1_b  = (const float*)d_in[9];
    const float* fc2_w  = (const float*)d_in[10];
    const float* fc2_b  = (const float*)d_in[11];
    const float* fc3_w  = (const float*)d_in[12];
    const float* fc3_b  = (const float*)d_in[13];
    float* out = (float*)d_out;

    cudaFuncSetAttribute(lstm_fused, cudaFuncAttributeMaxDynamicSharedMemorySize, SMEMSZ);

    conv_all_kernel<<<(G4*Hn + 255)/256, 256>>>(w_hh0, w_hh1, w_ih1);
    lstm_fused<<<128, 256, SMEMSZ>>>(x_time, w_ih0, b0, b1);
    heads_kernel<<<Bn, 256>>>(x_stat, fc1_w, fc1_b, fc2_w, fc2_b, fc3_w, fc3_b, out);
}

// round 11
// speedup vs baseline: 7.2812x; 1.5109x over previous
#include <cuda_runtime.h>
#include <cuda_fp16.h>
#include <cstdint>
#include <math.h>

#define Tn 256
#define Bn 256
#define Hn 512
#define BH (Bn*Hn)
#define G4 2048

// ---------------- device globals (scratch) ----------------
__device__ __align__(128) __half g_whh0[G4*Hn];
__device__ __align__(128) __half g_whh1[G4*Hn];
__device__ __align__(128) __half g_wih1[G4*Hn];
__device__ __align__(128) __half g_h0[(size_t)Tn*BH];
__device__ __align__(128) __half g_h1[(size_t)Tn*BH];
__device__ __align__(128) float g_xp[134217728];      // [t][bt][nt][tid(256)][32] fp32
// per-(layer,bt,mg,t) release counters, padded to 32B
__device__ __align__(128) unsigned g_cnt[16*257*8];

// ---------------- SMEM layout (bytes) ----------------
// W tiles: 64 packed rows pr = nh*32 + g*8 + u, stride 1040 (512 fp16 + 8 pad)
// A: per-pair private region: pair mg at ABASE + mg*17408; 2 bufs of 8704
//    (32 rows x 272 B, row = global row mg*32 + r)
#define W0OFF 0
#define W1OFF 66560
#define ABASE 133120
#define WIH0OFF 202752
#define SMEMSZ 204800

// ---------------- PTX helpers ----------------
__device__ __forceinline__ uint32_t su32(const void* p){
    uint32_t a;
    asm("{ .reg .u64 t; cvta.to.shared.u64 t, %1; cvt.u32.u64 %0, t; }" : "=r"(a) : "l"(p));
    return a;
}
__device__ __forceinline__ void ldmx4(uint32_t* r, uint32_t a){
    asm volatile("ldmatrix.sync.aligned.m8n8.x4.shared.b16 {%0,%1,%2,%3}, [%4];"
        : "=r"(r[0]), "=r"(r[1]), "=r"(r[2]), "=r"(r[3]) : "r"(a));
}
__device__ __forceinline__ void mma_f16(float* c, const uint32_t* a, uint32_t b0, uint32_t b1){
    asm("mma.sync.aligned.m16n8k16.row.col.f32.f16.f16.f32 "
        "{%0,%1,%2,%3}, {%4,%5,%6,%7}, {%8,%9}, {%0,%1,%2,%3};"
        : "+f"(c[0]), "+f"(c[1]), "+f"(c[2]), "+f"(c[3])
        : "r"(a[0]), "r"(a[1]), "r"(a[2]), "r"(a[3]), "r"(b0), "r"(b1));
}
__device__ __forceinline__ void cpa16(uint32_t dst, const void* src){
    asm volatile("cp.async.cg.shared.global [%0], [%1], 16;" :: "r"(dst), "l"(src));
}
#define CP_COMMIT asm volatile("cp.async.commit_group;" ::: "memory")
#define CP_WAIT0  asm volatile("cp.async.wait_group 0;" ::: "memory")
#define CP_WAIT1  asm volatile("cp.async.wait_group 1;" ::: "memory")
// two-warp named barrier for the mg pair (ids 1..4; __syncthreads uses 0)
#define PAIRBAR(mg) asm volatile("bar.sync %0, 64;" :: "r"((mg)+1) : "memory")

__device__ __forceinline__ uint32_t packh2(float a, float b){
    __half2 v = __floats2half2_rn(a, b);
    return *(uint32_t*)&v;
}
__device__ __forceinline__ float fsig(float x){
    return __fdividef(1.f, 1.f + __expf(-x));
}
__device__ __forceinline__ float ftanh(float x){
    return 1.f - __fdividef(2.f, __expf(2.f*x) + 1.f);
}

// ---------------- per-warp counter sync ----------------
__device__ __forceinline__ unsigned* cnt_ptr(int layer, int bt, int mg, int t){
    return &g_cnt[(size_t)(((layer*2 + bt)*4 + mg)*257 + t)*8];
}
__device__ __forceinline__ void warp_wait(unsigned* p, unsigned tgt, int lane){
    if (lane == 0){
        volatile unsigned* v = p;
        while (*v < tgt) {}
        __threadfence();
    }
    __syncwarp();
}
// release: every lane fences its own STGs, then lane 0 bumps the counter
__device__ __forceinline__ void warp_publish(unsigned* p, int lane){
    __threadfence();
    __syncwarp();
    if (lane == 0) atomicAdd(p, 1u);
}

// ---------------- prologue: fp32 -> fp16 weight convert + counter reset ----------------
__global__ void conv_all_kernel(const float* __restrict__ whh0,
                                const float* __restrict__ whh1,
                                const float* __restrict__ wih1)
{
    int i = blockIdx.x * blockDim.x + threadIdx.x;
    if (i < 16*257*8) g_cnt[i] = 0u;
    if (i >= G4*Hn) return;
    g_whh0[i] = __float2half_rn(whh0[i]);
    g_whh1[i] = __float2half_rn(whh1[i]);
    g_wih1[i] = __float2half_rn(wih1[i]);
}

// ---------------- staging ----------------
// pair-split: warp nh stages rows [nh*16, nh*16+16) of pair mg's 32 rows, one K=128 chunk
__device__ __forceinline__ void stage_half(const __half* __restrict__ src,
                                           int kc, uint32_t buf, int mg, int nh, int lane)
{
    #pragma unroll
    for (int it = 0; it < 8; ++it){
        int idx = it*32 + lane;       // 0..255
        int r   = idx >> 4;           // 0..15
        int s   = idx & 15;
        cpa16(buf + (uint32_t)((nh*16 + r)*272 + s*16),
              src + (size_t)(mg*32 + nh*16 + r) * Hn + kc*128 + s*8);
    }
}

// persistent W tile (init only, block-wide): pr -> j: g=(pr>>3)&3, u=(pr&7)+(pr>>5)*8
__device__ __forceinline__ void stage_W(const __half* __restrict__ src,
                                        char* smem, int woff, int u0, int tid)
{
    for (int it = 0; it < 16; ++it){
        int idx = tid + it*256;
        int row = idx >> 6;
        int kk  = (idx & 63) << 3;
        int j = ((row >> 3) & 3) * Hn + u0 + (row & 7) + (row >> 5) * 8;
        uint4 v = *(const uint4*)(src + (size_t)j * Hn + kk);
        *(uint4*)(smem + woff + row*1040 + kk*2) = v;
    }
}

// ---------------- fragment pipelines (warp tile 32x32, mg4 x nh2, full K) ----------------
struct Fr2 { uint32_t a[8], wr[8], wx[8]; };
struct Fr1 { uint32_t a[8], wr[8]; };

__device__ __forceinline__ void load2(Fr2& f, uint32_t aB, uint32_t wrB, uint32_t wxB, int k16){
    ldmx4(f.a,     aB + k16*32);
    ldmx4(f.a + 4, aB + 4352 + k16*32);          // +16 rows * 272
    ldmx4(f.wr,     wrB + k16*32);
    ldmx4(f.wr + 4, wrB + 16640 + k16*32);       // +16 packed rows * 1040
    ldmx4(f.wx,     wxB + k16*32);
    ldmx4(f.wx + 4, wxB + 16640 + k16*32);
}
__device__ __forceinline__ void load1(Fr1& f, uint32_t aB, uint32_t wrB, int k16){
    ldmx4(f.a,     aB + k16*32);
    ldmx4(f.a + 4, aB + 4352 + k16*32);
    ldmx4(f.wr,     wrB + k16*32);
    ldmx4(f.wr + 4, wrB + 16640 + k16*32);
}

__device__ __forceinline__ void chunk2(uint32_t aB, uint32_t wrB, uint32_t wxB,
                                       float* accR, float* accX)
{
    Fr2 f[2];
    load2(f[0], aB, wrB, wxB, 0);
    #pragma unroll
    for (int k16 = 0; k16 < 8; ++k16){
        if (k16 < 7) load2(f[(k16+1)&1], aB, wrB, wxB, k16+1);
        const Fr2& fc = f[k16&1];
        #pragma unroll
        for (int mh = 0; mh < 2; ++mh)
            #pragma unroll
            for (int g = 0; g < 4; ++g)
                mma_f16(accR + (mh*4+g)*4, fc.a + mh*4, fc.wr[g*2], fc.wr[g*2+1]);
        #pragma unroll
        for (int mh = 0; mh < 2; ++mh)
            #pragma unroll
            for (int g = 0; g < 4; ++g)
                mma_f16(accX + (mh*4+g)*4, fc.a + mh*4, fc.wx[g*2], fc.wx[g*2+1]);
    }
}
__device__ __forceinline__ void chunk1(uint32_t aB, uint32_t wrB, float* accR)
{
    Fr1 f[2];
    load1(f[0], aB, wrB, 0);
    #pragma unroll
    for (int k16 = 0; k16 < 8; ++k16){
        if (k16 < 7) load1(f[(k16+1)&1], aB, wrB, k16+1);
        const Fr1& fc = f[k16&1];
        #pragma unroll
        for (int mh = 0; mh < 2; ++mh)
            #pragma unroll
            for (int g = 0; g < 4; ++g)
                mma_f16(accR + (mh*4+g)*4, fc.a + mh*4, fc.wr[g*2], fc.wr[g*2+1]);
    }
}

// full K=512 pair-synchronized GEMM: one producer wait, pair-split staging,
// named pair barriers ordering shared-buffer reuse.
template<int XP>
__device__ __forceinline__ void gemm512_p(const __half* __restrict__ src, uint32_t sb,
    uint32_t aoff, uint32_t wboff, float* accR, float* accX,
    int mg, int nh, int lane, unsigned* cnt, unsigned tgt)
{
    const uint32_t buf0 = sb + ABASE + (uint32_t)mg*17408u;
    const uint32_t buf1 = buf0 + 8704u;
    warp_wait(cnt, tgt, lane);
    stage_half(src, 0, buf0, mg, nh, lane); CP_COMMIT;
    stage_half(src, 1, buf1, mg, nh, lane); CP_COMMIT;

    #define CHUNK_AT(c, buf) do { \
        if (XP) chunk2((buf) + aoff, sb + W0OFF + wboff + (c)*256, \
                       sb + W1OFF + wboff + (c)*256, accR, accX); \
        else    chunk1((buf) + aoff, sb + W0OFF + wboff + (c)*256, accR); \
    } while(0)

    CP_WAIT1; PAIRBAR(mg);                 // buf0 ready (both halves)
    CHUNK_AT(0, buf0);
    PAIRBAR(mg);                           // pair done reading buf0
    stage_half(src, 2, buf0, mg, nh, lane); CP_COMMIT;
    CP_WAIT1; PAIRBAR(mg);                 // buf1 ready
    CHUNK_AT(1, buf1);
    PAIRBAR(mg);                           // pair done reading buf1
    stage_half(src, 3, buf1, mg, nh, lane); CP_COMMIT;
    CP_WAIT1; PAIRBAR(mg);                 // buf0 ready (chunk2)
    CHUNK_AT(2, buf0);
    CP_WAIT0; PAIRBAR(mg);                 // buf1 ready (chunk3), buf0 reads done
    CHUNK_AT(3, buf1);
    PAIRBAR(mg);                           // pair done reading buf1 (next step may restage)
    #undef CHUNK_AT
}

// ---------------- fused two-layer pipelined kernel ----------------
// 128 CTAs: role 0 (blk 0..63) = layer0 rec + xp for layer1;
//           role 1 (blk 64..127) = layer1 rec (consumes xp).
// Per role: 2 bt (128 b) x 32 nt (16 u). 8 warps: mg = wid>>1 (m32), nh = wid&1 (n32).
__global__ void __launch_bounds__(256, 1) lstm_fused(
    const float* __restrict__ x_time, const float* __restrict__ w_ih0,
    const float* __restrict__ bias0, const float* __restrict__ bias1)
{
    extern __shared__ __align__(128) char smem[];
    const int tid  = threadIdx.x;
    const int lane = tid & 31;
    const int wid  = tid >> 5;
    const int mg   = wid >> 1;
    const int nh   = wid & 1;
    const int role = blockIdx.x >> 6;
    const int lidx = blockIdx.x & 63;
    const int bt   = lidx >> 5;
    const int nt   = lidx & 31;
    const int b0   = bt * 128;
    const int u0   = nt * 16;
    const uint32_t sb = su32(smem);

    const uint32_t aoff  = (uint32_t)((lane & 15) * 272 + (lane >> 4) * 16);  // pair-relative
    const uint32_t wboff = (uint32_t)((nh*32 + (lane & 7) + ((lane >> 4) & 1) * 8) * 1040
                                      + ((lane >> 3) & 1) * 16);
    const int q2    = 2 * (lane & 3);
    const int rb0   = mg*32 + (lane >> 2);
    const int ubase = u0 + nh*8 + q2;

    if (role == 0){
        // ================= layer 0 + xp producer =================
        stage_W(g_whh0, smem, W0OFF, u0, tid);
        stage_W(g_wih1, smem, W1OFF, u0, tid);
        float* s_wih0 = (float*)(smem + WIH0OFF);
        if (tid < 64){
            int j = ((tid >> 3) & 3) * Hn + u0 + (tid & 7) + (tid >> 5) * 8;
            #pragma unroll
            for (int q = 0; q < 5; ++q) s_wih0[tid*5 + q] = w_ih0[(size_t)j*5 + q];
        }
        float breg[4][2], bx[4][2];
        #pragma unroll
        for (int g = 0; g < 4; ++g){
            breg[g][0] = bias0[g*Hn + ubase];
            breg[g][1] = bias0[g*Hn + ubase + 1];
            bx[g][0]   = bias1[g*Hn + ubase];
            bx[g][1]   = bias1[g*Hn + ubase + 1];
        }
        __syncthreads();

        float c[8];
        #pragma unroll
        for (int i = 0; i < 8; ++i) c[i] = 0.f;

        for (int t = 0; t <= Tn; ++t){
            float xr[4][5];
            if (t < Tn){
                #pragma unroll
                for (int mh = 0; mh < 2; ++mh)
                    #pragma unroll
                    for (int rs = 0; rs < 2; ++rs){
                        const float* p = x_time
                            + ((size_t)(b0 + rb0 + mh*16 + rs*8) * Tn + t) * 5;
                        #pragma unroll
                        for (int q = 0; q < 5; ++q) xr[mh*2+rs][q] = p[q];
                    }
            }

            float accR[32], accX[32];
            #pragma unroll
            for (int i = 0; i < 32; ++i){ accR[i] = 0.f; accX[i] = 0.f; }

            if (t > 0)
                gemm512_p<1>(g_h0 + (size_t)(t-1)*BH + (size_t)b0*Hn, sb, aoff, wboff,
                             accR, accX, mg, nh, lane, cnt_ptr(0, bt, mg, t-1), 64u);

            if (t < Tn){
                #pragma unroll
                for (int mh = 0; mh < 2; ++mh)
                    #pragma unroll
                    for (int rs = 0; rs < 2; ++rs)
                        #pragma unroll
                        for (int g = 0; g < 4; ++g)
                            #pragma unroll
                            for (int j = 0; j < 2; ++j){
                                const float* wr = s_wih0 + (nh*32 + g*8 + q2 + j)*5;
                                float d = breg[g][j];
                                #pragma unroll
                                for (int q = 0; q < 5; ++q) d += xr[mh*2+rs][q]*wr[q];
                                accR[(mh*4+g)*4 + rs*2 + j] += d;
                            }
                #pragma unroll
                for (int mh = 0; mh < 2; ++mh)
                    #pragma unroll
                    for (int rs = 0; rs < 2; ++rs){
                        int row = rb0 + mh*16 + rs*8;
                        float hv[2];
                        #pragma unroll
                        for (int j = 0; j < 2; ++j){
                            float ai = accR[(mh*4+0)*4 + rs*2 + j];
                            float af = accR[(mh*4+1)*4 + rs*2 + j];
                            float ag = accR[(mh*4+2)*4 + rs*2 + j];
                            float ao = accR[(mh*4+3)*4 + rs*2 + j];
                            int ci = mh*4 + rs*2 + j;
                            c[ci] = fsig(af) * c[ci] + fsig(ai) * ftanh(ag);
                            hv[j] = fsig(ao) * ftanh(c[ci]);
                        }
                        size_t ob = (size_t)t*BH + (size_t)(b0+row)*Hn + ubase;
                        *(uint32_t*)(g_h0 + ob) = packh2(hv[0], hv[1]);
                    }
            }

            if (t > 0){
                float* xp = g_xp + ((((size_t)(t-1)*2 + bt)*32 + nt)*256 + tid)*32;
                #pragma unroll
                for (int mh = 0; mh < 2; ++mh)
                    #pragma unroll
                    for (int g = 0; g < 4; ++g){
                        int i = mh*4 + g;
                        float4 v;
                        v.x = accX[i*4+0] + bx[g][0];
                        v.y = accX[i*4+1] + bx[g][1];
                        v.z = accX[i*4+2] + bx[g][0];
                        v.w = accX[i*4+3] + bx[g][1];
                        *(float4*)(xp + i*4) = v;
                    }
            }

            warp_publish(cnt_ptr(0, bt, mg, t), lane);
        }
    } else {
        // ================= layer 1 consumer =================
        stage_W(g_whh1, smem, W0OFF, u0, tid);
        __syncthreads();

        float c[8];
        #pragma unroll
        for (int i = 0; i < 8; ++i) c[i] = 0.f;

        for (int t = 0; t < Tn; ++t){
            // xp_t ready once L0 (same bt, mg; all nt, both nh) finished step t+1
            warp_wait(cnt_ptr(0, bt, mg, t+1), 64u, lane);
            const float* xps = g_xp + ((((size_t)t*2 + bt)*32 + nt)*256 + tid)*32;
            float xpre[32];
            #pragma unroll
            for (int i = 0; i < 8; ++i){
                float4 v = *(const float4*)(xps + i*4);
                xpre[i*4+0]=v.x; xpre[i*4+1]=v.y; xpre[i*4+2]=v.z; xpre[i*4+3]=v.w;
            }

            float accR[32];
            #pragma unroll
            for (int i = 0; i < 32; ++i) accR[i] = 0.f;

            if (t > 0)
                gemm512_p<0>(g_h1 + (size_t)(t-1)*BH + (size_t)b0*Hn, sb, aoff, wboff,
                             accR, (float*)0, mg, nh, lane, cnt_ptr(1, bt, mg, t-1), 64u);

            #pragma unroll
            for (int i = 0; i < 32; ++i) accR[i] += xpre[i];

            #pragma unroll
            for (int mh = 0; mh < 2; ++mh)
                #pragma unroll
                for (int rs = 0; rs < 2; ++rs){
                    int row = rb0 + mh*16 + rs*8;
                    float hv[2];
                    #pragma unroll
                    for (int j = 0; j < 2; ++j){
                        float ai = accR[(mh*4+0)*4 + rs*2 + j];
                        float af = accR[(mh*4+1)*4 + rs*2 + j];
                        float ag = accR[(mh*4+2)*4 + rs*2 + j];
                        float ao = accR[(mh*4+3)*4 + rs*2 + j];
                        int ci = mh*4 + rs*2 + j;
                        c[ci] = fsig(af) * c[ci] + fsig(ai) * ftanh(ag);
                        hv[j] = fsig(ao) * ftanh(c[ci]);
                    }
                    size_t ob = (size_t)t*BH + (size_t)(b0+row)*Hn + ubase;
                    *(uint32_t*)(g_h1 + ob) = packh2(hv[0], hv[1]);
                }

            warp_publish(cnt_ptr(1, bt, mg, t), lane);
        }
    }
}

// ---------------- heads ----------------
__global__ void __launch_bounds__(256) heads_kernel(
    const float* __restrict__ x_stat,
    const float* __restrict__ fc1_w, const float* __restrict__ fc1_b,
    const float* __restrict__ fc2_w, const float* __restrict__ fc2_b,
    const float* __restrict__ fc3_w, const float* __restrict__ fc3_b,
    float* __restrict__ out)
{
    const int b = blockIdx.x;
    const int tid = threadIdx.x;

    float p0 = 0.f, p1 = 0.f;
    for (int idx = tid; idx < Tn*Hn; idx += 256){
        int t = idx >> 9;
        int u = idx & 511;
        float hv = __half2float(g_h1[(size_t)t * BH + (size_t)b * Hn + u]);
        p0 += hv * fc1_w[idx];
        p1 += hv * fc1_w[Tn*Hn + idx];
    }
    __shared__ float s0[256], s1[256];
    s0[tid] = p0; s1[tid] = p1;
    __syncthreads();
    for (int s = 128; s > 0; s >>= 1){
        if (tid < s){ s0[tid] += s0[tid+s]; s1[tid] += s1[tid+s]; }
        __syncthreads();
    }
    if (tid == 0){
        float tp0 = s0[0] + fc1_b[0];
        float tp1 = s1[0] + fc1_b[1];
        float xs0 = x_stat[b*3+0], xs1 = x_stat[b*3+1], xs2 = x_stat[b*3+2];
        float sp0 = fc2_b[0] + xs0*fc2_w[0] + xs1*fc2_w[1] + xs2*fc2_w[2];
        float sp1 = fc2_b[1] + xs0*fc2_w[3] + xs1*fc2_w[4] + xs2*fc2_w[5];
        out[b*2+0] = fc3_b[0] + fc3_w[0]*sp0 + fc3_w[1]*sp1 + fc3_w[2]*tp0 + fc3_w[3]*tp1;
        out[b*2+1] = fc3_b[1] + fc3_w[4]*sp0 + fc3_w[5]*sp1 + fc3_w[6]*tp0 + fc3_w[7]*tp1;
    }
}

extern "C" void kernel_launch(void* const* d_in, const int* in_sizes, int n_in,
                              void* d_out, int out_size)
{
    const float* x_time = (const float*)d_in[0];
    const float* x_stat = (const float*)d_in[1];
    const float* w_ih0  = (const float*)d_in[2];
    const float* w_hh0  = (const float*)d_in[3];
    const float* b0     = (const float*)d_in[4];
    const float* w_ih1  = (const float*)d_in[5];
    const float* w_hh1  = (const float*)d_in[6];
    const float* b1     = (const float*)d_in[7];
    const float* fc1_w  = (const float*)d_in[8];
    const float* fc1_b  = (const float*)d_in[9];
    const float* fc2_w  = (const float*)d_in[10];
    const float* fc2_b  = (const float*)d_in[11];
    const float* fc3_w  = (const float*)d_in[12];
    const float* fc3_b  = (const float*)d_in[13];
    float* out = (float*)d_out;

    cudaFuncSetAttribute(lstm_fused, cudaFuncAttributeMaxDynamicSharedMemorySize, SMEMSZ);

    conv_all_kernel<<<(G4*Hn + 255)/256, 256>>>(w_hh0, w_hh1, w_ih1);
    lstm_fused<<<128, 256, SMEMSZ>>>(x_time, w_ih0, b0, b1);
    heads_kernel<<<Bn, 256>>>(x_stat, fc1_w, fc1_b, fc2_w, fc2_b, fc3_w, fc3_b, out);
}

// round 12
// speedup vs baseline: 7.6158x; 1.0460x over previous
#include <cuda_runtime.h>
#include <cuda_fp16.h>
#include <cstdint>
#include <math.h>

#define Tn 256
#define Bn 256
#define Hn 512
#define BH (Bn*Hn)
#define G4 2048

// ---------------- device globals (scratch) ----------------
__device__ __align__(128) __half g_whh0[G4*Hn];
__device__ __align__(128) __half g_whh1[G4*Hn];
__device__ __align__(128) __half g_wih1[G4*Hn];
__device__ __align__(128) __half g_h0[(size_t)Tn*BH];
__device__ __align__(128) __half g_h1[(size_t)Tn*BH];
__device__ __align__(128) float g_xp[134217728];      // [t][bt][nt][tid(256)][32] fp32
// per-(layer,bt,mg,t) release counters, padded to 32B
__device__ __align__(128) unsigned g_cnt[16*257*8];

// ---------------- SMEM layout (bytes) ----------------
// W tiles: 64 packed rows pr = nh*32 + g*8 + u, stride 1040 (512 fp16 + 8 pad)
// A: per-pair private region: pair mg at ABASE + mg*17408; 2 bufs of 8704
//    (32 rows x 272 B, row = global row mg*32 + r)
#define W0OFF 0
#define W1OFF 66560
#define ABASE 133120
#define WIH0OFF 202752
#define SMEMSZ 204800

// ---------------- PTX helpers ----------------
__device__ __forceinline__ uint32_t su32(const void* p){
    uint32_t a;
    asm("{ .reg .u64 t; cvta.to.shared.u64 t, %1; cvt.u32.u64 %0, t; }" : "=r"(a) : "l"(p));
    return a;
}
__device__ __forceinline__ void ldmx4(uint32_t* r, uint32_t a){
    asm volatile("ldmatrix.sync.aligned.m8n8.x4.shared.b16 {%0,%1,%2,%3}, [%4];"
        : "=r"(r[0]), "=r"(r[1]), "=r"(r[2]), "=r"(r[3]) : "r"(a));
}
__device__ __forceinline__ void mma_f16(float* c, const uint32_t* a, uint32_t b0, uint32_t b1){
    asm("mma.sync.aligned.m16n8k16.row.col.f32.f16.f16.f32 "
        "{%0,%1,%2,%3}, {%4,%5,%6,%7}, {%8,%9}, {%0,%1,%2,%3};"
        : "+f"(c[0]), "+f"(c[1]), "+f"(c[2]), "+f"(c[3])
        : "r"(a[0]), "r"(a[1]), "r"(a[2]), "r"(a[3]), "r"(b0), "r"(b1));
}
__device__ __forceinline__ void cpa16(uint32_t dst, const void* src){
    asm volatile("cp.async.cg.shared.global [%0], [%1], 16;" :: "r"(dst), "l"(src));
}
#define CP_COMMIT asm volatile("cp.async.commit_group;" ::: "memory")
#define CP_WAIT0  asm volatile("cp.async.wait_group 0;" ::: "memory")
#define CP_WAIT1  asm volatile("cp.async.wait_group 1;" ::: "memory")
// two-warp named barrier for the mg pair (ids 1..4; __syncthreads uses 0)
#define PAIRBAR(mg) asm volatile("bar.sync %0, 64;" :: "r"((mg)+1) : "memory")

__device__ __forceinline__ uint32_t packh2(float a, float b){
    __half2 v = __floats2half2_rn(a, b);
    return *(uint32_t*)&v;
}
__device__ __forceinline__ float fsig(float x){
    return __fdividef(1.f, 1.f + __expf(-x));
}
__device__ __forceinline__ float ftanh(float x){
    return 1.f - __fdividef(2.f, __expf(2.f*x) + 1.f);
}

// ---------------- per-warp counter sync ----------------
__device__ __forceinline__ unsigned* cnt_ptr(int layer, int bt, int mg, int t){
    return &g_cnt[(size_t)(((layer*2 + bt)*4 + mg)*257 + t)*8];
}
__device__ __forceinline__ void warp_wait(unsigned* p, unsigned tgt, int lane){
    if (lane == 0){
        volatile unsigned* v = p;
        while (*v < tgt) {}
        __threadfence();
    }
    __syncwarp();
}
// release: every lane fences its own STGs, then lane 0 bumps the counter
__device__ __forceinline__ void warp_publish(unsigned* p, int lane){
    __threadfence();
    __syncwarp();
    if (lane == 0) atomicAdd(p, 1u);
}

// ---------------- prologue: fp32 -> fp16 weight convert + counter reset ----------------
__global__ void conv_all_kernel(const float* __restrict__ whh0,
                                const float* __restrict__ whh1,
                                const float* __restrict__ wih1)
{
    int i = blockIdx.x * blockDim.x + threadIdx.x;
    if (i < 16*257*8) g_cnt[i] = 0u;
    if (i >= G4*Hn) return;
    g_whh0[i] = __float2half_rn(whh0[i]);
    g_whh1[i] = __float2half_rn(whh1[i]);
    g_wih1[i] = __float2half_rn(wih1[i]);
}

// ---------------- staging ----------------
// pair-split: warp nh stages rows [nh*16, nh*16+16) of pair mg's 32 rows, one K=128 chunk
__device__ __forceinline__ void stage_half(const __half* __restrict__ src,
                                           int kc, uint32_t buf, int mg, int nh, int lane)
{
    #pragma unroll
    for (int it = 0; it < 8; ++it){
        int idx = it*32 + lane;       // 0..255
        int r   = idx >> 4;           // 0..15
        int s   = idx & 15;
        cpa16(buf + (uint32_t)((nh*16 + r)*272 + s*16),
              src + (size_t)(mg*32 + nh*16 + r) * Hn + kc*128 + s*8);
    }
}

// persistent W tile (init only, block-wide): pr -> j: g=(pr>>3)&3, u=(pr&7)+(pr>>5)*8
__device__ __forceinline__ void stage_W(const __half* __restrict__ src,
                                        char* smem, int woff, int u0, int tid)
{
    for (int it = 0; it < 16; ++it){
        int idx = tid + it*256;
        int row = idx >> 6;
        int kk  = (idx & 63) << 3;
        int j = ((row >> 3) & 3) * Hn + u0 + (row & 7) + (row >> 5) * 8;
        uint4 v = *(const uint4*)(src + (size_t)j * Hn + kk);
        *(uint4*)(smem + woff + row*1040 + kk*2) = v;
    }
}

// ---------------- fragment pipelines (warp tile 32x32, mg4 x nh2) ----------------
struct Fr2 { uint32_t a[8], wr[8], wx[8]; };
struct Fr1 { uint32_t a[8], wr[8]; };

__device__ __forceinline__ void load2(Fr2& f, uint32_t aB, uint32_t wrB, uint32_t wxB, int k16){
    ldmx4(f.a,     aB + k16*32);
    ldmx4(f.a + 4, aB + 4352 + k16*32);          // +16 rows * 272
    ldmx4(f.wr,     wrB + k16*32);
    ldmx4(f.wr + 4, wrB + 16640 + k16*32);       // +16 packed rows * 1040
    ldmx4(f.wx,     wxB + k16*32);
    ldmx4(f.wx + 4, wxB + 16640 + k16*32);
}
__device__ __forceinline__ void load1(Fr1& f, uint32_t aB, uint32_t wrB, int k16){
    ldmx4(f.a,     aB + k16*32);
    ldmx4(f.a + 4, aB + 4352 + k16*32);
    ldmx4(f.wr,     wrB + k16*32);
    ldmx4(f.wr + 4, wrB + 16640 + k16*32);
}

__device__ __forceinline__ void chunk2(uint32_t aB, uint32_t wrB, uint32_t wxB,
                                       float* accR, float* accX)
{
    Fr2 f[2];
    load2(f[0], aB, wrB, wxB, 0);
    #pragma unroll
    for (int k16 = 0; k16 < 8; ++k16){
        if (k16 < 7) load2(f[(k16+1)&1], aB, wrB, wxB, k16+1);
        const Fr2& fc = f[k16&1];
        #pragma unroll
        for (int mh = 0; mh < 2; ++mh)
            #pragma unroll
            for (int g = 0; g < 4; ++g)
                mma_f16(accR + (mh*4+g)*4, fc.a + mh*4, fc.wr[g*2], fc.wr[g*2+1]);
        #pragma unroll
        for (int mh = 0; mh < 2; ++mh)
            #pragma unroll
            for (int g = 0; g < 4; ++g)
                mma_f16(accX + (mh*4+g)*4, fc.a + mh*4, fc.wx[g*2], fc.wx[g*2+1]);
    }
}
__device__ __forceinline__ void chunk1(uint32_t aB, uint32_t wrB, float* accR)
{
    Fr1 f[2];
    load1(f[0], aB, wrB, 0);
    #pragma unroll
    for (int k16 = 0; k16 < 8; ++k16){
        if (k16 < 7) load1(f[(k16+1)&1], aB, wrB, k16+1);
        const Fr1& fc = f[k16&1];
        #pragma unroll
        for (int mh = 0; mh < 2; ++mh)
            #pragma unroll
            for (int g = 0; g < 4; ++g)
                mma_f16(accR + (mh*4+g)*4, fc.a + mh*4, fc.wr[g*2], fc.wr[g*2+1]);
    }
}

// chunk-range pair-synchronized GEMM.
// chunks [c0, c1): for c < XPC run rec+xp (wrOFF + W1OFF), else rec-only (wrOFF).
template<int XPC>
__device__ __forceinline__ void gemm_loop(const __half* __restrict__ src, uint32_t sb,
    uint32_t aoff, uint32_t wboff, int wrOFF, float* accR, float* accX,
    int c0, int c1, int mg, int nh, int lane)
{
    const uint32_t buf0 = sb + ABASE + (uint32_t)mg*17408u;
    const uint32_t bufs[2] = {buf0, buf0 + 8704u};
    stage_half(src, c0, bufs[c0 & 1], mg, nh, lane); CP_COMMIT;
    if (c0 + 1 < c1){ stage_half(src, c0+1, bufs[(c0+1) & 1], mg, nh, lane); CP_COMMIT; }
    #pragma unroll 1
    for (int c = c0; c < c1; ++c){
        if (c + 1 < c1) { CP_WAIT1; } else { CP_WAIT0; }
        PAIRBAR(mg);                 // both halves of bufs[c&1] staged & visible
        uint32_t aB = bufs[c & 1] + aoff;
        if (c < XPC)
            chunk2(aB, sb + wrOFF + wboff + c*256, sb + W1OFF + wboff + c*256, accR, accX);
        else
            chunk1(aB, sb + wrOFF + wboff + c*256, accR);
        PAIRBAR(mg);                 // pair done reading bufs[c&1]
        if (c + 2 < c1){ stage_half(src, c+2, bufs[c & 1], mg, nh, lane); CP_COMMIT; }
    }
}

// ---------------- fused two-layer pipelined kernel ----------------
// 128 CTAs: role 0 (blk 0..63) = layer0 rec + xp K-chunks 0..1;
//           role 1 (blk 64..127) = layer1 rec + xp K-chunks 2..3 (balanced).
// Per role: 2 bt (128 b) x 32 nt (16 u). 8 warps: mg = wid>>1 (m32), nh = wid&1 (n32).
__global__ void __launch_bounds__(256, 1) lstm_fused(
    const float* __restrict__ x_time, const float* __restrict__ w_ih0,
    const float* __restrict__ bias0, const float* __restrict__ bias1)
{
    extern __shared__ __align__(128) char smem[];
    const int tid  = threadIdx.x;
    const int lane = tid & 31;
    const int wid  = tid >> 5;
    const int mg   = wid >> 1;
    const int nh   = wid & 1;
    const int role = blockIdx.x >> 6;
    const int lidx = blockIdx.x & 63;
    const int bt   = lidx >> 5;
    const int nt   = lidx & 31;
    const int b0   = bt * 128;
    const int u0   = nt * 16;
    const uint32_t sb = su32(smem);

    const uint32_t aoff  = (uint32_t)((lane & 15) * 272 + (lane >> 4) * 16);  // pair-relative
    const uint32_t wboff = (uint32_t)((nh*32 + (lane & 7) + ((lane >> 4) & 1) * 8) * 1040
                                      + ((lane >> 3) & 1) * 16);
    const int q2    = 2 * (lane & 3);
    const int rb0   = mg*32 + (lane >> 2);
    const int ubase = u0 + nh*8 + q2;

    if (role == 0){
        // ================= layer 0 + xp (K 0..255) producer =================
        stage_W(g_whh0, smem, W0OFF, u0, tid);
        stage_W(g_wih1, smem, W1OFF, u0, tid);
        float* s_wih0 = (float*)(smem + WIH0OFF);
        if (tid < 64){
            int j = ((tid >> 3) & 3) * Hn + u0 + (tid & 7) + (tid >> 5) * 8;
            #pragma unroll
            for (int q = 0; q < 5; ++q) s_wih0[tid*5 + q] = w_ih0[(size_t)j*5 + q];
        }
        float breg[4][2], bx[4][2];
        #pragma unroll
        for (int g = 0; g < 4; ++g){
            breg[g][0] = bias0[g*Hn + ubase];
            breg[g][1] = bias0[g*Hn + ubase + 1];
            bx[g][0]   = bias1[g*Hn + ubase];
            bx[g][1]   = bias1[g*Hn + ubase + 1];
        }
        __syncthreads();

        float c[8];
        #pragma unroll
        for (int i = 0; i < 8; ++i) c[i] = 0.f;

        for (int t = 0; t <= Tn; ++t){
            float xr[4][5];
            if (t < Tn){
                #pragma unroll
                for (int mh = 0; mh < 2; ++mh)
                    #pragma unroll
                    for (int rs = 0; rs < 2; ++rs){
                        const float* p = x_time
                            + ((size_t)(b0 + rb0 + mh*16 + rs*8) * Tn + t) * 5;
                        #pragma unroll
                        for (int q = 0; q < 5; ++q) xr[mh*2+rs][q] = p[q];
                    }
            }

            float accR[32], accX[32];
            #pragma unroll
            for (int i = 0; i < 32; ++i){ accR[i] = 0.f; accX[i] = 0.f; }

            if (t > 0){
                warp_wait(cnt_ptr(0, bt, mg, t-1), 64u, lane);
                gemm_loop<2>(g_h0 + (size_t)(t-1)*BH + (size_t)b0*Hn, sb, aoff, wboff,
                             W0OFF, accR, accX, 0, 4, mg, nh, lane);
            }

            if (t < Tn){
                #pragma unroll
                for (int mh = 0; mh < 2; ++mh)
                    #pragma unroll
                    for (int rs = 0; rs < 2; ++rs)
                        #pragma unroll
                        for (int g = 0; g < 4; ++g)
                            #pragma unroll
                            for (int j = 0; j < 2; ++j){
                                const float* wr = s_wih0 + (nh*32 + g*8 + q2 + j)*5;
                                float d = breg[g][j];
                                #pragma unroll
                                for (int q = 0; q < 5; ++q) d += xr[mh*2+rs][q]*wr[q];
                                accR[(mh*4+g)*4 + rs*2 + j] += d;
                            }
                #pragma unroll
                for (int mh = 0; mh < 2; ++mh)
                    #pragma unroll
                    for (int rs = 0; rs < 2; ++rs){
                        int row = rb0 + mh*16 + rs*8;
                        float hv[2];
                        #pragma unroll
                        for (int j = 0; j < 2; ++j){
                            float ai = accR[(mh*4+0)*4 + rs*2 + j];
                            float af = accR[(mh*4+1)*4 + rs*2 + j];
                            float ag = accR[(mh*4+2)*4 + rs*2 + j];
                            float ao = accR[(mh*4+3)*4 + rs*2 + j];
                            int ci = mh*4 + rs*2 + j;
                            c[ci] = fsig(af) * c[ci] + fsig(ai) * ftanh(ag);
                            hv[j] = fsig(ao) * ftanh(c[ci]);
                        }
                        size_t ob = (size_t)t*BH + (size_t)(b0+row)*Hn + ubase;
                        *(uint32_t*)(g_h0 + ob) = packh2(hv[0], hv[1]);
                    }
            }

            if (t > 0){
                // xp partial (K 0..255) + bias1, consumer fragment layout
                float* xp = g_xp + ((((size_t)(t-1)*2 + bt)*32 + nt)*256 + tid)*32;
                #pragma unroll
                for (int mh = 0; mh < 2; ++mh)
                    #pragma unroll
                    for (int g = 0; g < 4; ++g){
                        int i = mh*4 + g;
                        float4 v;
                        v.x = accX[i*4+0] + bx[g][0];
                        v.y = accX[i*4+1] + bx[g][1];
                        v.z = accX[i*4+2] + bx[g][0];
                        v.w = accX[i*4+3] + bx[g][1];
                        *(float4*)(xp + i*4) = v;
                    }
            }

            warp_publish(cnt_ptr(0, bt, mg, t), lane);
        }
    } else {
        // ================= layer 1 + xp (K 256..511) =================
        stage_W(g_whh1, smem, W0OFF, u0, tid);
        stage_W(g_wih1, smem, W1OFF, u0, tid);
        __syncthreads();

        float c[8];
        #pragma unroll
        for (int i = 0; i < 8; ++i) c[i] = 0.f;

        for (int t = 0; t < Tn; ++t){
            // h0_t + xp-partial_t ready once L0 (same bt, mg) finished step t+1
            warp_wait(cnt_ptr(0, bt, mg, t+1), 64u, lane);
            const float* xps = g_xp + ((((size_t)t*2 + bt)*32 + nt)*256 + tid)*32;
            float xpre[32];
            #pragma unroll
            for (int i = 0; i < 8; ++i){
                float4 v = *(const float4*)(xps + i*4);
                xpre[i*4+0]=v.x; xpre[i*4+1]=v.y; xpre[i*4+2]=v.z; xpre[i*4+3]=v.w;
            }

            float accR[32];
            #pragma unroll
            for (int i = 0; i < 32; ++i) accR[i] = 0.f;

            // xp K-half 256..511: h0_t chunks 2,3 against wih1
            gemm_loop<0>(g_h0 + (size_t)t*BH + (size_t)b0*Hn, sb, aoff, wboff,
                         W1OFF, accR, (float*)0, 2, 4, mg, nh, lane);

            if (t > 0){
                warp_wait(cnt_ptr(1, bt, mg, t-1), 64u, lane);
                gemm_loop<0>(g_h1 + (size_t)(t-1)*BH + (size_t)b0*Hn, sb, aoff, wboff,
                             W0OFF, accR, (float*)0, 0, 4, mg, nh, lane);
            }

            #pragma unroll
            for (int i = 0; i < 32; ++i) accR[i] += xpre[i];

            #pragma unroll
            for (int mh = 0; mh < 2; ++mh)
                #pragma unroll
                for (int rs = 0; rs < 2; ++rs){
                    int row = rb0 + mh*16 + rs*8;
                    float hv[2];
                    #pragma unroll
                    for (int j = 0; j < 2; ++j){
                        float ai = accR[(mh*4+0)*4 + rs*2 + j];
                        float af = accR[(mh*4+1)*4 + rs*2 + j];
                        float ag = accR[(mh*4+2)*4 + rs*2 + j];
                        float ao = accR[(mh*4+3)*4 + rs*2 + j];
                        int ci = mh*4 + rs*2 + j;
                        c[ci] = fsig(af) * c[ci] + fsig(ai) * ftanh(ag);
                        hv[j] = fsig(ao) * ftanh(c[ci]);
                    }
                    size_t ob = (size_t)t*BH + (size_t)(b0+row)*Hn + ubase;
                    *(uint32_t*)(g_h1 + ob) = packh2(hv[0], hv[1]);
                }

            warp_publish(cnt_ptr(1, bt, mg, t), lane);
        }
    }
}

// ---------------- heads ----------------
__global__ void __launch_bounds__(256) heads_kernel(
    const float* __restrict__ x_stat,
    const float* __restrict__ fc1_w, const float* __restrict__ fc1_b,
    const float* __restrict__ fc2_w, const float* __restrict__ fc2_b,
    const float* __restrict__ fc3_w, const float* __restrict__ fc3_b,
    float* __restrict__ out)
{
    const int b = blockIdx.x;
    const int tid = threadIdx.x;

    float p0 = 0.f, p1 = 0.f;
    for (int idx = tid; idx < Tn*Hn; idx += 256){
        int t = idx >> 9;
        int u = idx & 511;
        float hv = __half2float(g_h1[(size_t)t * BH + (size_t)b * Hn + u]);
        p0 += hv * fc1_w[idx];
        p1 += hv * fc1_w[Tn*Hn + idx];
    }
    __shared__ float s0[256], s1[256];
    s0[tid] = p0; s1[tid] = p1;
    __syncthreads();
    for (int s = 128; s > 0; s >>= 1){
        if (tid < s){ s0[tid] += s0[tid+s]; s1[tid] += s1[tid+s]; }
        __syncthreads();
    }
    if (tid == 0){
        float tp0 = s0[0] + fc1_b[0];
        float tp1 = s1[0] + fc1_b[1];
        float xs0 = x_stat[b*3+0], xs1 = x_stat[b*3+1], xs2 = x_stat[b*3+2];
        float sp0 = fc2_b[0] + xs0*fc2_w[0] + xs1*fc2_w[1] + xs2*fc2_w[2];
        float sp1 = fc2_b[1] + xs0*fc2_w[3] + xs1*fc2_w[4] + xs2*fc2_w[5];
        out[b*2+0] = fc3_b[0] + fc3_w[0]*sp0 + fc3_w[1]*sp1 + fc3_w[2]*tp0 + fc3_w[3]*tp1;
        out[b*2+1] = fc3_b[1] + fc3_w[4]*sp0 + fc3_w[5]*sp1 + fc3_w[6]*tp0 + fc3_w[7]*tp1;
    }
}

extern "C" void kernel_launch(void* const* d_in, const int* in_sizes, int n_in,
                              void* d_out, int out_size)
{
    const float* x_time = (const float*)d_in[0];
    const float* x_stat = (const float*)d_in[1];
    const float* w_ih0  = (const float*)d_in[2];
    const float* w_hh0  = (const float*)d_in[3];
    const float* b0     = (const float*)d_in[4];
    const float* w_ih1  = (const float*)d_in[5];
    const float* w_hh1  = (const float*)d_in[6];
    const float* b1     = (const float*)d_in[7];
    const float* fc1_w  = (const float*)d_in[8];
    const float* fc1_b  = (const float*)d_in[9];
    const float* fc2_w  = (const float*)d_in[10];
    const float* fc2_b  = (const float*)d_in[11];
    const float* fc3_w  = (const float*)d_in[12];
    const float* fc3_b  = (const float*)d_in[13];
    float* out = (float*)d_out;

    cudaFuncSetAttribute(lstm_fused, cudaFuncAttributeMaxDynamicSharedMemorySize, SMEMSZ);

    conv_all_kernel<<<(G4*Hn + 255)/256, 256>>>(w_hh0, w_hh1, w_ih1);
    lstm_fused<<<128, 256, SMEMSZ>>>(x_time, w_ih0, b0, b1);
    heads_kernel<<<Bn, 256>>>(x_stat, fc1_w, fc1_b, fc2_w, fc2_b, fc3_w, fc3_b, out);
}